// round 1
// baseline (speedup 1.0000x reference)
#include <cuda_runtime.h>
#include <cstdint>
#include <math.h>

#define HD    256
#define LSEQ  50
#define SSEQ  50
#define NBATCH 64
#define MAXF  32
#define NSEQ  (NBATCH*MAXF)   // 2048

#define MB 64   // sequence rows per block (gru step)
#define UB 32   // hidden units per block (gru step)

// ---------------- device scratch (no runtime allocation allowed) ----------------
__device__ float g_H[2][NSEQ*HD];                       // ping-pong hidden state
__device__ float g_X1[(size_t)NSEQ*LSEQ*HD];            // layer-0 outputs (105 MB)
__device__ float g_FL[NSEQ*HD];                         // friend_last
__device__ float g_CAT[NSEQ*2*HD];                      // [self_x | friend_last]
__device__ float g_SF[NSEQ*HD];
__device__ float g_V[NSEQ*HD];
__device__ float g_TF[NSEQ];

// ---------------- Blackwell packed fp32 FMA (FFMA2) ----------------
__device__ __forceinline__ float2 ffma2(float2 a, float2 b, float2 c){
    unsigned long long ua = reinterpret_cast<unsigned long long&>(a);
    unsigned long long ub = reinterpret_cast<unsigned long long&>(b);
    unsigned long long uc = reinterpret_cast<unsigned long long&>(c);
    unsigned long long ud;
    asm("fma.rn.f32x2 %0, %1, %2, %3;" : "=l"(ud) : "l"(ua), "l"(ub), "l"(uc));
    return reinterpret_cast<float2&>(ud);
}

__device__ __forceinline__ float fast_sigmoid(float x){
    return __fdividef(1.f, 1.f + __expf(-x));
}
__device__ __forceinline__ float fast_tanh(float x){
    return 1.f - __fdividef(2.f, __expf(2.f*x) + 1.f);
}
__device__ __forceinline__ float softplus_f(float x){
    return (x > 20.f) ? x : log1pf(expf(x));
}

// ---------------- GRU step: fused dual-GEMM + gate epilogue ----------------
// Computes, for a tile of 64 rows x 32 hidden units:
//   acc_r, acc_z  = x_t@Wih_{r,z}^T + h@Whh_{r,z}^T     (combined)
//   acc_nih       = x_t@Wih_n^T
//   acc_nhh       = h@Whh_n^T                            (kept separate: r multiplies it)
template<int PHASE>
__device__ __forceinline__ void gru_gemm_phase(
    const float* __restrict__ A, int rowStride,
    const float* __restrict__ W,
    int rb, int ub, int tx, int ty, int tid,
    float (*As)[68], float (*Ws)[100],
    float2 (&acc)[4][4])
{
    for (int kc = 0; kc < HD; kc += 32) {
        // stage A tile: 64 rows x 32 k, transposed to As[k][row]
        #pragma unroll
        for (int q = 0; q < 2; ++q) {
            int idx = q*256 + tid;          // 0..511 float4 slots
            int row = idx >> 3;
            int k4  = (idx & 7) << 2;
            const float4 v = *reinterpret_cast<const float4*>(
                &A[(size_t)(rb+row)*rowStride + kc + k4]);
            As[k4+0][row] = v.x; As[k4+1][row] = v.y;
            As[k4+2][row] = v.z; As[k4+3][row] = v.w;
        }
        // stage W tile: 3 gates x 32 units x 32 k, transposed to Ws[k][g*32+u]
        #pragma unroll
        for (int q = 0; q < 3; ++q) {
            int idx  = q*256 + tid;         // 0..767 float4 slots
            int wrow = idx >> 3;            // 0..95
            int k4   = (idx & 7) << 2;
            int g = wrow >> 5, u = wrow & 31;
            const float4 v = *reinterpret_cast<const float4*>(
                &W[(size_t)(g*HD + ub + u)*HD + kc + k4]);
            Ws[k4+0][wrow] = v.x; Ws[k4+1][wrow] = v.y;
            Ws[k4+2][wrow] = v.z; Ws[k4+3][wrow] = v.w;
        }
        __syncthreads();
        #pragma unroll
        for (int k = 0; k < 32; ++k) {
            const float4 a4 = *reinterpret_cast<const float4*>(&As[k][ty<<2]);
            const float2 br = *reinterpret_cast<const float2*>(&Ws[k][      (tx<<1)]);
            const float2 bz = *reinterpret_cast<const float2*>(&Ws[k][32 + (tx<<1)]);
            const float2 bn = *reinterpret_cast<const float2*>(&Ws[k][64 + (tx<<1)]);
            float av[4] = {a4.x, a4.y, a4.z, a4.w};
            #pragma unroll
            for (int i = 0; i < 4; ++i) {
                float2 aa = make_float2(av[i], av[i]);
                acc[0][i] = ffma2(aa, br, acc[0][i]);
                acc[1][i] = ffma2(aa, bz, acc[1][i]);
                acc[PHASE ? 3 : 2][i] = ffma2(aa, bn, acc[PHASE ? 3 : 2][i]);
            }
        }
        __syncthreads();
    }
}

__global__ __launch_bounds__(256) void gru_step_kernel(
    const float* __restrict__ Xin,   // [NSEQ, LSEQ, HD] layer input
    const float* __restrict__ Hprev, // [NSEQ, HD]
    float* __restrict__ Hnew,        // [NSEQ, HD]
    const float* __restrict__ Wih, const float* __restrict__ Whh,
    const float* __restrict__ bih, const float* __restrict__ bhh,
    float* __restrict__ Xout,        // layer0: store outputs; else null
    float* __restrict__ FL,          // layer1: friend_last; else null
    const int* __restrict__ flen,    // [NSEQ]
    int t)
{
    __shared__ float As[32][68];
    __shared__ float Ws[32][100];
    const int tid = threadIdx.x;
    const int tx = tid & 15, ty = tid >> 4;
    const int rb = blockIdx.x * MB;
    const int ub = blockIdx.y * UB;

    float2 acc[4][4];
    #pragma unroll
    for (int g = 0; g < 4; ++g)
        #pragma unroll
        for (int i = 0; i < 4; ++i) acc[g][i] = make_float2(0.f, 0.f);

    gru_gemm_phase<0>(Xin + (size_t)t*HD, LSEQ*HD, Wih, rb, ub, tx, ty, tid, As, Ws, acc);
    gru_gemm_phase<1>(Hprev,              HD,      Whh, rb, ub, tx, ty, tid, As, Ws, acc);

    #pragma unroll
    for (int i = 0; i < 4; ++i) {
        const int row = rb + (ty<<2) + i;
        #pragma unroll
        for (int uu = 0; uu < 2; ++uu) {
            const int j = ub + (tx<<1) + uu;
            const float ar  = uu ? acc[0][i].y : acc[0][i].x;
            const float az  = uu ? acc[1][i].y : acc[1][i].x;
            const float ani = uu ? acc[2][i].y : acc[2][i].x;
            const float anh = uu ? acc[3][i].y : acc[3][i].x;
            const float r = fast_sigmoid(ar + bih[j]      + bhh[j]);
            const float z = fast_sigmoid(az + bih[HD+j]   + bhh[HD+j]);
            const float n = fast_tanh(ani + bih[2*HD+j] + r*(anh + bhh[2*HD+j]));
            const float hp = Hprev[(size_t)row*HD + j];
            const float h  = (1.f - z)*n + z*hp;
            Hnew[(size_t)row*HD + j] = h;
            if (Xout) Xout[((size_t)row*LSEQ + t)*HD + j] = h;
            if (FL)  { if (t == flen[row] - 1) FL[(size_t)row*HD + j] = h; }
        }
    }
}

// ---------------- generic C[M,N] = A[M,K] @ W^T (TRANSW=0: W[n*K+k]; 1: W[k*N+n]) ----
template<int TRANSW>
__global__ __launch_bounds__(256) void sgemm_tn(
    const float* __restrict__ A, const float* __restrict__ W, float* __restrict__ C,
    int M, int N, int K)
{
    __shared__ float As[32][68];
    __shared__ float Bs[32][68];
    const int tid = threadIdx.x;
    const int tx = tid & 15, ty = tid >> 4;
    const int mb = blockIdx.x * 64, nb = blockIdx.y * 64;

    float2 acc[4][2];
    #pragma unroll
    for (int i = 0; i < 4; ++i) { acc[i][0] = make_float2(0.f,0.f); acc[i][1] = make_float2(0.f,0.f); }

    for (int kc = 0; kc < K; kc += 32) {
        #pragma unroll
        for (int q = 0; q < 2; ++q) {
            int idx = q*256 + tid;
            int row = idx >> 3;
            int k4  = (idx & 7) << 2;
            const float4 v = *reinterpret_cast<const float4*>(&A[(size_t)(mb+row)*K + kc + k4]);
            As[k4+0][row] = v.x; As[k4+1][row] = v.y; As[k4+2][row] = v.z; As[k4+3][row] = v.w;
        }
        if (!TRANSW) {
            #pragma unroll
            for (int q = 0; q < 2; ++q) {
                int idx = q*256 + tid;
                int n  = idx >> 3;
                int k4 = (idx & 7) << 2;
                const float4 v = *reinterpret_cast<const float4*>(&W[(size_t)(nb+n)*K + kc + k4]);
                Bs[k4+0][n] = v.x; Bs[k4+1][n] = v.y; Bs[k4+2][n] = v.z; Bs[k4+3][n] = v.w;
            }
        } else {
            #pragma unroll
            for (int q = 0; q < 2; ++q) {
                int idx = q*256 + tid;
                int k  = idx >> 4;
                int n4 = (idx & 15) << 2;
                const float4 v = *reinterpret_cast<const float4*>(&W[(size_t)(kc+k)*N + nb + n4]);
                *reinterpret_cast<float4*>(&Bs[k][n4]) = v;
            }
        }
        __syncthreads();
        #pragma unroll
        for (int k = 0; k < 32; ++k) {
            const float4 a4 = *reinterpret_cast<const float4*>(&As[k][ty<<2]);
            const float4 b4 = *reinterpret_cast<const float4*>(&Bs[k][tx<<2]);
            const float2 b0 = make_float2(b4.x, b4.y);
            const float2 b1 = make_float2(b4.z, b4.w);
            float av[4] = {a4.x, a4.y, a4.z, a4.w};
            #pragma unroll
            for (int i = 0; i < 4; ++i) {
                float2 aa = make_float2(av[i], av[i]);
                acc[i][0] = ffma2(aa, b0, acc[i][0]);
                acc[i][1] = ffma2(aa, b1, acc[i][1]);
            }
        }
        __syncthreads();
    }
    #pragma unroll
    for (int i = 0; i < 4; ++i) {
        const int row = mb + (ty<<2) + i;
        float4 o;
        o.x = acc[i][0].x; o.y = acc[i][0].y; o.z = acc[i][1].x; o.w = acc[i][1].y;
        *reinterpret_cast<float4*>(&C[(size_t)row*N + nb + (tx<<2)]) = o;
    }
}

// ---------------- small helper kernels ----------------
__global__ void zero_kernel(float* p, int n){
    int i = blockIdx.x*blockDim.x + threadIdx.x;
    if (i < n) p[i] = 0.f;
}

__global__ void build_cat(const float* __restrict__ self_x,
                          const float* __restrict__ FL,
                          float* __restrict__ CAT){
    const int m = blockIdx.x, tid = threadIdx.x;
    CAT[(size_t)m*2*HD + tid]      = self_x[(size_t)(m>>5)*HD + tid];
    CAT[(size_t)m*2*HD + HD + tid] = FL[(size_t)m*HD + tid];
}

// tf[m] = sum_{s<clen} softplus(common_x[m,s,:]·v[m]) * exp(-common_time[m,s])
__global__ __launch_bounds__(256) void tf_kernel(
    const float* __restrict__ common_x, const float* __restrict__ common_time,
    const float* __restrict__ V, const int* __restrict__ clen, float* __restrict__ TF)
{
    const int m = blockIdx.x;
    __shared__ float vs[HD];
    __shared__ float wsum[8];
    const int tid = threadIdx.x;
    vs[tid] = V[(size_t)m*HD + tid];
    __syncthreads();
    const int warp = tid >> 5, lane = tid & 31;
    const int cl = clen[m];
    float acc = 0.f;
    for (int s = warp; s < cl; s += 8) {
        const float* cx = common_x + ((size_t)m*SSEQ + s)*HD;
        float p = 0.f;
        #pragma unroll
        for (int q = 0; q < 8; ++q) p += cx[lane + 32*q] * vs[lane + 32*q];
        #pragma unroll
        for (int off = 16; off; off >>= 1) p += __shfl_xor_sync(0xffffffffu, p, off);
        if (lane == 0)
            acc += softplus_f(p) * expf(-common_time[(size_t)m*SSEQ + s]);
    }
    if (lane == 0) wsum[warp] = acc;
    __syncthreads();
    if (tid == 0) {
        float s = 0.f;
        for (int w = 0; w < 8; ++w) s += wsum[w];
        TF[m] = s;
    }
}

// softmax over padded MAXF (invalid slots: logit 0, zeroed vectors) + weighted sum
__global__ __launch_bounds__(256) void out_kernel(
    const float* __restrict__ TF, const float* __restrict__ FL,
    const int* __restrict__ fnum, float* __restrict__ out)
{
    const int b = blockIdx.x;
    __shared__ float w[MAXF];
    const int tid = threadIdx.x;
    const int fn = fnum[b];
    if (tid < MAXF) w[tid] = (tid < fn) ? TF[b*MAXF + tid] : 0.f;
    __syncthreads();
    if (tid == 0) {
        float mx = w[0];
        for (int f = 1; f < MAXF; ++f) mx = fmaxf(mx, w[f]);
        float s = 0.f;
        for (int f = 0; f < MAXF; ++f) { float e = expf(w[f] - mx); w[f] = e; s += e; }
        float inv = 1.f / s;
        for (int f = 0; f < MAXF; ++f) w[f] *= inv;
    }
    __syncthreads();
    float acc = 0.f;
    for (int f = 0; f < fn; ++f)
        acc += w[f] * FL[(size_t)(b*MAXF + f)*HD + tid];
    out[(size_t)b*HD + tid] = acc;
}

// ---------------- host launcher ----------------
extern "C" void kernel_launch(void* const* d_in, const int* in_sizes, int n_in,
                              void* d_out, int out_size)
{
    const float* self_x      = (const float*)d_in[0];
    const float* common_x    = (const float*)d_in[1];
    const float* common_time = (const float*)d_in[2];
    const float* friend_x    = (const float*)d_in[3];
    const float* Wih0 = (const float*)d_in[4];
    const float* Whh0 = (const float*)d_in[5];
    const float* bih0 = (const float*)d_in[6];
    const float* bhh0 = (const float*)d_in[7];
    const float* Wih1 = (const float*)d_in[8];
    const float* Whh1 = (const float*)d_in[9];
    const float* bih1 = (const float*)d_in[10];
    const float* bhh1 = (const float*)d_in[11];
    const float* Wf   = (const float*)d_in[12];
    const float* Wb   = (const float*)d_in[13];
    const int*   flen = (const int*)d_in[14];
    const int*   fnum = (const int*)d_in[15];
    const int*   clen = (const int*)d_in[16];
    float* out = (float*)d_out;

    float *Hbase, *X1, *FL, *CAT, *SF, *V, *TF;
    cudaGetSymbolAddress((void**)&Hbase, g_H);
    cudaGetSymbolAddress((void**)&X1,   g_X1);
    cudaGetSymbolAddress((void**)&FL,   g_FL);
    cudaGetSymbolAddress((void**)&CAT,  g_CAT);
    cudaGetSymbolAddress((void**)&SF,   g_SF);
    cudaGetSymbolAddress((void**)&V,    g_V);
    cudaGetSymbolAddress((void**)&TF,   g_TF);
    float* Hb[2] = {Hbase, Hbase + (size_t)NSEQ*HD};

    const dim3 sgrid(NSEQ/MB, HD/UB);

    // ---- GRU layer 0 ----
    zero_kernel<<<(NSEQ*HD + 255)/256, 256>>>(Hb[0], NSEQ*HD);
    for (int t = 0; t < LSEQ; ++t)
        gru_step_kernel<<<sgrid, 256>>>(friend_x, Hb[t&1], Hb[(t+1)&1],
                                        Wih0, Whh0, bih0, bhh0,
                                        X1, nullptr, nullptr, t);
    // ---- GRU layer 1 ----
    zero_kernel<<<(NSEQ*HD + 255)/256, 256>>>(Hb[0], NSEQ*HD);
    for (int t = 0; t < LSEQ; ++t)
        gru_step_kernel<<<sgrid, 256>>>(X1, Hb[t&1], Hb[(t+1)&1],
                                        Wih1, Whh1, bih1, bhh1,
                                        nullptr, FL, flen, t);

    // ---- tail ----
    build_cat<<<NSEQ, 256>>>(self_x, FL, CAT);
    sgemm_tn<0><<<dim3(NSEQ/64, HD/64), 256>>>(CAT, Wf, SF, NSEQ, HD, 2*HD);
    sgemm_tn<1><<<dim3(NSEQ/64, HD/64), 256>>>(SF,  Wb, V,  NSEQ, HD, HD);
    tf_kernel<<<NSEQ, 256>>>(common_x, common_time, V, clen, TF);
    out_kernel<<<NBATCH, 256>>>(TF, FL, fnum, out);
}

// round 3
// speedup vs baseline: 1.6377x; 1.6377x over previous
#include <cuda_runtime.h>
#include <cuda_bf16.h>
#include <cstdint>
#include <math.h>

#define HD    256
#define LSEQ  50
#define SSEQ  50
#define NBATCH 64
#define MAXF  32
#define NSEQ  (NBATCH*MAXF)            // 2048
#define MTOT  (NSEQ*LSEQ)              // 102400
#define G3    (3*HD)                   // 768

// ---------------- device scratch ----------------
__device__ float          g_H[2][NSEQ*HD];
__device__ __nv_bfloat16  g_Hh[2][NSEQ*HD];
__device__ __nv_bfloat16  g_Hl[2][NSEQ*HD];
__device__ float          g_GI[(size_t)MTOT*G3];          // 315 MB (shared by both layers)
__device__ __nv_bfloat16  g_FXh[(size_t)MTOT*HD];
__device__ __nv_bfloat16  g_FXl[(size_t)MTOT*HD];
__device__ __nv_bfloat16  g_X1h[(size_t)MTOT*HD];
__device__ __nv_bfloat16  g_X1l[(size_t)MTOT*HD];
__device__ __nv_bfloat16  g_Wh[4][G3*HD];                 // Wih0,Whh0,Wih1,Whh1 (hi)
__device__ __nv_bfloat16  g_Wl[4][G3*HD];                 // (lo)
__device__ float g_FL[NSEQ*HD];
__device__ float g_CAT[NSEQ*2*HD];
__device__ float g_SF[NSEQ*HD];
__device__ float g_V[NSEQ*HD];
__device__ float g_TF[NSEQ];

// ---------------- helpers ----------------
__device__ __forceinline__ float fast_sigmoid(float x){
    return __fdividef(1.f, 1.f + __expf(-x));
}
__device__ __forceinline__ float fast_tanh(float x){
    return 1.f - __fdividef(2.f, __expf(2.f*x) + 1.f);
}
__device__ __forceinline__ float softplus_f(float x){
    return (x > 20.f) ? x : log1pf(expf(x));
}
__device__ __forceinline__ float2 ffma2(float2 a, float2 b, float2 c){
    unsigned long long ua = reinterpret_cast<unsigned long long&>(a);
    unsigned long long ub = reinterpret_cast<unsigned long long&>(b);
    unsigned long long uc = reinterpret_cast<unsigned long long&>(c);
    unsigned long long ud;
    asm("fma.rn.f32x2 %0, %1, %2, %3;" : "=l"(ud) : "l"(ua), "l"(ub), "l"(uc));
    return reinterpret_cast<float2&>(ud);
}
__device__ __forceinline__ uint32_t smem_u32(const void* p){
    return (uint32_t)__cvta_generic_to_shared(p);
}
__device__ __forceinline__ void ldsm_x4(unsigned* r, uint32_t addr){
    asm volatile("ldmatrix.sync.aligned.m8n8.x4.shared.b16 {%0,%1,%2,%3}, [%4];\n"
        : "=r"(r[0]), "=r"(r[1]), "=r"(r[2]), "=r"(r[3]) : "r"(addr));
}
__device__ __forceinline__ void mma16816(float* c, const unsigned* a, const unsigned* b){
    asm volatile("mma.sync.aligned.m16n8k16.row.col.f32.bf16.bf16.f32 "
        "{%0,%1,%2,%3}, {%4,%5,%6,%7}, {%8,%9}, {%0,%1,%2,%3};\n"
        : "+f"(c[0]), "+f"(c[1]), "+f"(c[2]), "+f"(c[3])
        : "r"(a[0]), "r"(a[1]), "r"(a[2]), "r"(a[3]), "r"(b[0]), "r"(b[1]));
}

// ---------------- hi/lo split conversion ----------------
__global__ void split_kernel(const float* __restrict__ x,
                             __nv_bfloat16* __restrict__ hi,
                             __nv_bfloat16* __restrict__ lo, int n){
    int i = blockIdx.x*256 + threadIdx.x;
    if (i < n){
        float v = x[i];
        __nv_bfloat16 h = __float2bfloat16(v);
        hi[i] = h;
        lo[i] = __float2bfloat16(v - __bfloat162float(h));
    }
}

__global__ void zeroH_kernel(float* __restrict__ H,
                             __nv_bfloat16* __restrict__ Hh,
                             __nv_bfloat16* __restrict__ Hl){
    int i = blockIdx.x*256 + threadIdx.x;
    H[i] = 0.f;
    Hh[i] = __float2bfloat16(0.f);
    Hl[i] = __float2bfloat16(0.f);
}

// =====================================================================
// Unified HMMA GEMM (bf16 hi/lo x3, fp32 accum):
//   C[row, p] = sum_k A[row,k] * W[w(p), k],  w(p) = (p/32)*256 + ub + p%32
// block tile: 128 rows x 96 cols (= 32 units x 3 gates), K=256, 8 warps (4x2)
// EPI=0: write C to GI (row*768 + blockIdx.y*96 + c)         [big x-GEMM]
// EPI=1: GRU gate epilogue (reads GI slice at t, Hprev; emits H/Hh/Hl, X1, FL)
// =====================================================================
struct __align__(16) SmemT {
    union {
        struct {
            unsigned short Ash[128][40];
            unsigned short Asl[128][40];
            unsigned short Bsh[96][40];
            unsigned short Bsl[96][40];
        } s;
        float Cs[128*96];   // 49152 B
    };
};

template<int EPI>
__global__ __launch_bounds__(256) void hmma_kernel(
    const __nv_bfloat16* __restrict__ Ah, const __nv_bfloat16* __restrict__ Al,
    const __nv_bfloat16* __restrict__ Bh, const __nv_bfloat16* __restrict__ Bl,
    float* __restrict__ GI,
    const float* __restrict__ Hprev, float* __restrict__ Hn,
    __nv_bfloat16* __restrict__ Hnh, __nv_bfloat16* __restrict__ Hnl,
    __nv_bfloat16* __restrict__ X1h, __nv_bfloat16* __restrict__ X1l,
    float* __restrict__ FL, const int* __restrict__ flen,
    const float* __restrict__ bih, const float* __restrict__ bhh,
    int t)
{
    __shared__ SmemT sm;
    const int tid  = threadIdx.x;
    const int lane = tid & 31, warp = tid >> 5;
    const int wm = warp >> 1, wn = warp & 1;
    const int row0 = blockIdx.x * 128;
    const int ubu  = blockIdx.y * 32;     // unit base

    // ldmatrix per-thread address components
    const int grp = lane >> 3, rr = lane & 7;
    const int a_m = (grp & 1)*8 + rr, a_k = (grp >> 1)*8;
    const int b_n = (grp >> 1)*8 + rr, b_k = (grp & 1)*8;

    const uint32_t sAsh = smem_u32(&sm.s.Ash[0][0]);
    const uint32_t sAsl = smem_u32(&sm.s.Asl[0][0]);
    const uint32_t sBsh = smem_u32(&sm.s.Bsh[0][0]);
    const uint32_t sBsl = smem_u32(&sm.s.Bsl[0][0]);

    float c[2][6][4];
    #pragma unroll
    for (int mt = 0; mt < 2; ++mt)
        #pragma unroll
        for (int nt = 0; nt < 6; ++nt)
            #pragma unroll
            for (int q = 0; q < 4; ++q) c[mt][nt][q] = 0.f;

    for (int kc = 0; kc < 8; ++kc) {
        const int kk = kc * 32;
        // ---- stage A (128x32 hi+lo): 128 rows x 4 uint4 = 512 slots, 2 iters ----
        #pragma unroll
        for (int q = 0; q < 2; ++q) {
            int idx = q*256 + tid;          // 0..511
            int r = idx >> 2, ks = (idx & 3) << 3;
            *(uint4*)&sm.s.Ash[r][ks] = *(const uint4*)&Ah[(size_t)(row0+r)*HD + kk + ks];
            *(uint4*)&sm.s.Asl[r][ks] = *(const uint4*)&Al[(size_t)(row0+r)*HD + kk + ks];
        }
        // ---- stage B (96x32 hi+lo), strided 3-gate row selection: 384 slots ----
        #pragma unroll
        for (int q = 0; q < 2; ++q) {
            int idx = q*256 + tid;
            if (idx < 384) {
                int p = idx >> 2, ks = (idx & 3) << 3;
                int w = (p >> 5)*HD + ubu + (p & 31);
                *(uint4*)&sm.s.Bsh[p][ks] = *(const uint4*)&Bh[(size_t)w*HD + kk + ks];
                *(uint4*)&sm.s.Bsl[p][ks] = *(const uint4*)&Bl[(size_t)w*HD + kk + ks];
            }
        }
        __syncthreads();
        // ---- MMA over chunk (2 x k16) ----
        #pragma unroll
        for (int kt = 0; kt < 2; ++kt) {
            unsigned ah[2][4], al[2][4], bh[3][4], bl[3][4];
            #pragma unroll
            for (int mt = 0; mt < 2; ++mt) {
                uint32_t off = 2u*((wm*32 + mt*16 + a_m)*40 + kt*16 + a_k);
                ldsm_x4(ah[mt], sAsh + off);
                ldsm_x4(al[mt], sAsl + off);
            }
            #pragma unroll
            for (int np = 0; np < 3; ++np) {
                uint32_t off = 2u*((wn*48 + np*16 + b_n)*40 + kt*16 + b_k);
                ldsm_x4(bh[np], sBsh + off);
                ldsm_x4(bl[np], sBsl + off);
            }
            #pragma unroll
            for (int mt = 0; mt < 2; ++mt)
                #pragma unroll
                for (int nt = 0; nt < 6; ++nt) {
                    const unsigned* B1 = &bh[nt>>1][(nt&1)*2];
                    const unsigned* B2 = &bl[nt>>1][(nt&1)*2];
                    mma16816(c[mt][nt], ah[mt], B1);  // Ah*Bh
                    mma16816(c[mt][nt], al[mt], B1);  // Al*Bh
                    mma16816(c[mt][nt], ah[mt], B2);  // Ah*Bl
                }
        }
        __syncthreads();
    }

    if (EPI == 0) {
        // big GEMM: write pre-activations to GI (packed col = bY*96 + local)
        const size_t colbase = (size_t)blockIdx.y * 96;
        #pragma unroll
        for (int mt = 0; mt < 2; ++mt)
            #pragma unroll
            for (int nt = 0; nt < 6; ++nt) {
                int rw = row0 + wm*32 + mt*16 + (lane >> 2);
                int cl = wn*48 + nt*8 + ((lane & 3) << 1);
                float2 v0 = make_float2(c[mt][nt][0], c[mt][nt][1]);
                float2 v1 = make_float2(c[mt][nt][2], c[mt][nt][3]);
                *(float2*)&GI[(size_t)rw*G3 + colbase + cl]     = v0;
                *(float2*)&GI[(size_t)(rw+8)*G3 + colbase + cl] = v1;
            }
    } else {
        // store pre-activations to SMEM, then fused gate epilogue
        #pragma unroll
        for (int mt = 0; mt < 2; ++mt)
            #pragma unroll
            for (int nt = 0; nt < 6; ++nt) {
                int rl = wm*32 + mt*16 + (lane >> 2);
                int cl = wn*48 + nt*8 + ((lane & 3) << 1);
                *(float2*)&sm.Cs[rl*96 + cl]     = make_float2(c[mt][nt][0], c[mt][nt][1]);
                *(float2*)&sm.Cs[(rl+8)*96 + cl] = make_float2(c[mt][nt][2], c[mt][nt][3]);
            }
        __syncthreads();

        const int jl = tid & 31;
        const int j  = ubu + jl;
        const float b_r  = bih[j]      + bhh[j];
        const float b_z  = bih[HD+j]   + bhh[HD+j];
        const float bi_n = bih[2*HD+j];
        const float bh_n = bhh[2*HD+j];
        const size_t colbase = (size_t)blockIdx.y * 96;

        #pragma unroll
        for (int i = 0; i < 16; ++i) {
            const int rl  = (tid >> 5) + i*8;
            const int row = row0 + rl;
            const size_t gbase = ((size_t)row*LSEQ + t)*G3 + colbase;
            const float ar = sm.Cs[rl*96 + jl];
            const float az = sm.Cs[rl*96 + 32 + jl];
            const float an = sm.Cs[rl*96 + 64 + jl];
            const float r = fast_sigmoid(ar + GI[gbase + jl]      + b_r);
            const float z = fast_sigmoid(az + GI[gbase + 32 + jl] + b_z);
            const float n = fast_tanh(GI[gbase + 64 + jl] + bi_n + r*(an + bh_n));
            const float hp = Hprev[(size_t)row*HD + j];
            const float h  = (1.f - z)*n + z*hp;
            Hn[(size_t)row*HD + j] = h;
            __nv_bfloat16 hh = __float2bfloat16(h);
            __nv_bfloat16 hl = __float2bfloat16(h - __bfloat162float(hh));
            Hnh[(size_t)row*HD + j] = hh;
            Hnl[(size_t)row*HD + j] = hl;
            if (X1h) {
                size_t xi = ((size_t)row*LSEQ + t)*HD + j;
                X1h[xi] = hh; X1l[xi] = hl;
            }
            if (FL) {
                if (t == flen[row] - 1) FL[(size_t)row*HD + j] = h;
            }
        }
    }
}

// ---------------- fp32 tail GEMM (small) ----------------
template<int TRANSW>
__global__ __launch_bounds__(256) void sgemm_tn(
    const float* __restrict__ A, const float* __restrict__ W, float* __restrict__ C,
    int M, int N, int K)
{
    __shared__ float As[32][68];
    __shared__ float Bs[32][68];
    const int tid = threadIdx.x;
    const int tx = tid & 15, ty = tid >> 4;
    const int mb = blockIdx.x * 64, nb = blockIdx.y * 64;

    float2 acc[4][2];
    #pragma unroll
    for (int i = 0; i < 4; ++i) { acc[i][0] = make_float2(0.f,0.f); acc[i][1] = make_float2(0.f,0.f); }

    for (int kc = 0; kc < K; kc += 32) {
        #pragma unroll
        for (int q = 0; q < 2; ++q) {
            int idx = q*256 + tid;
            int row = idx >> 3;
            int k4  = (idx & 7) << 2;
            const float4 v = *reinterpret_cast<const float4*>(&A[(size_t)(mb+row)*K + kc + k4]);
            As[k4+0][row] = v.x; As[k4+1][row] = v.y; As[k4+2][row] = v.z; As[k4+3][row] = v.w;
        }
        if (!TRANSW) {
            #pragma unroll
            for (int q = 0; q < 2; ++q) {
                int idx = q*256 + tid;
                int n  = idx >> 3;
                int k4 = (idx & 7) << 2;
                const float4 v = *reinterpret_cast<const float4*>(&W[(size_t)(nb+n)*K + kc + k4]);
                Bs[k4+0][n] = v.x; Bs[k4+1][n] = v.y; Bs[k4+2][n] = v.z; Bs[k4+3][n] = v.w;
            }
        } else {
            #pragma unroll
            for (int q = 0; q < 2; ++q) {
                int idx = q*256 + tid;
                int k  = idx >> 4;
                int n4 = (idx & 15) << 2;
                const float4 v = *reinterpret_cast<const float4*>(&W[(size_t)(kc+k)*N + nb + n4]);
                *reinterpret_cast<float4*>(&Bs[k][n4]) = v;
            }
        }
        __syncthreads();
        #pragma unroll
        for (int k = 0; k < 32; ++k) {
            const float4 a4 = *reinterpret_cast<const float4*>(&As[k][ty<<2]);
            const float4 b4 = *reinterpret_cast<const float4*>(&Bs[k][tx<<2]);
            const float2 b0 = make_float2(b4.x, b4.y);
            const float2 b1 = make_float2(b4.z, b4.w);
            float av[4] = {a4.x, a4.y, a4.z, a4.w};
            #pragma unroll
            for (int i = 0; i < 4; ++i) {
                float2 aa = make_float2(av[i], av[i]);
                acc[i][0] = ffma2(aa, b0, acc[i][0]);
                acc[i][1] = ffma2(aa, b1, acc[i][1]);
            }
        }
        __syncthreads();
    }
    #pragma unroll
    for (int i = 0; i < 4; ++i) {
        const int row = mb + (ty<<2) + i;
        float4 o;
        o.x = acc[i][0].x; o.y = acc[i][0].y; o.z = acc[i][1].x; o.w = acc[i][1].y;
        *reinterpret_cast<float4*>(&C[(size_t)row*N + nb + (tx<<2)]) = o;
    }
}

__global__ void build_cat(const float* __restrict__ self_x,
                          const float* __restrict__ FL,
                          float* __restrict__ CAT){
    const int m = blockIdx.x, tid = threadIdx.x;
    CAT[(size_t)m*2*HD + tid]      = self_x[(size_t)(m>>5)*HD + tid];
    CAT[(size_t)m*2*HD + HD + tid] = FL[(size_t)m*HD + tid];
}

__global__ __launch_bounds__(256) void tf_kernel(
    const float* __restrict__ common_x, const float* __restrict__ common_time,
    const float* __restrict__ V, const int* __restrict__ clen, float* __restrict__ TF)
{
    const int m = blockIdx.x;
    __shared__ float vs[HD];
    __shared__ float wsum[8];
    const int tid = threadIdx.x;
    vs[tid] = V[(size_t)m*HD + tid];
    __syncthreads();
    const int warp = tid >> 5, lane = tid & 31;
    const int cl = clen[m];
    float acc = 0.f;
    for (int s = warp; s < cl; s += 8) {
        const float* cx = common_x + ((size_t)m*SSEQ + s)*HD;
        float p = 0.f;
        #pragma unroll
        for (int q = 0; q < 8; ++q) p += cx[lane + 32*q] * vs[lane + 32*q];
        #pragma unroll
        for (int off = 16; off; off >>= 1) p += __shfl_xor_sync(0xffffffffu, p, off);
        if (lane == 0)
            acc += softplus_f(p) * expf(-common_time[(size_t)m*SSEQ + s]);
    }
    if (lane == 0) wsum[warp] = acc;
    __syncthreads();
    if (tid == 0) {
        float s = 0.f;
        for (int w = 0; w < 8; ++w) s += wsum[w];
        TF[m] = s;
    }
}

__global__ __launch_bounds__(256) void out_kernel(
    const float* __restrict__ TF, const float* __restrict__ FL,
    const int* __restrict__ fnum, float* __restrict__ out)
{
    const int b = blockIdx.x;
    __shared__ float w[MAXF];
    const int tid = threadIdx.x;
    const int fn = fnum[b];
    if (tid < MAXF) w[tid] = (tid < fn) ? TF[b*MAXF + tid] : 0.f;
    __syncthreads();
    if (tid == 0) {
        float mx = w[0];
        for (int f = 1; f < MAXF; ++f) mx = fmaxf(mx, w[f]);
        float s = 0.f;
        for (int f = 0; f < MAXF; ++f) { float e = expf(w[f] - mx); w[f] = e; s += e; }
        float inv = 1.f / s;
        for (int f = 0; f < MAXF; ++f) w[f] *= inv;
    }
    __syncthreads();
    float acc = 0.f;
    for (int f = 0; f < fn; ++f)
        acc += w[f] * FL[(size_t)(b*MAXF + f)*HD + tid];
    out[(size_t)b*HD + tid] = acc;
}

// ---------------- host launcher ----------------
extern "C" void kernel_launch(void* const* d_in, const int* in_sizes, int n_in,
                              void* d_out, int out_size)
{
    const float* self_x      = (const float*)d_in[0];
    const float* common_x    = (const float*)d_in[1];
    const float* common_time = (const float*)d_in[2];
    const float* friend_x    = (const float*)d_in[3];
    const float* Wih0 = (const float*)d_in[4];
    const float* Whh0 = (const float*)d_in[5];
    const float* bih0 = (const float*)d_in[6];
    const float* bhh0 = (const float*)d_in[7];
    const float* Wih1 = (const float*)d_in[8];
    const float* Whh1 = (const float*)d_in[9];
    const float* bih1 = (const float*)d_in[10];
    const float* bhh1 = (const float*)d_in[11];
    const float* Wf   = (const float*)d_in[12];
    const float* Wb   = (const float*)d_in[13];
    const int*   flen = (const int*)d_in[14];
    const int*   fnum = (const int*)d_in[15];
    const int*   clen = (const int*)d_in[16];
    float* out = (float*)d_out;

    float *H, *GI, *FL, *CAT, *SF, *V, *TF;
    __nv_bfloat16 *Hh, *Hl, *FXh, *FXl, *X1h, *X1l, *Wh, *Wl;
    cudaGetSymbolAddress((void**)&H,   g_H);
    cudaGetSymbolAddress((void**)&Hh,  g_Hh);
    cudaGetSymbolAddress((void**)&Hl,  g_Hl);
    cudaGetSymbolAddress((void**)&GI,  g_GI);
    cudaGetSymbolAddress((void**)&FXh, g_FXh);
    cudaGetSymbolAddress((void**)&FXl, g_FXl);
    cudaGetSymbolAddress((void**)&X1h, g_X1h);
    cudaGetSymbolAddress((void**)&X1l, g_X1l);
    cudaGetSymbolAddress((void**)&Wh,  g_Wh);
    cudaGetSymbolAddress((void**)&Wl,  g_Wl);
    cudaGetSymbolAddress((void**)&FL,  g_FL);
    cudaGetSymbolAddress((void**)&CAT, g_CAT);
    cudaGetSymbolAddress((void**)&SF,  g_SF);
    cudaGetSymbolAddress((void**)&V,   g_V);
    cudaGetSymbolAddress((void**)&TF,  g_TF);

    float* Hp[2]          = {H, H + (size_t)NSEQ*HD};
    __nv_bfloat16* Hhp[2] = {Hh, Hh + (size_t)NSEQ*HD};
    __nv_bfloat16* Hlp[2] = {Hl, Hl + (size_t)NSEQ*HD};
    const float* Wsrc[4]  = {Wih0, Whh0, Wih1, Whh1};

    // --- conversions ---
    split_kernel<<<((size_t)MTOT*HD + 255)/256, 256>>>(friend_x, FXh, FXl, MTOT*HD);
    for (int w = 0; w < 4; ++w)
        split_kernel<<<(G3*HD + 255)/256, 256>>>(Wsrc[w], Wh + (size_t)w*G3*HD,
                                                 Wl + (size_t)w*G3*HD, G3*HD);

    const dim3 big_grid(MTOT/128, 8);
    const dim3 step_grid(NSEQ/128, 8);

    // ---- layer 0 ----
    hmma_kernel<0><<<big_grid, 256>>>(FXh, FXl, Wh + 0*(size_t)G3*HD, Wl + 0*(size_t)G3*HD,
        GI, nullptr, nullptr, nullptr, nullptr, nullptr, nullptr, nullptr, nullptr,
        nullptr, nullptr, 0);
    zeroH_kernel<<<(NSEQ*HD)/256, 256>>>(Hp[0], Hhp[0], Hlp[0]);
    for (int t = 0; t < LSEQ; ++t) {
        int a = t & 1, b = (t+1) & 1;
        hmma_kernel<1><<<step_grid, 256>>>(Hhp[a], Hlp[a],
            Wh + 1*(size_t)G3*HD, Wl + 1*(size_t)G3*HD,
            GI, Hp[a], Hp[b], Hhp[b], Hlp[b],
            X1h, X1l, nullptr, nullptr, bih0, bhh0, t);
    }

    // ---- layer 1 ----
    hmma_kernel<0><<<big_grid, 256>>>(X1h, X1l, Wh + 2*(size_t)G3*HD, Wl + 2*(size_t)G3*HD,
        GI, nullptr, nullptr, nullptr, nullptr, nullptr, nullptr, nullptr, nullptr,
        nullptr, nullptr, 0);
    zeroH_kernel<<<(NSEQ*HD)/256, 256>>>(Hp[0], Hhp[0], Hlp[0]);
    for (int t = 0; t < LSEQ; ++t) {
        int a = t & 1, b = (t+1) & 1;
        hmma_kernel<1><<<step_grid, 256>>>(Hhp[a], Hlp[a],
            Wh + 3*(size_t)G3*HD, Wl + 3*(size_t)G3*HD,
            GI, Hp[a], Hp[b], Hhp[b], Hlp[b],
            nullptr, nullptr, FL, flen, bih1, bhh1, t);
    }

    // ---- tail ----
    build_cat<<<NSEQ, 256>>>(self_x, FL, CAT);
    sgemm_tn<0><<<dim3(NSEQ/64, HD/64), 256>>>(CAT, Wf, SF, NSEQ, HD, 2*HD);
    sgemm_tn<1><<<dim3(NSEQ/64, HD/64), 256>>>(SF,  Wb, V,  NSEQ, HD, HD);
    tf_kernel<<<NSEQ, 256>>>(common_x, common_time, V, clen, TF);
    out_kernel<<<NBATCH, 256>>>(TF, FL, fnum, out);
}

// round 4
// speedup vs baseline: 1.7051x; 1.0411x over previous
#include <cuda_runtime.h>
#include <cuda_bf16.h>
#include <cstdint>
#include <math.h>

#define HD    256
#define LSEQ  50
#define SSEQ  50
#define NBATCH 64
#define MAXF  32
#define NSEQ  (NBATCH*MAXF)            // 2048
#define MTOT  (NSEQ*LSEQ)              // 102400
#define G3    (3*HD)                   // 768

// ---------------- device scratch ----------------
__device__ float          g_H[2][NSEQ*HD];
__device__ __nv_bfloat16  g_Hh[2][NSEQ*HD];
__device__ __nv_bfloat16  g_Hl[2][NSEQ*HD];
__device__ float          g_GI[(size_t)MTOT*G3];          // 315 MB (shared by both layers)
__device__ __nv_bfloat16  g_FXh[(size_t)MTOT*HD];
__device__ __nv_bfloat16  g_FXl[(size_t)MTOT*HD];
__device__ __nv_bfloat16  g_X1h[(size_t)MTOT*HD];
__device__ __nv_bfloat16  g_X1l[(size_t)MTOT*HD];
__device__ __nv_bfloat16  g_Wh[4][G3*HD];                 // Wih0,Whh0,Wih1,Whh1 (hi)
__device__ __nv_bfloat16  g_Wl[4][G3*HD];                 // (lo)
__device__ float g_FL[NSEQ*HD];
__device__ float g_CAT[NSEQ*2*HD];
__device__ float g_SF[NSEQ*HD];
__device__ float g_V[NSEQ*HD];
__device__ float g_TF[NSEQ];
__device__ unsigned g_cnt[16];                            // per-rowgroup step counters

// ---------------- helpers ----------------
__device__ __forceinline__ float fast_sigmoid(float x){
    return __fdividef(1.f, 1.f + __expf(-x));
}
__device__ __forceinline__ float fast_tanh(float x){
    return 1.f - __fdividef(2.f, __expf(2.f*x) + 1.f);
}
__device__ __forceinline__ float softplus_f(float x){
    return (x > 20.f) ? x : log1pf(expf(x));
}
__device__ __forceinline__ float2 ffma2(float2 a, float2 b, float2 c){
    unsigned long long ua = reinterpret_cast<unsigned long long&>(a);
    unsigned long long ub = reinterpret_cast<unsigned long long&>(b);
    unsigned long long uc = reinterpret_cast<unsigned long long&>(c);
    unsigned long long ud;
    asm("fma.rn.f32x2 %0, %1, %2, %3;" : "=l"(ud) : "l"(ua), "l"(ub), "l"(uc));
    return reinterpret_cast<float2&>(ud);
}
__device__ __forceinline__ uint32_t smem_u32(const void* p){
    return (uint32_t)__cvta_generic_to_shared(p);
}
__device__ __forceinline__ void ldsm_x4(unsigned* r, uint32_t addr){
    asm volatile("ldmatrix.sync.aligned.m8n8.x4.shared.b16 {%0,%1,%2,%3}, [%4];\n"
        : "=r"(r[0]), "=r"(r[1]), "=r"(r[2]), "=r"(r[3]) : "r"(addr));
}
__device__ __forceinline__ void mma16816(float* c, const unsigned* a, const unsigned* b){
    asm volatile("mma.sync.aligned.m16n8k16.row.col.f32.bf16.bf16.f32 "
        "{%0,%1,%2,%3}, {%4,%5,%6,%7}, {%8,%9}, {%0,%1,%2,%3};\n"
        : "+f"(c[0]), "+f"(c[1]), "+f"(c[2]), "+f"(c[3])
        : "r"(a[0]), "r"(a[1]), "r"(a[2]), "r"(a[3]), "r"(b[0]), "r"(b[1]));
}
__device__ __forceinline__ unsigned ld_acq(const unsigned* p){
    unsigned v;
    asm volatile("ld.acquire.gpu.u32 %0, [%1];" : "=r"(v) : "l"(p) : "memory");
    return v;
}

// ---------------- hi/lo split conversion ----------------
__global__ void split_kernel(const float* __restrict__ x,
                             __nv_bfloat16* __restrict__ hi,
                             __nv_bfloat16* __restrict__ lo, int n){
    int i = blockIdx.x*256 + threadIdx.x;
    if (i < n){
        float v = x[i];
        __nv_bfloat16 h = __float2bfloat16(v);
        hi[i] = h;
        lo[i] = __float2bfloat16(v - __bfloat162float(h));
    }
}

__global__ void zeroH_kernel(float* __restrict__ H,
                             __nv_bfloat16* __restrict__ Hh,
                             __nv_bfloat16* __restrict__ Hl){
    int i = blockIdx.x*256 + threadIdx.x;
    H[i] = 0.f;
    Hh[i] = __float2bfloat16(0.f);
    Hl[i] = __float2bfloat16(0.f);
    if (blockIdx.x == 0 && threadIdx.x < 16) g_cnt[threadIdx.x] = 0u;
}

// =====================================================================
// Big x-GEMM: GI[row, by*96 + c] = sum_k A[row,k]*W[w(c),k], 3-term bf16
// =====================================================================
struct __align__(16) SmemBig {
    unsigned short Ash[128][40];
    unsigned short Asl[128][40];
    unsigned short Bsh[96][40];
    unsigned short Bsl[96][40];
};

__global__ __launch_bounds__(256) void hmma_big(
    const __nv_bfloat16* __restrict__ Ah, const __nv_bfloat16* __restrict__ Al,
    const __nv_bfloat16* __restrict__ Bh, const __nv_bfloat16* __restrict__ Bl,
    float* __restrict__ GI)
{
    __shared__ SmemBig sm;
    const int tid  = threadIdx.x;
    const int lane = tid & 31, warp = tid >> 5;
    const int wm = warp >> 1, wn = warp & 1;
    const int row0 = blockIdx.x * 128;
    const int ubu  = blockIdx.y * 32;

    const int grp = lane >> 3, rr = lane & 7;
    const int a_m = (grp & 1)*8 + rr, a_k = (grp >> 1)*8;
    const int b_n = (grp >> 1)*8 + rr, b_k = (grp & 1)*8;

    const uint32_t sAsh = smem_u32(&sm.Ash[0][0]);
    const uint32_t sAsl = smem_u32(&sm.Asl[0][0]);
    const uint32_t sBsh = smem_u32(&sm.Bsh[0][0]);
    const uint32_t sBsl = smem_u32(&sm.Bsl[0][0]);

    float c[2][6][4];
    #pragma unroll
    for (int mt = 0; mt < 2; ++mt)
        #pragma unroll
        for (int nt = 0; nt < 6; ++nt)
            #pragma unroll
            for (int q = 0; q < 4; ++q) c[mt][nt][q] = 0.f;

    for (int kc = 0; kc < 8; ++kc) {
        const int kk = kc * 32;
        #pragma unroll
        for (int q = 0; q < 2; ++q) {
            int idx = q*256 + tid;
            int r = idx >> 2, ks = (idx & 3) << 3;
            *(uint4*)&sm.Ash[r][ks] = *(const uint4*)&Ah[(size_t)(row0+r)*HD + kk + ks];
            *(uint4*)&sm.Asl[r][ks] = *(const uint4*)&Al[(size_t)(row0+r)*HD + kk + ks];
        }
        #pragma unroll
        for (int q = 0; q < 2; ++q) {
            int idx = q*256 + tid;
            if (idx < 384) {
                int p = idx >> 2, ks = (idx & 3) << 3;
                int w = (p >> 5)*HD + ubu + (p & 31);
                *(uint4*)&sm.Bsh[p][ks] = *(const uint4*)&Bh[(size_t)w*HD + kk + ks];
                *(uint4*)&sm.Bsl[p][ks] = *(const uint4*)&Bl[(size_t)w*HD + kk + ks];
            }
        }
        __syncthreads();
        #pragma unroll
        for (int kt = 0; kt < 2; ++kt) {
            unsigned ah[2][4], al[2][4], bh[3][4], bl[3][4];
            #pragma unroll
            for (int mt = 0; mt < 2; ++mt) {
                uint32_t off = 2u*((wm*32 + mt*16 + a_m)*40 + kt*16 + a_k);
                ldsm_x4(ah[mt], sAsh + off);
                ldsm_x4(al[mt], sAsl + off);
            }
            #pragma unroll
            for (int np = 0; np < 3; ++np) {
                uint32_t off = 2u*((wn*48 + np*16 + b_n)*40 + kt*16 + b_k);
                ldsm_x4(bh[np], sBsh + off);
                ldsm_x4(bl[np], sBsl + off);
            }
            #pragma unroll
            for (int mt = 0; mt < 2; ++mt)
                #pragma unroll
                for (int nt = 0; nt < 6; ++nt) {
                    const unsigned* B1 = &bh[nt>>1][(nt&1)*2];
                    const unsigned* B2 = &bl[nt>>1][(nt&1)*2];
                    mma16816(c[mt][nt], ah[mt], B1);
                    mma16816(c[mt][nt], al[mt], B1);
                    mma16816(c[mt][nt], ah[mt], B2);
                }
        }
        __syncthreads();
    }

    const size_t colbase = (size_t)blockIdx.y * 96;
    #pragma unroll
    for (int mt = 0; mt < 2; ++mt)
        #pragma unroll
        for (int nt = 0; nt < 6; ++nt) {
            int rw = row0 + wm*32 + mt*16 + (lane >> 2);
            int cl = wn*48 + nt*8 + ((lane & 3) << 1);
            *(float2*)&GI[(size_t)rw*G3 + colbase + cl]     = make_float2(c[mt][nt][0], c[mt][nt][1]);
            *(float2*)&GI[(size_t)(rw+8)*G3 + colbase + cl] = make_float2(c[mt][nt][2], c[mt][nt][3]);
        }
}

// =====================================================================
// Persistent GRU recurrence: ONE launch per layer, 128 CTAs (16 rowgroups x 8
// unit-blocks), Whh tile resident in SMEM for all 50 steps, per-rowgroup
// 8-CTA barriers between steps (monotonic counters, release/acquire).
// Dynamic SMEM layout (bytes):
//   [0)              Bsh: 96 x 264 shorts  (50688)
//   [50688)          Bsl: 96 x 264 shorts  (50688)
//   [101376)         union { Ash[128][40]+Asl[128][40] shorts | Cs[128*96] float }
//   total 150528
// =====================================================================
#define SM_B_STRIDE 264
#define SM_TOTAL_PERSIST (96*SM_B_STRIDE*2*2 + 128*96*4)

template<int LAYER>
__global__ __launch_bounds__(256) void gru_persist(
    const __nv_bfloat16* __restrict__ Whh_h, const __nv_bfloat16* __restrict__ Whh_l,
    const float* __restrict__ GI,
    float* __restrict__ Hbase,
    __nv_bfloat16* __restrict__ Hhb, __nv_bfloat16* __restrict__ Hlb,
    __nv_bfloat16* __restrict__ X1h, __nv_bfloat16* __restrict__ X1l,
    float* __restrict__ FL, const int* __restrict__ flen,
    const float* __restrict__ bih, const float* __restrict__ bhh)
{
    extern __shared__ unsigned short sdyn[];
    unsigned short* Bsh = sdyn;                       // 96 x 264
    unsigned short* Bsl = Bsh + 96*SM_B_STRIDE;
    unsigned short* Ash = Bsl + 96*SM_B_STRIDE;       // union begin
    unsigned short* Asl = Ash + 128*40;
    float* Cs = (float*)(Bsl + 96*SM_B_STRIDE);       // overlaps Ash/Asl

    const int tid  = threadIdx.x;
    const int lane = tid & 31, warp = tid >> 5;
    const int wm = warp >> 1, wn = warp & 1;
    const int rg   = blockIdx.x;          // rowgroup 0..15
    const int row0 = rg * 128;
    const int ubu  = blockIdx.y * 32;

    const int grp = lane >> 3, rr = lane & 7;
    const int a_m = (grp & 1)*8 + rr, a_k = (grp >> 1)*8;
    const int b_n = (grp >> 1)*8 + rr, b_k = (grp & 1)*8;

    const uint32_t sAsh = smem_u32(Ash);
    const uint32_t sAsl = smem_u32(Asl);
    const uint32_t sBsh = smem_u32(Bsh);
    const uint32_t sBsl = smem_u32(Bsl);

    // ---- load Whh tile once (96 gate-rows x 256 k, hi+lo) ----
    for (int idx = tid; idx < 96*32; idx += 256) {     // 96 rows x 32 uint4
        int p = idx >> 5, ks = (idx & 31) << 3;
        int w = (p >> 5)*HD + ubu + (p & 31);
        *(uint4*)&Bsh[p*SM_B_STRIDE + ks] = *(const uint4*)&Whh_h[(size_t)w*HD + ks];
        *(uint4*)&Bsl[p*SM_B_STRIDE + ks] = *(const uint4*)&Whh_l[(size_t)w*HD + ks];
    }
    __syncthreads();

    const int jl = tid & 31;
    const int j  = ubu + jl;
    const float b_r  = bih[j]      + bhh[j];
    const float b_z  = bih[HD+j]   + bhh[HD+j];
    const float bi_n = bih[2*HD+j];
    const float bh_n = bhh[2*HD+j];
    const size_t colbase = (size_t)blockIdx.y * 96;

    for (int t = 0; t < LSEQ; ++t) {
        const int pa = t & 1, pb = (t+1) & 1;
        const float* Hprev = Hbase + (size_t)pa*NSEQ*HD;
        float* Hn          = Hbase + (size_t)pb*NSEQ*HD;
        const __nv_bfloat16* Ah = Hhb + (size_t)pa*NSEQ*HD;
        const __nv_bfloat16* Al = Hlb + (size_t)pa*NSEQ*HD;
        __nv_bfloat16* Hnh = Hhb + (size_t)pb*NSEQ*HD;
        __nv_bfloat16* Hnl = Hlb + (size_t)pb*NSEQ*HD;

        float c[2][6][4];
        #pragma unroll
        for (int mt = 0; mt < 2; ++mt)
            #pragma unroll
            for (int nt = 0; nt < 6; ++nt)
                #pragma unroll
                for (int q = 0; q < 4; ++q) c[mt][nt][q] = 0.f;

        for (int kc = 0; kc < 8; ++kc) {
            const int kk = kc * 32;
            #pragma unroll
            for (int q = 0; q < 2; ++q) {
                int idx = q*256 + tid;
                int r = idx >> 2, ks = (idx & 3) << 3;
                *(uint4*)&Ash[r*40 + ks] = *(const uint4*)&Ah[(size_t)(row0+r)*HD + kk + ks];
                *(uint4*)&Asl[r*40 + ks] = *(const uint4*)&Al[(size_t)(row0+r)*HD + kk + ks];
            }
            __syncthreads();
            #pragma unroll
            for (int kt = 0; kt < 2; ++kt) {
                unsigned ah[2][4], al[2][4], bh[3][4], bl[3][4];
                #pragma unroll
                for (int mt = 0; mt < 2; ++mt) {
                    uint32_t off = 2u*((wm*32 + mt*16 + a_m)*40 + kt*16 + a_k);
                    ldsm_x4(ah[mt], sAsh + off);
                    ldsm_x4(al[mt], sAsl + off);
                }
                #pragma unroll
                for (int np = 0; np < 3; ++np) {
                    uint32_t off = 2u*((wn*48 + np*16 + b_n)*SM_B_STRIDE + kk + kt*16 + b_k);
                    ldsm_x4(bh[np], sBsh + off);
                    ldsm_x4(bl[np], sBsl + off);
                }
                #pragma unroll
                for (int mt = 0; mt < 2; ++mt)
                    #pragma unroll
                    for (int nt = 0; nt < 6; ++nt) {
                        const unsigned* B1 = &bh[nt>>1][(nt&1)*2];
                        const unsigned* B2 = &bl[nt>>1][(nt&1)*2];
                        mma16816(c[mt][nt], ah[mt], B1);
                        mma16816(c[mt][nt], al[mt], B1);
                        mma16816(c[mt][nt], ah[mt], B2);
                    }
            }
            __syncthreads();
        }

        // ---- write pre-activations to Cs, then gate epilogue ----
        #pragma unroll
        for (int mt = 0; mt < 2; ++mt)
            #pragma unroll
            for (int nt = 0; nt < 6; ++nt) {
                int rl = wm*32 + mt*16 + (lane >> 2);
                int cl = wn*48 + nt*8 + ((lane & 3) << 1);
                *(float2*)&Cs[rl*96 + cl]     = make_float2(c[mt][nt][0], c[mt][nt][1]);
                *(float2*)&Cs[(rl+8)*96 + cl] = make_float2(c[mt][nt][2], c[mt][nt][3]);
            }
        __syncthreads();

        #pragma unroll
        for (int i = 0; i < 16; ++i) {
            const int rl  = (tid >> 5) + i*8;
            const int row = row0 + rl;
            const size_t gbase = ((size_t)row*LSEQ + t)*G3 + colbase;
            const float ar = Cs[rl*96 + jl];
            const float az = Cs[rl*96 + 32 + jl];
            const float an = Cs[rl*96 + 64 + jl];
            const float r = fast_sigmoid(ar + GI[gbase + jl]      + b_r);
            const float z = fast_sigmoid(az + GI[gbase + 32 + jl] + b_z);
            const float n = fast_tanh(GI[gbase + 64 + jl] + bi_n + r*(an + bh_n));
            const float hp = Hprev[(size_t)row*HD + j];
            const float h  = (1.f - z)*n + z*hp;
            Hn[(size_t)row*HD + j] = h;
            __nv_bfloat16 hh = __float2bfloat16(h);
            __nv_bfloat16 hl = __float2bfloat16(h - __bfloat162float(hh));
            Hnh[(size_t)row*HD + j] = hh;
            Hnl[(size_t)row*HD + j] = hl;
            if (LAYER == 0) {
                size_t xi = ((size_t)row*LSEQ + t)*HD + j;
                X1h[xi] = hh; X1l[xi] = hl;
            } else {
                if (t == flen[row] - 1) FL[(size_t)row*HD + j] = h;
            }
        }

        // ---- 8-CTA rowgroup barrier (monotonic counter) ----
        __threadfence();
        __syncthreads();
        if (tid == 0) {
            atomicAdd(&g_cnt[rg], 1u);
            const unsigned target = 8u*(unsigned)(t+1);
            while (ld_acq(&g_cnt[rg]) < target) __nanosleep(32);
        }
        __syncthreads();
    }
}

// ---------------- fp32 tail GEMM (small) ----------------
template<int TRANSW>
__global__ __launch_bounds__(256) void sgemm_tn(
    const float* __restrict__ A, const float* __restrict__ W, float* __restrict__ C,
    int M, int N, int K)
{
    __shared__ float As[32][68];
    __shared__ float Bs[32][68];
    const int tid = threadIdx.x;
    const int tx = tid & 15, ty = tid >> 4;
    const int mb = blockIdx.x * 64, nb = blockIdx.y * 64;

    float2 acc[4][2];
    #pragma unroll
    for (int i = 0; i < 4; ++i) { acc[i][0] = make_float2(0.f,0.f); acc[i][1] = make_float2(0.f,0.f); }

    for (int kc = 0; kc < K; kc += 32) {
        #pragma unroll
        for (int q = 0; q < 2; ++q) {
            int idx = q*256 + tid;
            int row = idx >> 3;
            int k4  = (idx & 7) << 2;
            const float4 v = *reinterpret_cast<const float4*>(&A[(size_t)(mb+row)*K + kc + k4]);
            As[k4+0][row] = v.x; As[k4+1][row] = v.y; As[k4+2][row] = v.z; As[k4+3][row] = v.w;
        }
        if (!TRANSW) {
            #pragma unroll
            for (int q = 0; q < 2; ++q) {
                int idx = q*256 + tid;
                int n  = idx >> 3;
                int k4 = (idx & 7) << 2;
                const float4 v = *reinterpret_cast<const float4*>(&W[(size_t)(nb+n)*K + kc + k4]);
                Bs[k4+0][n] = v.x; Bs[k4+1][n] = v.y; Bs[k4+2][n] = v.z; Bs[k4+3][n] = v.w;
            }
        } else {
            #pragma unroll
            for (int q = 0; q < 2; ++q) {
                int idx = q*256 + tid;
                int k  = idx >> 4;
                int n4 = (idx & 15) << 2;
                const float4 v = *reinterpret_cast<const float4*>(&W[(size_t)(kc+k)*N + nb + n4]);
                *reinterpret_cast<float4*>(&Bs[k][n4]) = v;
            }
        }
        __syncthreads();
        #pragma unroll
        for (int k = 0; k < 32; ++k) {
            const float4 a4 = *reinterpret_cast<const float4*>(&As[k][ty<<2]);
            const float4 b4 = *reinterpret_cast<const float4*>(&Bs[k][tx<<2]);
            const float2 b0 = make_float2(b4.x, b4.y);
            const float2 b1 = make_float2(b4.z, b4.w);
            float av[4] = {a4.x, a4.y, a4.z, a4.w};
            #pragma unroll
            for (int i = 0; i < 4; ++i) {
                float2 aa = make_float2(av[i], av[i]);
                acc[i][0] = ffma2(aa, b0, acc[i][0]);
                acc[i][1] = ffma2(aa, b1, acc[i][1]);
            }
        }
        __syncthreads();
    }
    #pragma unroll
    for (int i = 0; i < 4; ++i) {
        const int row = mb + (ty<<2) + i;
        float4 o;
        o.x = acc[i][0].x; o.y = acc[i][0].y; o.z = acc[i][1].x; o.w = acc[i][1].y;
        *reinterpret_cast<float4*>(&C[(size_t)row*N + nb + (tx<<2)]) = o;
    }
}

__global__ void build_cat(const float* __restrict__ self_x,
                          const float* __restrict__ FL,
                          float* __restrict__ CAT){
    const int m = blockIdx.x, tid = threadIdx.x;
    CAT[(size_t)m*2*HD + tid]      = self_x[(size_t)(m>>5)*HD + tid];
    CAT[(size_t)m*2*HD + HD + tid] = FL[(size_t)m*HD + tid];
}

__global__ __launch_bounds__(256) void tf_kernel(
    const float* __restrict__ common_x, const float* __restrict__ common_time,
    const float* __restrict__ V, const int* __restrict__ clen, float* __restrict__ TF)
{
    const int m = blockIdx.x;
    __shared__ float vs[HD];
    __shared__ float wsum[8];
    const int tid = threadIdx.x;
    vs[tid] = V[(size_t)m*HD + tid];
    __syncthreads();
    const int warp = tid >> 5, lane = tid & 31;
    const int cl = clen[m];
    float acc = 0.f;
    for (int s = warp; s < cl; s += 8) {
        const float* cx = common_x + ((size_t)m*SSEQ + s)*HD;
        float p = 0.f;
        #pragma unroll
        for (int q = 0; q < 8; ++q) p += cx[lane + 32*q] * vs[lane + 32*q];
        #pragma unroll
        for (int off = 16; off; off >>= 1) p += __shfl_xor_sync(0xffffffffu, p, off);
        if (lane == 0)
            acc += softplus_f(p) * expf(-common_time[(size_t)m*SSEQ + s]);
    }
    if (lane == 0) wsum[warp] = acc;
    __syncthreads();
    if (tid == 0) {
        float s = 0.f;
        for (int w = 0; w < 8; ++w) s += wsum[w];
        TF[m] = s;
    }
}

__global__ __launch_bounds__(256) void out_kernel(
    const float* __restrict__ TF, const float* __restrict__ FL,
    const int* __restrict__ fnum, float* __restrict__ out)
{
    const int b = blockIdx.x;
    __shared__ float w[MAXF];
    const int tid = threadIdx.x;
    const int fn = fnum[b];
    if (tid < MAXF) w[tid] = (tid < fn) ? TF[b*MAXF + tid] : 0.f;
    __syncthreads();
    if (tid == 0) {
        float mx = w[0];
        for (int f = 1; f < MAXF; ++f) mx = fmaxf(mx, w[f]);
        float s = 0.f;
        for (int f = 0; f < MAXF; ++f) { float e = expf(w[f] - mx); w[f] = e; s += e; }
        float inv = 1.f / s;
        for (int f = 0; f < MAXF; ++f) w[f] *= inv;
    }
    __syncthreads();
    float acc = 0.f;
    for (int f = 0; f < fn; ++f)
        acc += w[f] * FL[(size_t)(b*MAXF + f)*HD + tid];
    out[(size_t)b*HD + tid] = acc;
}

// ---------------- host launcher ----------------
extern "C" void kernel_launch(void* const* d_in, const int* in_sizes, int n_in,
                              void* d_out, int out_size)
{
    const float* self_x      = (const float*)d_in[0];
    const float* common_x    = (const float*)d_in[1];
    const float* common_time = (const float*)d_in[2];
    const float* friend_x    = (const float*)d_in[3];
    const float* Wih0 = (const float*)d_in[4];
    const float* Whh0 = (const float*)d_in[5];
    const float* bih0 = (const float*)d_in[6];
    const float* bhh0 = (const float*)d_in[7];
    const float* Wih1 = (const float*)d_in[8];
    const float* Whh1 = (const float*)d_in[9];
    const float* bih1 = (const float*)d_in[10];
    const float* bhh1 = (const float*)d_in[11];
    const float* Wf   = (const float*)d_in[12];
    const float* Wb   = (const float*)d_in[13];
    const int*   flen = (const int*)d_in[14];
    const int*   fnum = (const int*)d_in[15];
    const int*   clen = (const int*)d_in[16];
    float* out = (float*)d_out;

    float *H, *GI, *FL, *CAT, *SF, *V, *TF;
    __nv_bfloat16 *Hh, *Hl, *FXh, *FXl, *X1h, *X1l, *Wh, *Wl;
    cudaGetSymbolAddress((void**)&H,   g_H);
    cudaGetSymbolAddress((void**)&Hh,  g_Hh);
    cudaGetSymbolAddress((void**)&Hl,  g_Hl);
    cudaGetSymbolAddress((void**)&GI,  g_GI);
    cudaGetSymbolAddress((void**)&FXh, g_FXh);
    cudaGetSymbolAddress((void**)&FXl, g_FXl);
    cudaGetSymbolAddress((void**)&X1h, g_X1h);
    cudaGetSymbolAddress((void**)&X1l, g_X1l);
    cudaGetSymbolAddress((void**)&Wh,  g_Wh);
    cudaGetSymbolAddress((void**)&Wl,  g_Wl);
    cudaGetSymbolAddress((void**)&FL,  g_FL);
    cudaGetSymbolAddress((void**)&CAT, g_CAT);
    cudaGetSymbolAddress((void**)&SF,  g_SF);
    cudaGetSymbolAddress((void**)&V,   g_V);
    cudaGetSymbolAddress((void**)&TF,  g_TF);

    const float* Wsrc[4] = {Wih0, Whh0, Wih1, Whh1};

    static bool attr_done = false;
    if (!attr_done) {
        cudaFuncSetAttribute(gru_persist<0>, cudaFuncAttributeMaxDynamicSharedMemorySize, SM_TOTAL_PERSIST);
        cudaFuncSetAttribute(gru_persist<1>, cudaFuncAttributeMaxDynamicSharedMemorySize, SM_TOTAL_PERSIST);
        attr_done = true;
    }

    // --- conversions ---
    split_kernel<<<((size_t)MTOT*HD + 255)/256, 256>>>(friend_x, FXh, FXl, MTOT*HD);
    for (int w = 0; w < 4; ++w)
        split_kernel<<<(G3*HD + 255)/256, 256>>>(Wsrc[w], Wh + (size_t)w*G3*HD,
                                                 Wl + (size_t)w*G3*HD, G3*HD);

    const dim3 big_grid(MTOT/128, 8);
    const dim3 pgrid(16, 8);

    // ---- layer 0 ----
    hmma_big<<<big_grid, 256>>>(FXh, FXl, Wh + 0*(size_t)G3*HD, Wl + 0*(size_t)G3*HD, GI);
    zeroH_kernel<<<(NSEQ*HD)/256, 256>>>(H, Hh, Hl);
    gru_persist<0><<<pgrid, 256, SM_TOTAL_PERSIST>>>(
        Wh + 1*(size_t)G3*HD, Wl + 1*(size_t)G3*HD, GI,
        H, Hh, Hl, X1h, X1l, nullptr, nullptr, bih0, bhh0);

    // ---- layer 1 ----
    hmma_big<<<big_grid, 256>>>(X1h, X1l, Wh + 2*(size_t)G3*HD, Wl + 2*(size_t)G3*HD, GI);
    zeroH_kernel<<<(NSEQ*HD)/256, 256>>>(H, Hh, Hl);
    gru_persist<1><<<pgrid, 256, SM_TOTAL_PERSIST>>>(
        Wh + 3*(size_t)G3*HD, Wl + 3*(size_t)G3*HD, GI,
        H, Hh, Hl, nullptr, nullptr, FL, flen, bih1, bhh1);

    // ---- tail ----
    build_cat<<<NSEQ, 256>>>(self_x, FL, CAT);
    sgemm_tn<0><<<dim3(NSEQ/64, HD/64), 256>>>(CAT, Wf, SF, NSEQ, HD, 2*HD);
    sgemm_tn<1><<<dim3(NSEQ/64, HD/64), 256>>>(SF,  Wb, V,  NSEQ, HD, HD);
    tf_kernel<<<NSEQ, 256>>>(common_x, common_time, V, clen, TF);
    out_kernel<<<NBATCH, 256>>>(TF, FL, fnum, out);
}

// round 6
// speedup vs baseline: 1.8980x; 1.1131x over previous
#include <cuda_runtime.h>
#include <cuda_bf16.h>
#include <cstdint>
#include <math.h>

#define HD    256
#define LSEQ  50
#define SSEQ  50
#define NBATCH 64
#define MAXF  32
#define NSEQ  (NBATCH*MAXF)            // 2048
#define MTOT  (NSEQ*LSEQ)              // 102400
#define G3    (3*HD)                   // 768

// ---------------- device scratch ----------------
__device__ float          g_H[2][NSEQ*HD];
__device__ __nv_bfloat16  g_Hh[2][NSEQ*HD];
__device__ __nv_bfloat16  g_Hl[2][NSEQ*HD];
__device__ float          g_GI[(size_t)MTOT*G3];
__device__ __nv_bfloat16  g_FXh[(size_t)MTOT*HD];
__device__ __nv_bfloat16  g_FXl[(size_t)MTOT*HD];
__device__ __nv_bfloat16  g_X1h[(size_t)MTOT*HD];
__device__ __nv_bfloat16  g_X1l[(size_t)MTOT*HD];
__device__ __nv_bfloat16  g_Wh[4][G3*HD];
__device__ __nv_bfloat16  g_Wl[4][G3*HD];
__device__ float g_FL[NSEQ*HD];
__device__ float g_CAT[NSEQ*2*HD];
__device__ float g_SF[NSEQ*HD];
__device__ float g_V[NSEQ*HD];
__device__ float g_TF[NSEQ];
__device__ unsigned g_cnt[16];

// ---------------- helpers ----------------
__device__ __forceinline__ float fast_sigmoid(float x){
    return __fdividef(1.f, 1.f + __expf(-x));
}
__device__ __forceinline__ float fast_tanh(float x){
    return 1.f - __fdividef(2.f, __expf(2.f*x) + 1.f);
}
__device__ __forceinline__ float softplus_f(float x){
    return (x > 20.f) ? x : log1pf(expf(x));
}
__device__ __forceinline__ float2 ffma2(float2 a, float2 b, float2 c){
    unsigned long long ua = reinterpret_cast<unsigned long long&>(a);
    unsigned long long ub = reinterpret_cast<unsigned long long&>(b);
    unsigned long long uc = reinterpret_cast<unsigned long long&>(c);
    unsigned long long ud;
    asm("fma.rn.f32x2 %0, %1, %2, %3;" : "=l"(ud) : "l"(ua), "l"(ub), "l"(uc));
    return reinterpret_cast<float2&>(ud);
}
__device__ __forceinline__ uint32_t smem_u32(const void* p){
    return (uint32_t)__cvta_generic_to_shared(p);
}
__device__ __forceinline__ void ldsm_x4(unsigned* r, uint32_t addr){
    asm volatile("ldmatrix.sync.aligned.m8n8.x4.shared.b16 {%0,%1,%2,%3}, [%4];\n"
        : "=r"(r[0]), "=r"(r[1]), "=r"(r[2]), "=r"(r[3]) : "r"(addr));
}
__device__ __forceinline__ void mma16816(float* c, const unsigned* a, const unsigned* b){
    asm volatile("mma.sync.aligned.m16n8k16.row.col.f32.bf16.bf16.f32 "
        "{%0,%1,%2,%3}, {%4,%5,%6,%7}, {%8,%9}, {%0,%1,%2,%3};\n"
        : "+f"(c[0]), "+f"(c[1]), "+f"(c[2]), "+f"(c[3])
        : "r"(a[0]), "r"(a[1]), "r"(a[2]), "r"(a[3]), "r"(b[0]), "r"(b[1]));
}
__device__ __forceinline__ unsigned ld_acq(const unsigned* p){
    unsigned v;
    asm volatile("ld.acquire.gpu.u32 %0, [%1];" : "=r"(v) : "l"(p) : "memory");
    return v;
}
__device__ __forceinline__ void cp16(uint32_t dst, const void* src){
    asm volatile("cp.async.cg.shared.global [%0], [%1], 16;" :: "r"(dst), "l"(src) : "memory");
}
#define CP_COMMIT() asm volatile("cp.async.commit_group;" ::: "memory")
#define CP_WAIT1()  asm volatile("cp.async.wait_group 1;" ::: "memory")
#define CP_WAIT0()  asm volatile("cp.async.wait_group 0;" ::: "memory")

// ---------------- staging (cp.async, one 32-k chunk) ----------------
// A chunk: 128 rows x 32 k, padded stride 40 shorts
__device__ __forceinline__ void stageA_cp(uint32_t sA_h, uint32_t sA_l,
        const __nv_bfloat16* __restrict__ Ah, const __nv_bfloat16* __restrict__ Al,
        int row0, int kk, int tid){
    #pragma unroll
    for (int q = 0; q < 2; ++q) {
        int idx = q*256 + tid;            // 0..511
        int r = idx >> 2, ks = (idx & 3) << 3;
        size_t s = (size_t)(row0+r)*HD + kk + ks;
        uint32_t d = (uint32_t)(r*40 + ks)*2u;
        cp16(sA_h + d, Ah + s);
        cp16(sA_l + d, Al + s);
    }
}
// B chunk: 96 gate-rows (p -> (p/32)*256 + ubu + p%32) x 32 k, stride 40
__device__ __forceinline__ void stageB_cp(uint32_t sB_h, uint32_t sB_l,
        const __nv_bfloat16* __restrict__ Bh, const __nv_bfloat16* __restrict__ Bl,
        int ubu, int kk, int tid){
    #pragma unroll
    for (int q = 0; q < 2; ++q) {
        int idx = q*256 + tid;
        if (idx < 384) {
            int p = idx >> 2, ks = (idx & 3) << 3;
            int w = (p >> 5)*HD + ubu + (p & 31);
            size_t s = (size_t)w*HD + kk + ks;
            uint32_t d = (uint32_t)(p*40 + ks)*2u;
            cp16(sB_h + d, Bh + s);
            cp16(sB_l + d, Bl + s);
        }
    }
}

// ---------------- MMA on one staged 32-k chunk (3-term hi/lo) ----------------
__device__ __forceinline__ void mma_chunk(
    float (&c)[2][6][4],
    uint32_t aAsh, uint32_t aAsl, uint32_t aBsh, uint32_t aBsl,
    int a_m, int a_k, int b_n, int b_k, int wm, int wn, int bstride, int bkoff)
{
    #pragma unroll
    for (int kt = 0; kt < 2; ++kt) {
        unsigned ah[2][4], al[2][4], bh[3][4], bl[3][4];
        #pragma unroll
        for (int mt = 0; mt < 2; ++mt) {
            uint32_t off = 2u*((wm*32 + mt*16 + a_m)*40 + kt*16 + a_k);
            ldsm_x4(ah[mt], aAsh + off);
            ldsm_x4(al[mt], aAsl + off);
        }
        #pragma unroll
        for (int np = 0; np < 3; ++np) {
            uint32_t off = 2u*((wn*48 + np*16 + b_n)*bstride + bkoff + kt*16 + b_k);
            ldsm_x4(bh[np], aBsh + off);
            ldsm_x4(bl[np], aBsl + off);
        }
        #pragma unroll
        for (int mt = 0; mt < 2; ++mt)
            #pragma unroll
            for (int nt = 0; nt < 6; ++nt) {
                const unsigned* B1 = &bh[nt>>1][(nt&1)*2];
                const unsigned* B2 = &bl[nt>>1][(nt&1)*2];
                mma16816(c[mt][nt], ah[mt], B1);
                mma16816(c[mt][nt], al[mt], B1);
                mma16816(c[mt][nt], ah[mt], B2);
            }
    }
}

// ---------------- hi/lo split conversion ----------------
__global__ void split_kernel(const float* __restrict__ x,
                             __nv_bfloat16* __restrict__ hi,
                             __nv_bfloat16* __restrict__ lo, int n){
    int i = blockIdx.x*256 + threadIdx.x;
    if (i < n){
        float v = x[i];
        __nv_bfloat16 h = __float2bfloat16(v);
        hi[i] = h;
        lo[i] = __float2bfloat16(v - __bfloat162float(h));
    }
}

__global__ void zeroH_kernel(float* __restrict__ H,
                             __nv_bfloat16* __restrict__ Hh,
                             __nv_bfloat16* __restrict__ Hl){
    int i = blockIdx.x*256 + threadIdx.x;
    H[i] = 0.f;
    Hh[i] = __float2bfloat16(0.f);
    Hl[i] = __float2bfloat16(0.f);
    if (blockIdx.x == 0 && threadIdx.x < 16) g_cnt[threadIdx.x] = 0u;
}

// =====================================================================
// Big x-GEMM, cp.async double-buffered. grid (8 unit-blocks, 800 row-blocks)
// dyn smem: Ash[2]10240 | Asl[2]10240*? layout below (bytes):
//   ASH 0 (2 x 10240), ASL 20480 (2 x 10240), BSH 40960 (2 x 7680), BSL 56320
// =====================================================================
#define BIG_ASH 0u
#define BIG_ASL 20480u
#define BIG_BSH 40960u
#define BIG_BSL 56320u
#define BIG_DYN 71680u

__global__ __launch_bounds__(256) void hmma_big(
    const __nv_bfloat16* __restrict__ Ah, const __nv_bfloat16* __restrict__ Al,
    const __nv_bfloat16* __restrict__ Bh, const __nv_bfloat16* __restrict__ Bl,
    float* __restrict__ GI)
{
    extern __shared__ char smraw[];
    const uint32_t sb = smem_u32(smraw);
    const int tid  = threadIdx.x;
    const int lane = tid & 31, warp = tid >> 5;
    const int wm = warp >> 1, wn = warp & 1;
    const int ubu  = blockIdx.x * 32;
    const int row0 = blockIdx.y * 128;

    const int grp = lane >> 3, rr = lane & 7;
    const int a_m = (grp & 1)*8 + rr, a_k = (grp >> 1)*8;
    const int b_n = (grp >> 1)*8 + rr, b_k = (grp & 1)*8;

    float c[2][6][4];
    #pragma unroll
    for (int mt = 0; mt < 2; ++mt)
        #pragma unroll
        for (int nt = 0; nt < 6; ++nt)
            #pragma unroll
            for (int q = 0; q < 4; ++q) c[mt][nt][q] = 0.f;

    // prologue: prefetch chunk 0 into buffer 0
    stageA_cp(sb + BIG_ASH, sb + BIG_ASL, Ah, Al, row0, 0, tid);
    stageB_cp(sb + BIG_BSH, sb + BIG_BSL, Bh, Bl, ubu, 0, tid);
    CP_COMMIT();

    for (int kc = 0; kc < 8; ++kc) {
        const int buf = kc & 1;
        if (kc < 7) {
            const int nb = buf ^ 1;
            stageA_cp(sb + BIG_ASH + nb*10240u, sb + BIG_ASL + nb*10240u,
                      Ah, Al, row0, (kc+1)*32, tid);
            stageB_cp(sb + BIG_BSH + nb*7680u, sb + BIG_BSL + nb*7680u,
                      Bh, Bl, ubu, (kc+1)*32, tid);
            CP_COMMIT();
            CP_WAIT1();
        } else {
            CP_WAIT0();
        }
        __syncthreads();
        mma_chunk(c, sb + BIG_ASH + buf*10240u, sb + BIG_ASL + buf*10240u,
                     sb + BIG_BSH + buf*7680u,  sb + BIG_BSL + buf*7680u,
                  a_m, a_k, b_n, b_k, wm, wn, 40, 0);
        __syncthreads();
    }

    const size_t colbase = (size_t)blockIdx.x * 96;
    #pragma unroll
    for (int mt = 0; mt < 2; ++mt)
        #pragma unroll
        for (int nt = 0; nt < 6; ++nt) {
            int rw = row0 + wm*32 + mt*16 + (lane >> 2);
            int cl = wn*48 + nt*8 + ((lane & 3) << 1);
            *(float2*)&GI[(size_t)rw*G3 + colbase + cl]     = make_float2(c[mt][nt][0], c[mt][nt][1]);
            *(float2*)&GI[(size_t)(rw+8)*G3 + colbase + cl] = make_float2(c[mt][nt][2], c[mt][nt][3]);
        }
}

// =====================================================================
// Persistent GRU recurrence, Whh resident + cp.async double-buffered A.
// grid (16 rowgroups, 8 unit-blocks). dyn smem (bytes):
//   BSH 0 (50688 = 96x264 shorts), BSL 50688,
//   ASH 101376 (2 x 10240), ASL 121856 (2 x 10240), CS 142336 (49152)
// =====================================================================
#define GRU_BSH 0u
#define GRU_BSL 50688u
#define GRU_ASH 101376u
#define GRU_ASL 121856u
#define GRU_CS  142336u
#define GRU_DYN 191488u
#define SM_B_STRIDE 264

template<int LAYER>
__global__ __launch_bounds__(256) void gru_persist(
    const __nv_bfloat16* __restrict__ Whh_h, const __nv_bfloat16* __restrict__ Whh_l,
    const float* __restrict__ GI,
    float* __restrict__ Hbase,
    __nv_bfloat16* __restrict__ Hhb, __nv_bfloat16* __restrict__ Hlb,
    __nv_bfloat16* __restrict__ X1h, __nv_bfloat16* __restrict__ X1l,
    float* __restrict__ FL, const int* __restrict__ flen,
    const float* __restrict__ bih, const float* __restrict__ bhh)
{
    extern __shared__ char smraw[];
    const uint32_t sb = smem_u32(smraw);
    unsigned short* Bsh = (unsigned short*)(smraw + GRU_BSH);
    unsigned short* Bsl = (unsigned short*)(smraw + GRU_BSL);
    float* Cs = (float*)(smraw + GRU_CS);

    const int tid  = threadIdx.x;
    const int lane = tid & 31, warp = tid >> 5;
    const int wm = warp >> 1, wn = warp & 1;
    const int rg   = blockIdx.x;
    const int row0 = rg * 128;
    const int ubu  = blockIdx.y * 32;

    const int grp = lane >> 3, rr = lane & 7;
    const int a_m = (grp & 1)*8 + rr, a_k = (grp >> 1)*8;
    const int b_n = (grp >> 1)*8 + rr, b_k = (grp & 1)*8;

    // ---- load Whh tile once (96 gate-rows x 256 k, hi+lo) ----
    for (int idx = tid; idx < 96*32; idx += 256) {     // 96 rows x 32 uint4
        int p = idx >> 5, ks = (idx & 31) << 3;
        int w = (p >> 5)*HD + ubu + (p & 31);
        *(uint4*)&Bsh[p*SM_B_STRIDE + ks] = *(const uint4*)&Whh_h[(size_t)w*HD + ks];
        *(uint4*)&Bsl[p*SM_B_STRIDE + ks] = *(const uint4*)&Whh_l[(size_t)w*HD + ks];
    }
    __syncthreads();

    const int jl = tid & 31;
    const int j  = ubu + jl;
    const float b_r  = bih[j]      + bhh[j];
    const float b_z  = bih[HD+j]   + bhh[HD+j];
    const float bi_n = bih[2*HD+j];
    const float bh_n = bhh[2*HD+j];
    const size_t colbase = (size_t)blockIdx.y * 96;

    for (int t = 0; t < LSEQ; ++t) {
        const int pa = t & 1, pb = (t+1) & 1;
        const float* Hprev = Hbase + (size_t)pa*NSEQ*HD;
        float* Hn          = Hbase + (size_t)pb*NSEQ*HD;
        const __nv_bfloat16* Ahp = Hhb + (size_t)pa*NSEQ*HD;
        const __nv_bfloat16* Alp = Hlb + (size_t)pa*NSEQ*HD;
        __nv_bfloat16* Hnh = Hhb + (size_t)pb*NSEQ*HD;
        __nv_bfloat16* Hnl = Hlb + (size_t)pb*NSEQ*HD;

        float c[2][6][4];
        #pragma unroll
        for (int mt = 0; mt < 2; ++mt)
            #pragma unroll
            for (int nt = 0; nt < 6; ++nt)
                #pragma unroll
                for (int q = 0; q < 4; ++q) c[mt][nt][q] = 0.f;

        if (t > 0) {   // h(0)=0 -> GEMM result is exactly 0, skip
            stageA_cp(sb + GRU_ASH, sb + GRU_ASL, Ahp, Alp, row0, 0, tid);
            CP_COMMIT();
            for (int kc = 0; kc < 8; ++kc) {
                const int buf = kc & 1;
                if (kc < 7) {
                    const int nb = buf ^ 1;
                    stageA_cp(sb + GRU_ASH + nb*10240u, sb + GRU_ASL + nb*10240u,
                              Ahp, Alp, row0, (kc+1)*32, tid);
                    CP_COMMIT();
                    CP_WAIT1();
                } else {
                    CP_WAIT0();
                }
                __syncthreads();
                mma_chunk(c, sb + GRU_ASH + buf*10240u, sb + GRU_ASL + buf*10240u,
                             sb + GRU_BSH, sb + GRU_BSL,
                          a_m, a_k, b_n, b_k, wm, wn, SM_B_STRIDE, kc*32);
                __syncthreads();
            }
        }

        // ---- pre-activations to Cs, then gate epilogue ----
        #pragma unroll
        for (int mt = 0; mt < 2; ++mt)
            #pragma unroll
            for (int nt = 0; nt < 6; ++nt) {
                int rl = wm*32 + mt*16 + (lane >> 2);
                int cl = wn*48 + nt*8 + ((lane & 3) << 1);
                *(float2*)&Cs[rl*96 + cl]     = make_float2(c[mt][nt][0], c[mt][nt][1]);
                *(float2*)&Cs[(rl+8)*96 + cl] = make_float2(c[mt][nt][2], c[mt][nt][3]);
            }
        __syncthreads();

        #pragma unroll
        for (int i = 0; i < 16; ++i) {
            const int rl  = (tid >> 5) + i*8;
            const int row = row0 + rl;
            const size_t gbase = ((size_t)row*LSEQ + t)*G3 + colbase;
            const float ar = Cs[rl*96 + jl];
            const float az = Cs[rl*96 + 32 + jl];
            const float an = Cs[rl*96 + 64 + jl];
            const float r = fast_sigmoid(ar + GI[gbase + jl]      + b_r);
            const float z = fast_sigmoid(az + GI[gbase + 32 + jl] + b_z);
            const float n = fast_tanh(GI[gbase + 64 + jl] + bi_n + r*(an + bh_n));
            const float hp = Hprev[(size_t)row*HD + j];
            const float h  = (1.f - z)*n + z*hp;
            Hn[(size_t)row*HD + j] = h;
            __nv_bfloat16 hh = __float2bfloat16(h);
            __nv_bfloat16 hl = __float2bfloat16(h - __bfloat162float(hh));
            Hnh[(size_t)row*HD + j] = hh;
            Hnl[(size_t)row*HD + j] = hl;
            if (LAYER == 0) {
                size_t xi = ((size_t)row*LSEQ + t)*HD + j;
                X1h[xi] = hh; X1l[xi] = hl;
            } else {
                if (t == flen[row] - 1) FL[(size_t)row*HD + j] = h;
            }
        }

        // ---- 8-CTA rowgroup barrier (monotonic counter) ----
        __threadfence();
        __syncthreads();
        if (tid == 0) {
            atomicAdd(&g_cnt[rg], 1u);
            const unsigned target = 8u*(unsigned)(t+1);
            while (ld_acq(&g_cnt[rg]) < target) __nanosleep(32);
        }
        __syncthreads();
    }
}

// ---------------- fp32 tail GEMM (small) ----------------
template<int TRANSW>
__global__ __launch_bounds__(256) void sgemm_tn(
    const float* __restrict__ A, const float* __restrict__ W, float* __restrict__ C,
    int M, int N, int K)
{
    __shared__ float As[32][68];
    __shared__ float Bs[32][68];
    const int tid = threadIdx.x;
    const int tx = tid & 15, ty = tid >> 4;
    const int mb = blockIdx.x * 64, nb = blockIdx.y * 64;

    float2 acc[4][2];
    #pragma unroll
    for (int i = 0; i < 4; ++i) { acc[i][0] = make_float2(0.f,0.f); acc[i][1] = make_float2(0.f,0.f); }

    for (int kc = 0; kc < K; kc += 32) {
        #pragma unroll
        for (int q = 0; q < 2; ++q) {
            int idx = q*256 + tid;
            int row = idx >> 3;
            int k4  = (idx & 7) << 2;
            const float4 v = *reinterpret_cast<const float4*>(&A[(size_t)(mb+row)*K + kc + k4]);
            As[k4+0][row] = v.x; As[k4+1][row] = v.y; As[k4+2][row] = v.z; As[k4+3][row] = v.w;
        }
        if (!TRANSW) {
            #pragma unroll
            for (int q = 0; q < 2; ++q) {
                int idx = q*256 + tid;
                int n  = idx >> 3;
                int k4 = (idx & 7) << 2;
                const float4 v = *reinterpret_cast<const float4*>(&W[(size_t)(nb+n)*K + kc + k4]);
                Bs[k4+0][n] = v.x; Bs[k4+1][n] = v.y; Bs[k4+2][n] = v.z; Bs[k4+3][n] = v.w;
            }
        } else {
            #pragma unroll
            for (int q = 0; q < 2; ++q) {
                int idx = q*256 + tid;
                int k  = idx >> 4;
                int n4 = (idx & 15) << 2;
                const float4 v = *reinterpret_cast<const float4*>(&W[(size_t)(kc+k)*N + nb + n4]);
                *reinterpret_cast<float4*>(&Bs[k][n4]) = v;
            }
        }
        __syncthreads();
        #pragma unroll
        for (int k = 0; k < 32; ++k) {
            const float4 a4 = *reinterpret_cast<const float4*>(&As[k][ty<<2]);
            const float4 b4 = *reinterpret_cast<const float4*>(&Bs[k][tx<<2]);
            const float2 b0 = make_float2(b4.x, b4.y);
            const float2 b1 = make_float2(b4.z, b4.w);
            float av[4] = {a4.x, a4.y, a4.z, a4.w};
            #pragma unroll
            for (int i = 0; i < 4; ++i) {
                float2 aa = make_float2(av[i], av[i]);
                acc[i][0] = ffma2(aa, b0, acc[i][0]);
                acc[i][1] = ffma2(aa, b1, acc[i][1]);
            }
        }
        __syncthreads();
    }
    #pragma unroll
    for (int i = 0; i < 4; ++i) {
        const int row = mb + (ty<<2) + i;
        float4 o;
        o.x = acc[i][0].x; o.y = acc[i][0].y; o.z = acc[i][1].x; o.w = acc[i][1].y;
        *reinterpret_cast<float4*>(&C[(size_t)row*N + nb + (tx<<2)]) = o;
    }
}

__global__ void build_cat(const float* __restrict__ self_x,
                          const float* __restrict__ FL,
                          float* __restrict__ CAT){
    const int m = blockIdx.x, tid = threadIdx.x;
    CAT[(size_t)m*2*HD + tid]      = self_x[(size_t)(m>>5)*HD + tid];
    CAT[(size_t)m*2*HD + HD + tid] = FL[(size_t)m*HD + tid];
}

__global__ __launch_bounds__(256) void tf_kernel(
    const float* __restrict__ common_x, const float* __restrict__ common_time,
    const float* __restrict__ V, const int* __restrict__ clen, float* __restrict__ TF)
{
    const int m = blockIdx.x;
    __shared__ float vs[HD];
    __shared__ float wsum[8];
    const int tid = threadIdx.x;
    vs[tid] = V[(size_t)m*HD + tid];
    __syncthreads();
    const int warp = tid >> 5, lane = tid & 31;
    const int cl = clen[m];
    float acc = 0.f;
    for (int s = warp; s < cl; s += 8) {
        const float* cx = common_x + ((size_t)m*SSEQ + s)*HD;
        float p = 0.f;
        #pragma unroll
        for (int q = 0; q < 8; ++q) p += cx[lane + 32*q] * vs[lane + 32*q];
        #pragma unroll
        for (int off = 16; off; off >>= 1) p += __shfl_xor_sync(0xffffffffu, p, off);
        if (lane == 0)
            acc += softplus_f(p) * expf(-common_time[(size_t)m*SSEQ + s]);
    }
    if (lane == 0) wsum[warp] = acc;
    __syncthreads();
    if (tid == 0) {
        float s = 0.f;
        for (int w = 0; w < 8; ++w) s += wsum[w];
        TF[m] = s;
    }
}

__global__ __launch_bounds__(256) void out_kernel(
    const float* __restrict__ TF, const float* __restrict__ FL,
    const int* __restrict__ fnum, float* __restrict__ out)
{
    const int b = blockIdx.x;
    __shared__ float w[MAXF];
    const int tid = threadIdx.x;
    const int fn = fnum[b];
    if (tid < MAXF) w[tid] = (tid < fn) ? TF[b*MAXF + tid] : 0.f;
    __syncthreads();
    if (tid == 0) {
        float mx = w[0];
        for (int f = 1; f < MAXF; ++f) mx = fmaxf(mx, w[f]);
        float s = 0.f;
        for (int f = 0; f < MAXF; ++f) { float e = expf(w[f] - mx); w[f] = e; s += e; }
        float inv = 1.f / s;
        for (int f = 0; f < MAXF; ++f) w[f] *= inv;
    }
    __syncthreads();
    float acc = 0.f;
    for (int f = 0; f < fn; ++f)
        acc += w[f] * FL[(size_t)(b*MAXF + f)*HD + tid];
    out[(size_t)b*HD + tid] = acc;
}

// ---------------- host launcher ----------------
extern "C" void kernel_launch(void* const* d_in, const int* in_sizes, int n_in,
                              void* d_out, int out_size)
{
    const float* self_x      = (const float*)d_in[0];
    const float* common_x    = (const float*)d_in[1];
    const float* common_time = (const float*)d_in[2];
    const float* friend_x    = (const float*)d_in[3];
    const float* Wih0 = (const float*)d_in[4];
    const float* Whh0 = (const float*)d_in[5];
    const float* bih0 = (const float*)d_in[6];
    const float* bhh0 = (const float*)d_in[7];
    const float* Wih1 = (const float*)d_in[8];
    const float* Whh1 = (const float*)d_in[9];
    const float* bih1 = (const float*)d_in[10];
    const float* bhh1 = (const float*)d_in[11];
    const float* Wf   = (const float*)d_in[12];
    const float* Wb   = (const float*)d_in[13];
    const int*   flen = (const int*)d_in[14];
    const int*   fnum = (const int*)d_in[15];
    const int*   clen = (const int*)d_in[16];
    float* out = (float*)d_out;

    float *H, *GI, *FL, *CAT, *SF, *V, *TF;
    __nv_bfloat16 *Hh, *Hl, *FXh, *FXl, *X1h, *X1l, *Wh, *Wl;
    cudaGetSymbolAddress((void**)&H,   g_H);
    cudaGetSymbolAddress((void**)&Hh,  g_Hh);
    cudaGetSymbolAddress((void**)&Hl,  g_Hl);
    cudaGetSymbolAddress((void**)&GI,  g_GI);
    cudaGetSymbolAddress((void**)&FXh, g_FXh);
    cudaGetSymbolAddress((void**)&FXl, g_FXl);
    cudaGetSymbolAddress((void**)&X1h, g_X1h);
    cudaGetSymbolAddress((void**)&X1l, g_X1l);
    cudaGetSymbolAddress((void**)&Wh,  g_Wh);
    cudaGetSymbolAddress((void**)&Wl,  g_Wl);
    cudaGetSymbolAddress((void**)&FL,  g_FL);
    cudaGetSymbolAddress((void**)&CAT, g_CAT);
    cudaGetSymbolAddress((void**)&SF,  g_SF);
    cudaGetSymbolAddress((void**)&V,   g_V);
    cudaGetSymbolAddress((void**)&TF,  g_TF);

    const float* Wsrc[4] = {Wih0, Whh0, Wih1, Whh1};

    static bool attr_done = false;
    if (!attr_done) {
        cudaFuncSetAttribute(hmma_big,      cudaFuncAttributeMaxDynamicSharedMemorySize, BIG_DYN);
        cudaFuncSetAttribute(gru_persist<0>, cudaFuncAttributeMaxDynamicSharedMemorySize, GRU_DYN);
        cudaFuncSetAttribute(gru_persist<1>, cudaFuncAttributeMaxDynamicSharedMemorySize, GRU_DYN);
        attr_done = true;
    }

    // --- conversions ---
    split_kernel<<<((size_t)MTOT*HD + 255)/256, 256>>>(friend_x, FXh, FXl, MTOT*HD);
    for (int w = 0; w < 4; ++w)
        split_kernel<<<(G3*HD + 255)/256, 256>>>(Wsrc[w], Wh + (size_t)w*G3*HD,
                                                 Wl + (size_t)w*G3*HD, G3*HD);

    const dim3 big_grid(8, MTOT/128);   // unit-fast -> A reuse in L2
    const dim3 pgrid(16, 8);

    // ---- layer 0 ----
    hmma_big<<<big_grid, 256, BIG_DYN>>>(FXh, FXl, Wh + 0*(size_t)G3*HD, Wl + 0*(size_t)G3*HD, GI);
    zeroH_kernel<<<(NSEQ*HD)/256, 256>>>(H, Hh, Hl);
    gru_persist<0><<<pgrid, 256, GRU_DYN>>>(
        Wh + 1*(size_t)G3*HD, Wl + 1*(size_t)G3*HD, GI,
        H, Hh, Hl, X1h, X1l, nullptr, nullptr, bih0, bhh0);

    // ---- layer 1 ----
    hmma_big<<<big_grid, 256, BIG_DYN>>>(X1h, X1l, Wh + 2*(size_t)G3*HD, Wl + 2*(size_t)G3*HD, GI);
    zeroH_kernel<<<(NSEQ*HD)/256, 256>>>(H, Hh, Hl);
    gru_persist<1><<<pgrid, 256, GRU_DYN>>>(
        Wh + 3*(size_t)G3*HD, Wl + 3*(size_t)G3*HD, GI,
        H, Hh, Hl, nullptr, nullptr, FL, flen, bih1, bhh1);

    // ---- tail ----
    build_cat<<<NSEQ, 256>>>(self_x, FL, CAT);
    sgemm_tn<0><<<dim3(NSEQ/64, HD/64), 256>>>(CAT, Wf, SF, NSEQ, HD, 2*HD);
    sgemm_tn<1><<<dim3(NSEQ/64, HD/64), 256>>>(SF,  Wb, V,  NSEQ, HD, HD);
    tf_kernel<<<NSEQ, 256>>>(common_x, common_time, V, clen, TF);
    out_kernel<<<NBATCH, 256>>>(TF, FL, fnum, out);
}

// round 7
// speedup vs baseline: 2.1586x; 1.1373x over previous
#include <cuda_runtime.h>
#include <cuda_bf16.h>
#include <cstdint>
#include <math.h>

#define HD    256
#define LSEQ  50
#define SSEQ  50
#define NBATCH 64
#define MAXF  32
#define NSEQ  (NBATCH*MAXF)            // 2048
#define MTOT  (NSEQ*LSEQ)              // 102400
#define G3    (3*HD)                   // 768

// ---------------- device scratch ----------------
__device__ float          g_H[2][NSEQ*HD];
__device__ __nv_bfloat16  g_Hh[2][NSEQ*HD];
__device__ __nv_bfloat16  g_Hl[2][NSEQ*HD];
__device__ float          g_GI[(size_t)MTOT*G3];
__device__ __nv_bfloat16  g_FXh[(size_t)MTOT*HD];
__device__ __nv_bfloat16  g_FXl[(size_t)MTOT*HD];
__device__ __nv_bfloat16  g_X1h[(size_t)MTOT*HD];
__device__ __nv_bfloat16  g_X1l[(size_t)MTOT*HD];
__device__ __nv_bfloat16  g_Wh[4][G3*HD];
__device__ __nv_bfloat16  g_Wl[4][G3*HD];
__device__ float g_FL[NSEQ*HD];
__device__ float g_CAT[NSEQ*2*HD];
__device__ float g_SF[NSEQ*HD];
__device__ float g_V[NSEQ*HD];
__device__ float g_TF[NSEQ];
__device__ unsigned g_cnt[16];

// ---------------- helpers ----------------
__device__ __forceinline__ float fast_sigmoid(float x){
    return __fdividef(1.f, 1.f + __expf(-x));
}
__device__ __forceinline__ float fast_tanh(float x){
    return 1.f - __fdividef(2.f, __expf(2.f*x) + 1.f);
}
__device__ __forceinline__ float softplus_f(float x){
    return (x > 20.f) ? x : log1pf(expf(x));
}
__device__ __forceinline__ float2 ffma2(float2 a, float2 b, float2 c){
    unsigned long long ua = reinterpret_cast<unsigned long long&>(a);
    unsigned long long ub = reinterpret_cast<unsigned long long&>(b);
    unsigned long long uc = reinterpret_cast<unsigned long long&>(c);
    unsigned long long ud;
    asm("fma.rn.f32x2 %0, %1, %2, %3;" : "=l"(ud) : "l"(ua), "l"(ub), "l"(uc));
    return reinterpret_cast<float2&>(ud);
}
__device__ __forceinline__ uint32_t smem_u32(const void* p){
    return (uint32_t)__cvta_generic_to_shared(p);
}
__device__ __forceinline__ void ldsm_x4(unsigned* r, uint32_t addr){
    asm volatile("ldmatrix.sync.aligned.m8n8.x4.shared.b16 {%0,%1,%2,%3}, [%4];\n"
        : "=r"(r[0]), "=r"(r[1]), "=r"(r[2]), "=r"(r[3]) : "r"(addr));
}
__device__ __forceinline__ void mma16816(float* c, const unsigned* a, const unsigned* b){
    asm volatile("mma.sync.aligned.m16n8k16.row.col.f32.bf16.bf16.f32 "
        "{%0,%1,%2,%3}, {%4,%5,%6,%7}, {%8,%9}, {%0,%1,%2,%3};\n"
        : "+f"(c[0]), "+f"(c[1]), "+f"(c[2]), "+f"(c[3])
        : "r"(a[0]), "r"(a[1]), "r"(a[2]), "r"(a[3]), "r"(b[0]), "r"(b[1]));
}
__device__ __forceinline__ unsigned ld_acq(const unsigned* p){
    unsigned v;
    asm volatile("ld.acquire.gpu.u32 %0, [%1];" : "=r"(v) : "l"(p) : "memory");
    return v;
}
__device__ __forceinline__ void cp16(uint32_t dst, const void* src){
    asm volatile("cp.async.cg.shared.global [%0], [%1], 16;" :: "r"(dst), "l"(src) : "memory");
}
#define CP_COMMIT() asm volatile("cp.async.commit_group;" ::: "memory")
#define CP_WAIT1()  asm volatile("cp.async.wait_group 1;" ::: "memory")
#define CP_WAIT0()  asm volatile("cp.async.wait_group 0;" ::: "memory")

// ---------------- staging (cp.async, one 32-k chunk) ----------------
__device__ __forceinline__ void stageA_cp(uint32_t sA_h, uint32_t sA_l,
        const __nv_bfloat16* __restrict__ Ah, const __nv_bfloat16* __restrict__ Al,
        int row0, int kk, int tid){
    #pragma unroll
    for (int q = 0; q < 2; ++q) {
        int idx = q*256 + tid;            // 0..511
        int r = idx >> 2, ks = (idx & 3) << 3;
        size_t s = (size_t)(row0+r)*HD + kk + ks;
        uint32_t d = (uint32_t)(r*40 + ks)*2u;
        cp16(sA_h + d, Ah + s);
        cp16(sA_l + d, Al + s);
    }
}
__device__ __forceinline__ void stageB_cp(uint32_t sB_h, uint32_t sB_l,
        const __nv_bfloat16* __restrict__ Bh, const __nv_bfloat16* __restrict__ Bl,
        int ubu, int kk, int tid){
    #pragma unroll
    for (int q = 0; q < 2; ++q) {
        int idx = q*256 + tid;
        if (idx < 384) {
            int p = idx >> 2, ks = (idx & 3) << 3;
            int w = (p >> 5)*HD + ubu + (p & 31);
            size_t s = (size_t)w*HD + kk + ks;
            uint32_t d = (uint32_t)(p*40 + ks)*2u;
            cp16(sB_h + d, Bh + s);
            cp16(sB_l + d, Bl + s);
        }
    }
}
// GI piece: 1/8 of a 128x96 fp32 slice into Cs (stride 128 floats), cols 0..95
__device__ __forceinline__ void stageGI_piece(uint32_t cs, const float* __restrict__ GI,
        int row0, int t, size_t colbase, int piece, int tid){
    #pragma unroll
    for (int q = 0; q < 2; ++q) {
        int i = q*256 + tid;
        if (i < 384) {
            int i2 = piece*384 + i;          // 0..3071
            int rl = i2 / 24, c16 = i2 % 24; // 24 x 16B per row
            const float* src = GI + ((size_t)(row0+rl)*LSEQ + t)*G3 + colbase + c16*4;
            cp16(cs + (uint32_t)(rl*128 + c16*4)*4u, src);
        }
    }
}

// ---------------- MMA on one staged 32-k chunk (3-term hi/lo) ----------------
__device__ __forceinline__ void mma_chunk(
    float (&c)[2][6][4],
    uint32_t aAsh, uint32_t aAsl, uint32_t aBsh, uint32_t aBsl,
    int a_m, int a_k, int b_n, int b_k, int wm, int wn, int bstride, int bkoff)
{
    #pragma unroll
    for (int kt = 0; kt < 2; ++kt) {
        unsigned ah[2][4], al[2][4], bh[3][4], bl[3][4];
        #pragma unroll
        for (int mt = 0; mt < 2; ++mt) {
            uint32_t off = 2u*((wm*32 + mt*16 + a_m)*40 + kt*16 + a_k);
            ldsm_x4(ah[mt], aAsh + off);
            ldsm_x4(al[mt], aAsl + off);
        }
        #pragma unroll
        for (int np = 0; np < 3; ++np) {
            uint32_t off = 2u*((wn*48 + np*16 + b_n)*bstride + bkoff + kt*16 + b_k);
            ldsm_x4(bh[np], aBsh + off);
            ldsm_x4(bl[np], aBsl + off);
        }
        #pragma unroll
        for (int mt = 0; mt < 2; ++mt)
            #pragma unroll
            for (int nt = 0; nt < 6; ++nt) {
                const unsigned* B1 = &bh[nt>>1][(nt&1)*2];
                const unsigned* B2 = &bl[nt>>1][(nt&1)*2];
                mma16816(c[mt][nt], ah[mt], B1);
                mma16816(c[mt][nt], al[mt], B1);
                mma16816(c[mt][nt], ah[mt], B2);
            }
    }
}

// ---------------- hi/lo split conversion ----------------
__global__ void split_kernel(const float* __restrict__ x,
                             __nv_bfloat16* __restrict__ hi,
                             __nv_bfloat16* __restrict__ lo, int n){
    int i = blockIdx.x*256 + threadIdx.x;
    if (i < n){
        float v = x[i];
        __nv_bfloat16 h = __float2bfloat16(v);
        hi[i] = h;
        lo[i] = __float2bfloat16(v - __bfloat162float(h));
    }
}

__global__ void zeroH_kernel(float* __restrict__ H){
    int i = blockIdx.x*256 + threadIdx.x;
    H[i] = 0.f;
    if (blockIdx.x == 0 && threadIdx.x < 16) g_cnt[threadIdx.x] = 0u;
}

// =====================================================================
// Big x-GEMM, cp.async double-buffered, 2 CTAs/SM.
// =====================================================================
#define BIG_ASH 0u
#define BIG_ASL 20480u
#define BIG_BSH 40960u
#define BIG_BSL 56320u
#define BIG_DYN 71680u

__global__ __launch_bounds__(256, 2) void hmma_big(
    const __nv_bfloat16* __restrict__ Ah, const __nv_bfloat16* __restrict__ Al,
    const __nv_bfloat16* __restrict__ Bh, const __nv_bfloat16* __restrict__ Bl,
    float* __restrict__ GI)
{
    extern __shared__ char smraw[];
    const uint32_t sb = smem_u32(smraw);
    const int tid  = threadIdx.x;
    const int lane = tid & 31, warp = tid >> 5;
    const int wm = warp >> 1, wn = warp & 1;
    const int ubu  = blockIdx.x * 32;
    const int row0 = blockIdx.y * 128;

    const int grp = lane >> 3, rr = lane & 7;
    const int a_m = (grp & 1)*8 + rr, a_k = (grp >> 1)*8;
    const int b_n = (grp >> 1)*8 + rr, b_k = (grp & 1)*8;

    float c[2][6][4];
    #pragma unroll
    for (int mt = 0; mt < 2; ++mt)
        #pragma unroll
        for (int nt = 0; nt < 6; ++nt)
            #pragma unroll
            for (int q = 0; q < 4; ++q) c[mt][nt][q] = 0.f;

    stageA_cp(sb + BIG_ASH, sb + BIG_ASL, Ah, Al, row0, 0, tid);
    stageB_cp(sb + BIG_BSH, sb + BIG_BSL, Bh, Bl, ubu, 0, tid);
    CP_COMMIT();

    for (int kc = 0; kc < 8; ++kc) {
        const int buf = kc & 1;
        if (kc < 7) {
            const int nb = buf ^ 1;
            stageA_cp(sb + BIG_ASH + nb*10240u, sb + BIG_ASL + nb*10240u,
                      Ah, Al, row0, (kc+1)*32, tid);
            stageB_cp(sb + BIG_BSH + nb*7680u, sb + BIG_BSL + nb*7680u,
                      Bh, Bl, ubu, (kc+1)*32, tid);
            CP_COMMIT();
            CP_WAIT1();
        } else {
            CP_WAIT0();
        }
        __syncthreads();
        mma_chunk(c, sb + BIG_ASH + buf*10240u, sb + BIG_ASL + buf*10240u,
                     sb + BIG_BSH + buf*7680u,  sb + BIG_BSL + buf*7680u,
                  a_m, a_k, b_n, b_k, wm, wn, 40, 0);
        __syncthreads();
    }

    const size_t colbase = (size_t)blockIdx.x * 96;
    #pragma unroll
    for (int mt = 0; mt < 2; ++mt)
        #pragma unroll
        for (int nt = 0; nt < 6; ++nt) {
            int rw = row0 + wm*32 + mt*16 + (lane >> 2);
            int cl = wn*48 + nt*8 + ((lane & 3) << 1);
            *(float2*)&GI[(size_t)rw*G3 + colbase + cl]     = make_float2(c[mt][nt][0], c[mt][nt][1]);
            *(float2*)&GI[(size_t)(rw+8)*G3 + colbase + cl] = make_float2(c[mt][nt][2], c[mt][nt][3]);
        }
}

// =====================================================================
// Persistent GRU recurrence. GI slice prefetched into Cs (stride-128 layout:
// cols 0-31 r-sum, 32-63 z-sum, 64-95 gi_n, 96-127 hh_n) overlapped with MMA.
// dyn smem (bytes): BSH 0 (50688), BSL 50688, ASH 101376 (2x10240),
//   ASL 121856 (2x10240), CS 142336 (65536) -> total 207872
// =====================================================================
#define GRU_BSH 0u
#define GRU_BSL 50688u
#define GRU_ASH 101376u
#define GRU_ASL 121856u
#define GRU_CS  142336u
#define GRU_DYN 207872u
#define SM_B_STRIDE 264

template<int LAYER>
__global__ __launch_bounds__(256) void gru_persist(
    const __nv_bfloat16* __restrict__ Whh_h, const __nv_bfloat16* __restrict__ Whh_l,
    const float* __restrict__ GI,
    float* __restrict__ Hbase,
    __nv_bfloat16* __restrict__ Hhb, __nv_bfloat16* __restrict__ Hlb,
    __nv_bfloat16* __restrict__ X1h, __nv_bfloat16* __restrict__ X1l,
    float* __restrict__ FL, const int* __restrict__ flen,
    const float* __restrict__ bih, const float* __restrict__ bhh)
{
    extern __shared__ char smraw[];
    const uint32_t sb = smem_u32(smraw);
    unsigned short* Bsh = (unsigned short*)(smraw + GRU_BSH);
    unsigned short* Bsl = (unsigned short*)(smraw + GRU_BSL);
    float* Cs = (float*)(smraw + GRU_CS);
    const uint32_t csb = sb + GRU_CS;

    const int tid  = threadIdx.x;
    const int lane = tid & 31, warp = tid >> 5;
    const int wm = warp >> 1, wn = warp & 1;
    const int rg   = blockIdx.x;
    const int row0 = rg * 128;
    const int ubu  = blockIdx.y * 32;

    const int grp = lane >> 3, rr = lane & 7;
    const int a_m = (grp & 1)*8 + rr, a_k = (grp >> 1)*8;
    const int b_n = (grp >> 1)*8 + rr, b_k = (grp & 1)*8;

    // ---- load Whh tile once ----
    for (int idx = tid; idx < 96*32; idx += 256) {
        int p = idx >> 5, ks = (idx & 31) << 3;
        int w = (p >> 5)*HD + ubu + (p & 31);
        *(uint4*)&Bsh[p*SM_B_STRIDE + ks] = *(const uint4*)&Whh_h[(size_t)w*HD + ks];
        *(uint4*)&Bsl[p*SM_B_STRIDE + ks] = *(const uint4*)&Whh_l[(size_t)w*HD + ks];
    }
    __syncthreads();

    const int jl = tid & 31;
    const int j  = ubu + jl;
    const float b_r  = bih[j]      + bhh[j];
    const float b_z  = bih[HD+j]   + bhh[HD+j];
    const float bi_n = bih[2*HD+j];
    const float bh_n = bhh[2*HD+j];
    const size_t colbase = (size_t)blockIdx.y * 96;

    for (int t = 0; t < LSEQ; ++t) {
        const int pa = t & 1, pb = (t+1) & 1;
        const float* Hprev = Hbase + (size_t)pa*NSEQ*HD;
        float* Hn          = Hbase + (size_t)pb*NSEQ*HD;
        const __nv_bfloat16* Ahp = Hhb + (size_t)pa*NSEQ*HD;
        const __nv_bfloat16* Alp = Hlb + (size_t)pa*NSEQ*HD;
        __nv_bfloat16* Hnh = Hhb + (size_t)pb*NSEQ*HD;
        __nv_bfloat16* Hnl = Hlb + (size_t)pb*NSEQ*HD;

        float c[2][6][4];
        #pragma unroll
        for (int mt = 0; mt < 2; ++mt)
            #pragma unroll
            for (int nt = 0; nt < 6; ++nt)
                #pragma unroll
                for (int q = 0; q < 4; ++q) c[mt][nt][q] = 0.f;

        if (t > 0) {   // h(0)=0 -> h-GEMM result is exactly 0, skip
            stageA_cp(sb + GRU_ASH, sb + GRU_ASL, Ahp, Alp, row0, 0, tid);
            stageGI_piece(csb, GI, row0, t, colbase, 0, tid);
            CP_COMMIT();
            for (int kc = 0; kc < 8; ++kc) {
                const int buf = kc & 1;
                if (kc < 7) {
                    const int nb = buf ^ 1;
                    stageA_cp(sb + GRU_ASH + nb*10240u, sb + GRU_ASL + nb*10240u,
                              Ahp, Alp, row0, (kc+1)*32, tid);
                    stageGI_piece(csb, GI, row0, t, colbase, kc+1, tid);
                    CP_COMMIT();
                    CP_WAIT1();
                } else {
                    CP_WAIT0();
                }
                __syncthreads();
                mma_chunk(c, sb + GRU_ASH + buf*10240u, sb + GRU_ASL + buf*10240u,
                             sb + GRU_BSH, sb + GRU_BSL,
                          a_m, a_k, b_n, b_k, wm, wn, SM_B_STRIDE, kc*32);
                __syncthreads();
            }
        } else {
            // stage GI only
            #pragma unroll
            for (int pc = 0; pc < 8; ++pc)
                stageGI_piece(csb, GI, row0, t, colbase, pc, tid);
            CP_COMMIT();
            CP_WAIT0();
            __syncthreads();
        }

        // ---- merge fragments into Cs: r/z add, n store (hh_n column) ----
        #pragma unroll
        for (int mt = 0; mt < 2; ++mt)
            #pragma unroll
            for (int nt = 0; nt < 6; ++nt) {
                int rl = wm*32 + mt*16 + (lane >> 2);
                int cl = wn*48 + nt*8 + ((lane & 3) << 1);
                const bool is_n = (cl >= 64);
                const int ccl = is_n ? cl + 32 : cl;
                float2* p0 = (float2*)&Cs[rl*128 + ccl];
                float2* p1 = (float2*)&Cs[(rl+8)*128 + ccl];
                if (is_n) {
                    *p0 = make_float2(c[mt][nt][0], c[mt][nt][1]);
                    *p1 = make_float2(c[mt][nt][2], c[mt][nt][3]);
                } else {
                    float2 v0 = *p0, v1 = *p1;
                    *p0 = make_float2(v0.x + c[mt][nt][0], v0.y + c[mt][nt][1]);
                    *p1 = make_float2(v1.x + c[mt][nt][2], v1.y + c[mt][nt][3]);
                }
            }
        __syncthreads();

        // ---- gate epilogue (pure SMEM + Hprev) ----
        #pragma unroll
        for (int i = 0; i < 16; ++i) {
            const int rl  = (tid >> 5) + i*8;
            const int row = row0 + rl;
            const float r = fast_sigmoid(Cs[rl*128 + jl]      + b_r);
            const float z = fast_sigmoid(Cs[rl*128 + 32 + jl] + b_z);
            const float n = fast_tanh(Cs[rl*128 + 64 + jl] + bi_n +
                                      r*(Cs[rl*128 + 96 + jl] + bh_n));
            const float hp = Hprev[(size_t)row*HD + j];
            const float h  = (1.f - z)*n + z*hp;
            Hn[(size_t)row*HD + j] = h;
            __nv_bfloat16 hh = __float2bfloat16(h);
            __nv_bfloat16 hl = __float2bfloat16(h - __bfloat162float(hh));
            Hnh[(size_t)row*HD + j] = hh;
            Hnl[(size_t)row*HD + j] = hl;
            if (LAYER == 0) {
                size_t xi = ((size_t)row*LSEQ + t)*HD + j;
                X1h[xi] = hh; X1l[xi] = hl;
            } else {
                if (t == flen[row] - 1) FL[(size_t)row*HD + j] = h;
            }
        }

        // ---- 8-CTA rowgroup barrier (monotonic counter) ----
        __threadfence();
        __syncthreads();
        if (tid == 0) {
            atomicAdd(&g_cnt[rg], 1u);
            const unsigned target = 8u*(unsigned)(t+1);
            while (ld_acq(&g_cnt[rg]) < target) __nanosleep(32);
        }
        __syncthreads();
    }
}

// ---------------- fp32 tail GEMM (small) ----------------
template<int TRANSW>
__global__ __launch_bounds__(256) void sgemm_tn(
    const float* __restrict__ A, const float* __restrict__ W, float* __restrict__ C,
    int M, int N, int K)
{
    __shared__ float As[32][68];
    __shared__ float Bs[32][68];
    const int tid = threadIdx.x;
    const int tx = tid & 15, ty = tid >> 4;
    const int mb = blockIdx.x * 64, nb = blockIdx.y * 64;

    float2 acc[4][2];
    #pragma unroll
    for (int i = 0; i < 4; ++i) { acc[i][0] = make_float2(0.f,0.f); acc[i][1] = make_float2(0.f,0.f); }

    for (int kc = 0; kc < K; kc += 32) {
        #pragma unroll
        for (int q = 0; q < 2; ++q) {
            int idx = q*256 + tid;
            int row = idx >> 3;
            int k4  = (idx & 7) << 2;
            const float4 v = *reinterpret_cast<const float4*>(&A[(size_t)(mb+row)*K + kc + k4]);
            As[k4+0][row] = v.x; As[k4+1][row] = v.y; As[k4+2][row] = v.z; As[k4+3][row] = v.w;
        }
        if (!TRANSW) {
            #pragma unroll
            for (int q = 0; q < 2; ++q) {
                int idx = q*256 + tid;
                int n  = idx >> 3;
                int k4 = (idx & 7) << 2;
                const float4 v = *reinterpret_cast<const float4*>(&W[(size_t)(nb+n)*K + kc + k4]);
                Bs[k4+0][n] = v.x; Bs[k4+1][n] = v.y; Bs[k4+2][n] = v.z; Bs[k4+3][n] = v.w;
            }
        } else {
            #pragma unroll
            for (int q = 0; q < 2; ++q) {
                int idx = q*256 + tid;
                int k  = idx >> 4;
                int n4 = (idx & 15) << 2;
                const float4 v = *reinterpret_cast<const float4*>(&W[(size_t)(kc+k)*N + nb + n4]);
                *reinterpret_cast<float4*>(&Bs[k][n4]) = v;
            }
        }
        __syncthreads();
        #pragma unroll
        for (int k = 0; k < 32; ++k) {
            const float4 a4 = *reinterpret_cast<const float4*>(&As[k][ty<<2]);
            const float4 b4 = *reinterpret_cast<const float4*>(&Bs[k][tx<<2]);
            const float2 b0 = make_float2(b4.x, b4.y);
            const float2 b1 = make_float2(b4.z, b4.w);
            float av[4] = {a4.x, a4.y, a4.z, a4.w};
            #pragma unroll
            for (int i = 0; i < 4; ++i) {
                float2 aa = make_float2(av[i], av[i]);
                acc[i][0] = ffma2(aa, b0, acc[i][0]);
                acc[i][1] = ffma2(aa, b1, acc[i][1]);
            }
        }
        __syncthreads();
    }
    #pragma unroll
    for (int i = 0; i < 4; ++i) {
        const int row = mb + (ty<<2) + i;
        float4 o;
        o.x = acc[i][0].x; o.y = acc[i][0].y; o.z = acc[i][1].x; o.w = acc[i][1].y;
        *reinterpret_cast<float4*>(&C[(size_t)row*N + nb + (tx<<2)]) = o;
    }
}

__global__ void build_cat(const float* __restrict__ self_x,
                          const float* __restrict__ FL,
                          float* __restrict__ CAT){
    const int m = blockIdx.x, tid = threadIdx.x;
    CAT[(size_t)m*2*HD + tid]      = self_x[(size_t)(m>>5)*HD + tid];
    CAT[(size_t)m*2*HD + HD + tid] = FL[(size_t)m*HD + tid];
}

__global__ __launch_bounds__(256) void tf_kernel(
    const float* __restrict__ common_x, const float* __restrict__ common_time,
    const float* __restrict__ V, const int* __restrict__ clen, float* __restrict__ TF)
{
    const int m = blockIdx.x;
    __shared__ float vs[HD];
    __shared__ float wsum[8];
    const int tid = threadIdx.x;
    vs[tid] = V[(size_t)m*HD + tid];
    __syncthreads();
    const int warp = tid >> 5, lane = tid & 31;
    const int cl = clen[m];
    float acc = 0.f;
    for (int s = warp; s < cl; s += 8) {
        const float* cx = common_x + ((size_t)m*SSEQ + s)*HD;
        float p = 0.f;
        #pragma unroll
        for (int q = 0; q < 8; ++q) p += cx[lane + 32*q] * vs[lane + 32*q];
        #pragma unroll
        for (int off = 16; off; off >>= 1) p += __shfl_xor_sync(0xffffffffu, p, off);
        if (lane == 0)
            acc += softplus_f(p) * expf(-common_time[(size_t)m*SSEQ + s]);
    }
    if (lane == 0) wsum[warp] = acc;
    __syncthreads();
    if (tid == 0) {
        float s = 0.f;
        for (int w = 0; w < 8; ++w) s += wsum[w];
        TF[m] = s;
    }
}

__global__ __launch_bounds__(256) void out_kernel(
    const float* __restrict__ TF, const float* __restrict__ FL,
    const int* __restrict__ fnum, float* __restrict__ out)
{
    const int b = blockIdx.x;
    __shared__ float w[MAXF];
    const int tid = threadIdx.x;
    const int fn = fnum[b];
    if (tid < MAXF) w[tid] = (tid < fn) ? TF[b*MAXF + tid] : 0.f;
    __syncthreads();
    if (tid == 0) {
        float mx = w[0];
        for (int f = 1; f < MAXF; ++f) mx = fmaxf(mx, w[f]);
        float s = 0.f;
        for (int f = 0; f < MAXF; ++f) { float e = expf(w[f] - mx); w[f] = e; s += e; }
        float inv = 1.f / s;
        for (int f = 0; f < MAXF; ++f) w[f] *= inv;
    }
    __syncthreads();
    float acc = 0.f;
    for (int f = 0; f < fn; ++f)
        acc += w[f] * FL[(size_t)(b*MAXF + f)*HD + tid];
    out[(size_t)b*HD + tid] = acc;
}

// ---------------- host launcher ----------------
extern "C" void kernel_launch(void* const* d_in, const int* in_sizes, int n_in,
                              void* d_out, int out_size)
{
    const float* self_x      = (const float*)d_in[0];
    const float* common_x    = (const float*)d_in[1];
    const float* common_time = (const float*)d_in[2];
    const float* friend_x    = (const float*)d_in[3];
    const float* Wih0 = (const float*)d_in[4];
    const float* Whh0 = (const float*)d_in[5];
    const float* bih0 = (const float*)d_in[6];
    const float* bhh0 = (const float*)d_in[7];
    const float* Wih1 = (const float*)d_in[8];
    const float* Whh1 = (const float*)d_in[9];
    const float* bih1 = (const float*)d_in[10];
    const float* bhh1 = (const float*)d_in[11];
    const float* Wf   = (const float*)d_in[12];
    const float* Wb   = (const float*)d_in[13];
    const int*   flen = (const int*)d_in[14];
    const int*   fnum = (const int*)d_in[15];
    const int*   clen = (const int*)d_in[16];
    float* out = (float*)d_out;

    float *H, *GI, *FL, *CAT, *SF, *V, *TF;
    __nv_bfloat16 *Hh, *Hl, *FXh, *FXl, *X1h, *X1l, *Wh, *Wl;
    cudaGetSymbolAddress((void**)&H,   g_H);
    cudaGetSymbolAddress((void**)&Hh,  g_Hh);
    cudaGetSymbolAddress((void**)&Hl,  g_Hl);
    cudaGetSymbolAddress((void**)&GI,  g_GI);
    cudaGetSymbolAddress((void**)&FXh, g_FXh);
    cudaGetSymbolAddress((void**)&FXl, g_FXl);
    cudaGetSymbolAddress((void**)&X1h, g_X1h);
    cudaGetSymbolAddress((void**)&X1l, g_X1l);
    cudaGetSymbolAddress((void**)&Wh,  g_Wh);
    cudaGetSymbolAddress((void**)&Wl,  g_Wl);
    cudaGetSymbolAddress((void**)&FL,  g_FL);
    cudaGetSymbolAddress((void**)&CAT, g_CAT);
    cudaGetSymbolAddress((void**)&SF,  g_SF);
    cudaGetSymbolAddress((void**)&V,   g_V);
    cudaGetSymbolAddress((void**)&TF,  g_TF);

    const float* Wsrc[4] = {Wih0, Whh0, Wih1, Whh1};

    static bool attr_done = false;
    if (!attr_done) {
        cudaFuncSetAttribute(hmma_big,       cudaFuncAttributeMaxDynamicSharedMemorySize, BIG_DYN);
        cudaFuncSetAttribute(gru_persist<0>, cudaFuncAttributeMaxDynamicSharedMemorySize, GRU_DYN);
        cudaFuncSetAttribute(gru_persist<1>, cudaFuncAttributeMaxDynamicSharedMemorySize, GRU_DYN);
        attr_done = true;
    }

    // --- conversions ---
    split_kernel<<<((size_t)MTOT*HD + 255)/256, 256>>>(friend_x, FXh, FXl, MTOT*HD);
    for (int w = 0; w < 4; ++w)
        split_kernel<<<(G3*HD + 255)/256, 256>>>(Wsrc[w], Wh + (size_t)w*G3*HD,
                                                 Wl + (size_t)w*G3*HD, G3*HD);

    const dim3 big_grid(8, MTOT/128);   // unit-fast -> A reuse in L2
    const dim3 pgrid(16, 8);

    // ---- layer 0 ----
    hmma_big<<<big_grid, 256, BIG_DYN>>>(FXh, FXl, Wh + 0*(size_t)G3*HD, Wl + 0*(size_t)G3*HD, GI);
    zeroH_kernel<<<(NSEQ*HD)/256, 256>>>(H);
    gru_persist<0><<<pgrid, 256, GRU_DYN>>>(
        Wh + 1*(size_t)G3*HD, Wl + 1*(size_t)G3*HD, GI,
        H, Hh, Hl, X1h, X1l, nullptr, nullptr, bih0, bhh0);

    // ---- layer 1 ----
    hmma_big<<<big_grid, 256, BIG_DYN>>>(X1h, X1l, Wh + 2*(size_t)G3*HD, Wl + 2*(size_t)G3*HD, GI);
    zeroH_kernel<<<(NSEQ*HD)/256, 256>>>(H);
    gru_persist<1><<<pgrid, 256, GRU_DYN>>>(
        Wh + 3*(size_t)G3*HD, Wl + 3*(size_t)G3*HD, GI,
        H, Hh, Hl, nullptr, nullptr, FL, flen, bih1, bhh1);

    // ---- tail ----
    build_cat<<<NSEQ, 256>>>(self_x, FL, CAT);
    sgemm_tn<0><<<dim3(NSEQ/64, HD/64), 256>>>(CAT, Wf, SF, NSEQ, HD, 2*HD);
    sgemm_tn<1><<<dim3(NSEQ/64, HD/64), 256>>>(SF,  Wb, V,  NSEQ, HD, HD);
    tf_kernel<<<NSEQ, 256>>>(common_x, common_time, V, clen, TF);
    out_kernel<<<NBATCH, 256>>>(TF, FL, fnum, out);
}

// round 8
// speedup vs baseline: 2.4876x; 1.1524x over previous
#include <cuda_runtime.h>
#include <cuda_bf16.h>
#include <cstdint>
#include <math.h>

#define HD    256
#define LSEQ  50
#define SSEQ  50
#define NBATCH 64
#define MAXF  32
#define NSEQ  (NBATCH*MAXF)            // 2048
#define MTOT  (NSEQ*LSEQ)              // 102400
#define G3    (3*HD)                   // 768

// ---------------- device scratch ----------------
__device__ __nv_bfloat16  g_Hh[2][NSEQ*HD];
__device__ __nv_bfloat16  g_Hl[2][NSEQ*HD];
__device__ float          g_GI[(size_t)MTOT*G3];
__device__ __nv_bfloat16  g_FXh[(size_t)MTOT*HD];
__device__ __nv_bfloat16  g_FXl[(size_t)MTOT*HD];
__device__ __nv_bfloat16  g_X1h[(size_t)MTOT*HD];
__device__ __nv_bfloat16  g_X1l[(size_t)MTOT*HD];
__device__ __nv_bfloat16  g_Wh[4][G3*HD];
__device__ __nv_bfloat16  g_Wl[4][G3*HD];
__device__ float g_FL[NSEQ*HD];
__device__ float g_CAT[NSEQ*2*HD];
__device__ float g_SF[NSEQ*HD];
__device__ float g_V[NSEQ*HD];
__device__ float g_TF[NSEQ];
__device__ unsigned g_cnt[32];         // 16 per layer
__device__ int g_perm[NSEQ];           // rows sorted by flen descending
__device__ int g_gmax[16];             // per-rowgroup max flen

// ---------------- helpers ----------------
__device__ __forceinline__ float fast_sigmoid(float x){
    return __fdividef(1.f, 1.f + __expf(-x));
}
__device__ __forceinline__ float fast_tanh(float x){
    return 1.f - __fdividef(2.f, __expf(2.f*x) + 1.f);
}
__device__ __forceinline__ float softplus_f(float x){
    return (x > 20.f) ? x : log1pf(expf(x));
}
__device__ __forceinline__ float2 ffma2(float2 a, float2 b, float2 c){
    unsigned long long ua = reinterpret_cast<unsigned long long&>(a);
    unsigned long long ub = reinterpret_cast<unsigned long long&>(b);
    unsigned long long uc = reinterpret_cast<unsigned long long&>(c);
    unsigned long long ud;
    asm("fma.rn.f32x2 %0, %1, %2, %3;" : "=l"(ud) : "l"(ua), "l"(ub), "l"(uc));
    return reinterpret_cast<float2&>(ud);
}
__device__ __forceinline__ uint32_t smem_u32(const void* p){
    return (uint32_t)__cvta_generic_to_shared(p);
}
__device__ __forceinline__ void ldsm_x4(unsigned* r, uint32_t addr){
    asm volatile("ldmatrix.sync.aligned.m8n8.x4.shared.b16 {%0,%1,%2,%3}, [%4];\n"
        : "=r"(r[0]), "=r"(r[1]), "=r"(r[2]), "=r"(r[3]) : "r"(addr));
}
__device__ __forceinline__ void mma16816(float* c, const unsigned* a, const unsigned* b){
    asm volatile("mma.sync.aligned.m16n8k16.row.col.f32.bf16.bf16.f32 "
        "{%0,%1,%2,%3}, {%4,%5,%6,%7}, {%8,%9}, {%0,%1,%2,%3};\n"
        : "+f"(c[0]), "+f"(c[1]), "+f"(c[2]), "+f"(c[3])
        : "r"(a[0]), "r"(a[1]), "r"(a[2]), "r"(a[3]), "r"(b[0]), "r"(b[1]));
}
__device__ __forceinline__ unsigned ld_acq(const unsigned* p){
    unsigned v;
    asm volatile("ld.acquire.gpu.u32 %0, [%1];" : "=r"(v) : "l"(p) : "memory");
    return v;
}
__device__ __forceinline__ void red_release(unsigned* p){
    asm volatile("red.release.gpu.global.add.u32 [%0], %1;" :: "l"(p), "r"(1u) : "memory");
}
__device__ __forceinline__ void cp16(uint32_t dst, const void* src){
    asm volatile("cp.async.cg.shared.global [%0], [%1], 16;" :: "r"(dst), "l"(src) : "memory");
}
#define CP_COMMIT() asm volatile("cp.async.commit_group;" ::: "memory")
#define CP_WAIT1()  asm volatile("cp.async.wait_group 1;" ::: "memory")
#define CP_WAIT0()  asm volatile("cp.async.wait_group 0;" ::: "memory")

// ---------------- sort rows by flen (descending, deterministic) ----------------
__global__ void rank_kernel(const int* __restrict__ flen){
    __shared__ int fl_s[NSEQ];
    for (int i = threadIdx.x; i < NSEQ; i += 256) fl_s[i] = flen[i];
    __syncthreads();
    const int i = blockIdx.x*256 + threadIdx.x;
    const int f = fl_s[i];
    int r = 0;
    for (int jj = 0; jj < NSEQ; ++jj) {
        int fj = fl_s[jj];
        r += (fj > f) || (fj == f && jj < i);
    }
    g_perm[r] = i;
    if ((r & 127) == 0) g_gmax[r >> 7] = f;
    if (blockIdx.x == 0 && threadIdx.x < 32) g_cnt[threadIdx.x] = 0u;
}

// ---------------- staging (cp.async) ----------------
// A chunk gather by perm: layout [(seq*LSEQ + t)*HD] (big GEMM)
__device__ __forceinline__ void stageA_seq(uint32_t sA_h, uint32_t sA_l,
        const __nv_bfloat16* __restrict__ Ah, const __nv_bfloat16* __restrict__ Al,
        const int* __restrict__ perm_s, int t, int kk, int tid){
    #pragma unroll
    for (int q = 0; q < 2; ++q) {
        int idx = q*256 + tid;
        int r = idx >> 2, ks = (idx & 3) << 3;
        size_t s = ((size_t)perm_s[r]*LSEQ + t)*HD + kk + ks;
        uint32_t d = (uint32_t)(r*40 + ks)*2u;
        cp16(sA_h + d, Ah + s);
        cp16(sA_l + d, Al + s);
    }
}
// A chunk gather by perm: layout [row*HD] (recurrence H)
__device__ __forceinline__ void stageA_row(uint32_t sA_h, uint32_t sA_l,
        const __nv_bfloat16* __restrict__ Ah, const __nv_bfloat16* __restrict__ Al,
        const int* __restrict__ perm_s, int kk, int tid){
    #pragma unroll
    for (int q = 0; q < 2; ++q) {
        int idx = q*256 + tid;
        int r = idx >> 2, ks = (idx & 3) << 3;
        size_t s = (size_t)perm_s[r]*HD + kk + ks;
        uint32_t d = (uint32_t)(r*40 + ks)*2u;
        cp16(sA_h + d, Ah + s);
        cp16(sA_l + d, Al + s);
    }
}
__device__ __forceinline__ void stageB_cp(uint32_t sB_h, uint32_t sB_l,
        const __nv_bfloat16* __restrict__ Bh, const __nv_bfloat16* __restrict__ Bl,
        int ubu, int kk, int tid){
    #pragma unroll
    for (int q = 0; q < 2; ++q) {
        int idx = q*256 + tid;
        if (idx < 384) {
            int p = idx >> 2, ks = (idx & 3) << 3;
            int w = (p >> 5)*HD + ubu + (p & 31);
            size_t s = (size_t)w*HD + kk + ks;
            uint32_t d = (uint32_t)(p*40 + ks)*2u;
            cp16(sB_h + d, Bh + s);
            cp16(sB_l + d, Bl + s);
        }
    }
}
// GI piece (gather by perm): 1/8 of 128x96 fp32 into Cs (stride 128 floats)
__device__ __forceinline__ void stageGI_piece(uint32_t cs, const float* __restrict__ GI,
        const int* __restrict__ perm_s, int t, size_t colbase, int piece, int tid){
    #pragma unroll
    for (int q = 0; q < 2; ++q) {
        int i = q*256 + tid;
        if (i < 384) {
            int i2 = piece*384 + i;          // 0..3071
            int rl = i2 / 24, c16 = i2 % 24;
            const float* src = GI + ((size_t)perm_s[rl]*LSEQ + t)*G3 + colbase + c16*4;
            cp16(cs + (uint32_t)(rl*128 + c16*4)*4u, src);
        }
    }
}

// ---------------- MMA on one staged 32-k chunk (3-term hi/lo) ----------------
__device__ __forceinline__ void mma_chunk(
    float (&c)[2][6][4],
    uint32_t aAsh, uint32_t aAsl, uint32_t aBsh, uint32_t aBsl,
    int a_m, int a_k, int b_n, int b_k, int wm, int wn, int bstride, int bkoff)
{
    #pragma unroll
    for (int kt = 0; kt < 2; ++kt) {
        unsigned ah[2][4], al[2][4], bh[3][4], bl[3][4];
        #pragma unroll
        for (int mt = 0; mt < 2; ++mt) {
            uint32_t off = 2u*((wm*32 + mt*16 + a_m)*40 + kt*16 + a_k);
            ldsm_x4(ah[mt], aAsh + off);
            ldsm_x4(al[mt], aAsl + off);
        }
        #pragma unroll
        for (int np = 0; np < 3; ++np) {
            uint32_t off = 2u*((wn*48 + np*16 + b_n)*bstride + bkoff + kt*16 + b_k);
            ldsm_x4(bh[np], aBsh + off);
            ldsm_x4(bl[np], aBsl + off);
        }
        #pragma unroll
        for (int mt = 0; mt < 2; ++mt)
            #pragma unroll
            for (int nt = 0; nt < 6; ++nt) {
                const unsigned* B1 = &bh[nt>>1][(nt&1)*2];
                const unsigned* B2 = &bl[nt>>1][(nt&1)*2];
                mma16816(c[mt][nt], ah[mt], B1);
                mma16816(c[mt][nt], al[mt], B1);
                mma16816(c[mt][nt], ah[mt], B2);
            }
    }
}

// ---------------- hi/lo split conversions ----------------
__global__ void split_kernel(const float* __restrict__ x,
                             __nv_bfloat16* __restrict__ hi,
                             __nv_bfloat16* __restrict__ lo, int n){
    int i = blockIdx.x*256 + threadIdx.x;
    if (i < n){
        float v = x[i];
        __nv_bfloat16 h = __float2bfloat16(v);
        hi[i] = h;
        lo[i] = __float2bfloat16(v - __bfloat162float(h));
    }
}
// friend_x split: skip dead (t >= flen[row]); dead entries stay 0 (zero-init, never written)
__global__ void split_fx(const float* __restrict__ x,
                         __nv_bfloat16* __restrict__ hi,
                         __nv_bfloat16* __restrict__ lo,
                         const int* __restrict__ flen){
    int i = blockIdx.x*256 + threadIdx.x;
    int t   = (i >> 8) % LSEQ;
    int row = i / (LSEQ*HD);
    if (t >= flen[row]) return;
    float v = x[i];
    __nv_bfloat16 h = __float2bfloat16(v);
    hi[i] = h;
    lo[i] = __float2bfloat16(v - __bfloat162float(h));
}

// =====================================================================
// Big x-GEMM, cp.async double-buffered, 2 CTAs/SM.
// grid (8 units, 16 seqgroups, 50 t); early exit when t >= gmax[sg].
// =====================================================================
#define BIG_ASH 0u
#define BIG_ASL 20480u
#define BIG_BSH 40960u
#define BIG_BSL 56320u
#define BIG_DYN 71680u

__global__ __launch_bounds__(256, 2) void hmma_big(
    const __nv_bfloat16* __restrict__ Ah, const __nv_bfloat16* __restrict__ Al,
    const __nv_bfloat16* __restrict__ Bh, const __nv_bfloat16* __restrict__ Bl,
    float* __restrict__ GI)
{
    const int sg = blockIdx.y;
    const int t  = blockIdx.z;
    if (t >= g_gmax[sg]) return;

    extern __shared__ char smraw[];
    __shared__ int perm_s[128];
    const uint32_t sb = smem_u32(smraw);
    const int tid  = threadIdx.x;
    const int lane = tid & 31, warp = tid >> 5;
    const int wm = warp >> 1, wn = warp & 1;
    const int ubu = blockIdx.x * 32;

    if (tid < 128) perm_s[tid] = g_perm[sg*128 + tid];
    __syncthreads();

    const int grp = lane >> 3, rr = lane & 7;
    const int a_m = (grp & 1)*8 + rr, a_k = (grp >> 1)*8;
    const int b_n = (grp >> 1)*8 + rr, b_k = (grp & 1)*8;

    float c[2][6][4];
    #pragma unroll
    for (int mt = 0; mt < 2; ++mt)
        #pragma unroll
        for (int nt = 0; nt < 6; ++nt)
            #pragma unroll
            for (int q = 0; q < 4; ++q) c[mt][nt][q] = 0.f;

    stageA_seq(sb + BIG_ASH, sb + BIG_ASL, Ah, Al, perm_s, t, 0, tid);
    stageB_cp(sb + BIG_BSH, sb + BIG_BSL, Bh, Bl, ubu, 0, tid);
    CP_COMMIT();

    for (int kc = 0; kc < 8; ++kc) {
        const int buf = kc & 1;
        if (kc < 7) {
            const int nb = buf ^ 1;
            stageA_seq(sb + BIG_ASH + nb*10240u, sb + BIG_ASL + nb*10240u,
                       Ah, Al, perm_s, t, (kc+1)*32, tid);
            stageB_cp(sb + BIG_BSH + nb*7680u, sb + BIG_BSL + nb*7680u,
                      Bh, Bl, ubu, (kc+1)*32, tid);
            CP_COMMIT();
            CP_WAIT1();
        } else {
            CP_WAIT0();
        }
        __syncthreads();
        mma_chunk(c, sb + BIG_ASH + buf*10240u, sb + BIG_ASL + buf*10240u,
                     sb + BIG_BSH + buf*7680u,  sb + BIG_BSL + buf*7680u,
                  a_m, a_k, b_n, b_k, wm, wn, 40, 0);
        __syncthreads();
    }

    const size_t colbase = (size_t)blockIdx.x * 96;
    #pragma unroll
    for (int mt = 0; mt < 2; ++mt)
        #pragma unroll
        for (int nt = 0; nt < 6; ++nt) {
            int rl = wm*32 + mt*16 + (lane >> 2);
            int cl = wn*48 + nt*8 + ((lane & 3) << 1);
            size_t r0 = ((size_t)perm_s[rl]*LSEQ + t)*G3;
            size_t r1 = ((size_t)perm_s[rl+8]*LSEQ + t)*G3;
            *(float2*)&GI[r0 + colbase + cl] = make_float2(c[mt][nt][0], c[mt][nt][1]);
            *(float2*)&GI[r1 + colbase + cl] = make_float2(c[mt][nt][2], c[mt][nt][3]);
        }
}

// =====================================================================
// Persistent GRU recurrence (per-rowgroup step bound gmax[rg]).
// dyn smem: BSH 0 (50688), BSL 50688, ASH 101376 (2x10240),
//   ASL 121856 (2x10240), CS 142336 (65536) -> 207872
// =====================================================================
#define GRU_BSH 0u
#define GRU_BSL 50688u
#define GRU_ASH 101376u
#define GRU_ASL 121856u
#define GRU_CS  142336u
#define GRU_DYN 207872u
#define SM_B_STRIDE 264

template<int LAYER>
__global__ __launch_bounds__(256) void gru_persist(
    const __nv_bfloat16* __restrict__ Whh_h, const __nv_bfloat16* __restrict__ Whh_l,
    const float* __restrict__ GI,
    __nv_bfloat16* __restrict__ Hhb, __nv_bfloat16* __restrict__ Hlb,
    __nv_bfloat16* __restrict__ X1h, __nv_bfloat16* __restrict__ X1l,
    float* __restrict__ FL, const int* __restrict__ flen,
    const float* __restrict__ bih, const float* __restrict__ bhh)
{
    extern __shared__ char smraw[];
    __shared__ int perm_s[128];
    __shared__ int flen_s[128];
    const uint32_t sb = smem_u32(smraw);
    float* Cs = (float*)(smraw + GRU_CS);
    const uint32_t csb = sb + GRU_CS;
    unsigned short* Bsh = (unsigned short*)(smraw + GRU_BSH);
    unsigned short* Bsl = (unsigned short*)(smraw + GRU_BSL);

    const int tid  = threadIdx.x;
    const int lane = tid & 31, warp = tid >> 5;
    const int wm = warp >> 1, wn = warp & 1;
    const int rg   = blockIdx.x;
    const int ubu  = blockIdx.y * 32;
    const int tmax = g_gmax[rg];

    if (tid < 128) {
        int p = g_perm[rg*128 + tid];
        perm_s[tid] = p;
        flen_s[tid] = flen[p];
    }

    const int grp = lane >> 3, rr = lane & 7;
    const int a_m = (grp & 1)*8 + rr, a_k = (grp >> 1)*8;
    const int b_n = (grp >> 1)*8 + rr, b_k = (grp & 1)*8;

    // ---- load Whh tile once ----
    for (int idx = tid; idx < 96*32; idx += 256) {
        int p = idx >> 5, ks = (idx & 31) << 3;
        int w = (p >> 5)*HD + ubu + (p & 31);
        *(uint4*)&Bsh[p*SM_B_STRIDE + ks] = *(const uint4*)&Whh_h[(size_t)w*HD + ks];
        *(uint4*)&Bsl[p*SM_B_STRIDE + ks] = *(const uint4*)&Whh_l[(size_t)w*HD + ks];
    }
    __syncthreads();

    const int jl = tid & 31;
    const int j  = ubu + jl;
    const float b_r  = bih[j]      + bhh[j];
    const float b_z  = bih[HD+j]   + bhh[HD+j];
    const float bi_n = bih[2*HD+j];
    const float bh_n = bhh[2*HD+j];
    const size_t colbase = (size_t)blockIdx.y * 96;
    unsigned* cnt = &g_cnt[rg + (LAYER ? 16 : 0)];

    for (int t = 0; t < tmax; ++t) {
        const int pa = t & 1, pb = (t+1) & 1;
        const __nv_bfloat16* Ahp = Hhb + (size_t)pa*NSEQ*HD;
        const __nv_bfloat16* Alp = Hlb + (size_t)pa*NSEQ*HD;
        __nv_bfloat16* Hnh = Hhb + (size_t)pb*NSEQ*HD;
        __nv_bfloat16* Hnl = Hlb + (size_t)pb*NSEQ*HD;

        float c[2][6][4];
        #pragma unroll
        for (int mt = 0; mt < 2; ++mt)
            #pragma unroll
            for (int nt = 0; nt < 6; ++nt)
                #pragma unroll
                for (int q = 0; q < 4; ++q) c[mt][nt][q] = 0.f;

        if (t > 0) {
            stageA_row(sb + GRU_ASH, sb + GRU_ASL, Ahp, Alp, perm_s, 0, tid);
            stageGI_piece(csb, GI, perm_s, t, colbase, 0, tid);
            CP_COMMIT();
            for (int kc = 0; kc < 8; ++kc) {
                const int buf = kc & 1;
                if (kc < 7) {
                    const int nb = buf ^ 1;
                    stageA_row(sb + GRU_ASH + nb*10240u, sb + GRU_ASL + nb*10240u,
                               Ahp, Alp, perm_s, (kc+1)*32, tid);
                    stageGI_piece(csb, GI, perm_s, t, colbase, kc+1, tid);
                    CP_COMMIT();
                    CP_WAIT1();
                } else {
                    CP_WAIT0();
                }
                __syncthreads();
                mma_chunk(c, sb + GRU_ASH + buf*10240u, sb + GRU_ASL + buf*10240u,
                             sb + GRU_BSH, sb + GRU_BSL,
                          a_m, a_k, b_n, b_k, wm, wn, SM_B_STRIDE, kc*32);
                __syncthreads();
            }
        } else {
            #pragma unroll
            for (int pc = 0; pc < 8; ++pc)
                stageGI_piece(csb, GI, perm_s, t, colbase, pc, tid);
            CP_COMMIT();
            CP_WAIT0();
            __syncthreads();
        }

        // ---- merge fragments: r/z add into Cs, n store to hh_n column ----
        #pragma unroll
        for (int mt = 0; mt < 2; ++mt)
            #pragma unroll
            for (int nt = 0; nt < 6; ++nt) {
                int rl = wm*32 + mt*16 + (lane >> 2);
                int cl = wn*48 + nt*8 + ((lane & 3) << 1);
                const bool is_n = (cl >= 64);
                const int ccl = is_n ? cl + 32 : cl;
                float2* p0 = (float2*)&Cs[rl*128 + ccl];
                float2* p1 = (float2*)&Cs[(rl+8)*128 + ccl];
                if (is_n) {
                    *p0 = make_float2(c[mt][nt][0], c[mt][nt][1]);
                    *p1 = make_float2(c[mt][nt][2], c[mt][nt][3]);
                } else {
                    float2 v0 = *p0, v1 = *p1;
                    *p0 = make_float2(v0.x + c[mt][nt][0], v0.y + c[mt][nt][1]);
                    *p1 = make_float2(v1.x + c[mt][nt][2], v1.y + c[mt][nt][3]);
                }
            }
        __syncthreads();

        // ---- gate epilogue ----
        #pragma unroll
        for (int i = 0; i < 16; ++i) {
            const int rl  = (tid >> 5) + i*8;
            const int row = perm_s[rl];
            const float r = fast_sigmoid(Cs[rl*128 + jl]      + b_r);
            const float z = fast_sigmoid(Cs[rl*128 + 32 + jl] + b_z);
            const float n = fast_tanh(Cs[rl*128 + 64 + jl] + bi_n +
                                      r*(Cs[rl*128 + 96 + jl] + bh_n));
            float hp = 0.f;
            if (t > 0)
                hp = __bfloat162float(Ahp[(size_t)row*HD + j]) +
                     __bfloat162float(Alp[(size_t)row*HD + j]);
            const float h  = (1.f - z)*n + z*hp;
            __nv_bfloat16 hh = __float2bfloat16(h);
            __nv_bfloat16 hl = __float2bfloat16(h - __bfloat162float(hh));
            Hnh[(size_t)row*HD + j] = hh;
            Hnl[(size_t)row*HD + j] = hl;
            if (LAYER == 0) {
                size_t xi = ((size_t)row*LSEQ + t)*HD + j;
                X1h[xi] = hh; X1l[xi] = hl;
            } else {
                if (t == flen_s[rl] - 1) FL[(size_t)row*HD + j] = h;
            }
        }

        // ---- 8-CTA rowgroup barrier (skip after final step) ----
        if (t + 1 < tmax) {
            __syncthreads();
            if (tid == 0) {
                red_release(cnt);
                const unsigned target = 8u*(unsigned)(t+1);
                while (ld_acq(cnt) < target) __nanosleep(32);
            }
            __syncthreads();
        }
    }
}

// ---------------- fp32 tail GEMM (small) ----------------
template<int TRANSW>
__global__ __launch_bounds__(256) void sgemm_tn(
    const float* __restrict__ A, const float* __restrict__ W, float* __restrict__ C,
    int M, int N, int K)
{
    __shared__ float As[32][68];
    __shared__ float Bs[32][68];
    const int tid = threadIdx.x;
    const int tx = tid & 15, ty = tid >> 4;
    const int mb = blockIdx.x * 64, nb = blockIdx.y * 64;

    float2 acc[4][2];
    #pragma unroll
    for (int i = 0; i < 4; ++i) { acc[i][0] = make_float2(0.f,0.f); acc[i][1] = make_float2(0.f,0.f); }

    for (int kc = 0; kc < K; kc += 32) {
        #pragma unroll
        for (int q = 0; q < 2; ++q) {
            int idx = q*256 + tid;
            int row = idx >> 3;
            int k4  = (idx & 7) << 2;
            const float4 v = *reinterpret_cast<const float4*>(&A[(size_t)(mb+row)*K + kc + k4]);
            As[k4+0][row] = v.x; As[k4+1][row] = v.y; As[k4+2][row] = v.z; As[k4+3][row] = v.w;
        }
        if (!TRANSW) {
            #pragma unroll
            for (int q = 0; q < 2; ++q) {
                int idx = q*256 + tid;
                int n  = idx >> 3;
                int k4 = (idx & 7) << 2;
                const float4 v = *reinterpret_cast<const float4*>(&W[(size_t)(nb+n)*K + kc + k4]);
                Bs[k4+0][n] = v.x; Bs[k4+1][n] = v.y; Bs[k4+2][n] = v.z; Bs[k4+3][n] = v.w;
            }
        } else {
            #pragma unroll
            for (int q = 0; q < 2; ++q) {
                int idx = q*256 + tid;
                int k  = idx >> 4;
                int n4 = (idx & 15) << 2;
                const float4 v = *reinterpret_cast<const float4*>(&W[(size_t)(kc+k)*N + nb + n4]);
                *reinterpret_cast<float4*>(&Bs[k][n4]) = v;
            }
        }
        __syncthreads();
        #pragma unroll
        for (int k = 0; k < 32; ++k) {
            const float4 a4 = *reinterpret_cast<const float4*>(&As[k][ty<<2]);
            const float4 b4 = *reinterpret_cast<const float4*>(&Bs[k][tx<<2]);
            const float2 b0 = make_float2(b4.x, b4.y);
            const float2 b1 = make_float2(b4.z, b4.w);
            float av[4] = {a4.x, a4.y, a4.z, a4.w};
            #pragma unroll
            for (int i = 0; i < 4; ++i) {
                float2 aa = make_float2(av[i], av[i]);
                acc[i][0] = ffma2(aa, b0, acc[i][0]);
                acc[i][1] = ffma2(aa, b1, acc[i][1]);
            }
        }
        __syncthreads();
    }
    #pragma unroll
    for (int i = 0; i < 4; ++i) {
        const int row = mb + (ty<<2) + i;
        float4 o;
        o.x = acc[i][0].x; o.y = acc[i][0].y; o.z = acc[i][1].x; o.w = acc[i][1].y;
        *reinterpret_cast<float4*>(&C[(size_t)row*N + nb + (tx<<2)]) = o;
    }
}

__global__ void build_cat(const float* __restrict__ self_x,
                          const float* __restrict__ FL,
                          float* __restrict__ CAT){
    const int m = blockIdx.x, tid = threadIdx.x;
    CAT[(size_t)m*2*HD + tid]      = self_x[(size_t)(m>>5)*HD + tid];
    CAT[(size_t)m*2*HD + HD + tid] = FL[(size_t)m*HD + tid];
}

__global__ __launch_bounds__(256) void tf_kernel(
    const float* __restrict__ common_x, const float* __restrict__ common_time,
    const float* __restrict__ V, const int* __restrict__ clen, float* __restrict__ TF)
{
    const int m = blockIdx.x;
    __shared__ float vs[HD];
    __shared__ float wsum[8];
    const int tid = threadIdx.x;
    vs[tid] = V[(size_t)m*HD + tid];
    __syncthreads();
    const int warp = tid >> 5, lane = tid & 31;
    const int cl = clen[m];
    float acc = 0.f;
    for (int s = warp; s < cl; s += 8) {
        const float* cx = common_x + ((size_t)m*SSEQ + s)*HD;
        float p = 0.f;
        #pragma unroll
        for (int q = 0; q < 8; ++q) p += cx[lane + 32*q] * vs[lane + 32*q];
        #pragma unroll
        for (int off = 16; off; off >>= 1) p += __shfl_xor_sync(0xffffffffu, p, off);
        if (lane == 0)
            acc += softplus_f(p) * expf(-common_time[(size_t)m*SSEQ + s]);
    }
    if (lane == 0) wsum[warp] = acc;
    __syncthreads();
    if (tid == 0) {
        float s = 0.f;
        for (int w = 0; w < 8; ++w) s += wsum[w];
        TF[m] = s;
    }
}

__global__ __launch_bounds__(256) void out_kernel(
    const float* __restrict__ TF, const float* __restrict__ FL,
    const int* __restrict__ fnum, float* __restrict__ out)
{
    const int b = blockIdx.x;
    __shared__ float w[MAXF];
    const int tid = threadIdx.x;
    const int fn = fnum[b];
    if (tid < MAXF) w[tid] = (tid < fn) ? TF[b*MAXF + tid] : 0.f;
    __syncthreads();
    if (tid == 0) {
        float mx = w[0];
        for (int f = 1; f < MAXF; ++f) mx = fmaxf(mx, w[f]);
        float s = 0.f;
        for (int f = 0; f < MAXF; ++f) { float e = expf(w[f] - mx); w[f] = e; s += e; }
        float inv = 1.f / s;
        for (int f = 0; f < MAXF; ++f) w[f] *= inv;
    }
    __syncthreads();
    float acc = 0.f;
    for (int f = 0; f < fn; ++f)
        acc += w[f] * FL[(size_t)(b*MAXF + f)*HD + tid];
    out[(size_t)b*HD + tid] = acc;
}

// ---------------- host launcher ----------------
extern "C" void kernel_launch(void* const* d_in, const int* in_sizes, int n_in,
                              void* d_out, int out_size)
{
    const float* self_x      = (const float*)d_in[0];
    const float* common_x    = (const float*)d_in[1];
    const float* common_time = (const float*)d_in[2];
    const float* friend_x    = (const float*)d_in[3];
    const float* Wih0 = (const float*)d_in[4];
    const float* Whh0 = (const float*)d_in[5];
    const float* bih0 = (const float*)d_in[6];
    const float* bhh0 = (const float*)d_in[7];
    const float* Wih1 = (const float*)d_in[8];
    const float* Whh1 = (const float*)d_in[9];
    const float* bih1 = (const float*)d_in[10];
    const float* bhh1 = (const float*)d_in[11];
    const float* Wf   = (const float*)d_in[12];
    const float* Wb   = (const float*)d_in[13];
    const int*   flen = (const int*)d_in[14];
    const int*   fnum = (const int*)d_in[15];
    const int*   clen = (const int*)d_in[16];
    float* out = (float*)d_out;

    float *GI, *FL, *CAT, *SF, *V, *TF;
    __nv_bfloat16 *Hh, *Hl, *FXh, *FXl, *X1h, *X1l, *Wh, *Wl;
    cudaGetSymbolAddress((void**)&Hh,  g_Hh);
    cudaGetSymbolAddress((void**)&Hl,  g_Hl);
    cudaGetSymbolAddress((void**)&GI,  g_GI);
    cudaGetSymbolAddress((void**)&FXh, g_FXh);
    cudaGetSymbolAddress((void**)&FXl, g_FXl);
    cudaGetSymbolAddress((void**)&X1h, g_X1h);
    cudaGetSymbolAddress((void**)&X1l, g_X1l);
    cudaGetSymbolAddress((void**)&Wh,  g_Wh);
    cudaGetSymbolAddress((void**)&Wl,  g_Wl);
    cudaGetSymbolAddress((void**)&FL,  g_FL);
    cudaGetSymbolAddress((void**)&CAT, g_CAT);
    cudaGetSymbolAddress((void**)&SF,  g_SF);
    cudaGetSymbolAddress((void**)&V,   g_V);
    cudaGetSymbolAddress((void**)&TF,  g_TF);

    const float* Wsrc[4] = {Wih0, Whh0, Wih1, Whh1};

    static bool attr_done = false;
    if (!attr_done) {
        cudaFuncSetAttribute(hmma_big,       cudaFuncAttributeMaxDynamicSharedMemorySize, BIG_DYN);
        cudaFuncSetAttribute(gru_persist<0>, cudaFuncAttributeMaxDynamicSharedMemorySize, GRU_DYN);
        cudaFuncSetAttribute(gru_persist<1>, cudaFuncAttributeMaxDynamicSharedMemorySize, GRU_DYN);
        attr_done = true;
    }

    // --- sort rows by flen + reset counters ---
    rank_kernel<<<NSEQ/256, 256>>>(flen);

    // --- conversions (friend_x skips dead (row,t)) ---
    split_fx<<<((size_t)MTOT*HD + 255)/256, 256>>>(friend_x, FXh, FXl, flen);
    for (int w = 0; w < 4; ++w)
        split_kernel<<<(G3*HD + 255)/256, 256>>>(Wsrc[w], Wh + (size_t)w*G3*HD,
                                                 Wl + (size_t)w*G3*HD, G3*HD);

    const dim3 big_grid(8, 16, LSEQ);
    const dim3 pgrid(16, 8);

    // ---- layer 0 ----
    hmma_big<<<big_grid, 256, BIG_DYN>>>(FXh, FXl, Wh + 0*(size_t)G3*HD, Wl + 0*(size_t)G3*HD, GI);
    gru_persist<0><<<pgrid, 256, GRU_DYN>>>(
        Wh + 1*(size_t)G3*HD, Wl + 1*(size_t)G3*HD, GI,
        Hh, Hl, X1h, X1l, nullptr, flen, bih0, bhh0);

    // ---- layer 1 ----
    hmma_big<<<big_grid, 256, BIG_DYN>>>(X1h, X1l, Wh + 2*(size_t)G3*HD, Wl + 2*(size_t)G3*HD, GI);
    gru_persist<1><<<pgrid, 256, GRU_DYN>>>(
        Wh + 3*(size_t)G3*HD, Wl + 3*(size_t)G3*HD, GI,
        Hh, Hl, nullptr, nullptr, FL, flen, bih1, bhh1);

    // ---- tail ----
    build_cat<<<NSEQ, 256>>>(self_x, FL, CAT);
    sgemm_tn<0><<<dim3(NSEQ/64, HD/64), 256>>>(CAT, Wf, SF, NSEQ, HD, 2*HD);
    sgemm_tn<1><<<dim3(NSEQ/64, HD/64), 256>>>(SF,  Wb, V,  NSEQ, HD, HD);
    tf_kernel<<<NSEQ, 256>>>(common_x, common_time, V, clen, TF);
    out_kernel<<<NBATCH, 256>>>(TF, FL, fnum, out);
}

// round 10
// speedup vs baseline: 2.7143x; 1.0911x over previous
#include <cuda_runtime.h>
#include <cuda_bf16.h>
#include <cstdint>
#include <math.h>

#define HD    256
#define LSEQ  50
#define SSEQ  50
#define NBATCH 64
#define MAXF  32
#define NSEQ  (NBATCH*MAXF)            // 2048
#define MTOT  (NSEQ*LSEQ)              // 102400
#define G3    (3*HD)                   // 768
#define NTILES (16*LSEQ*8)             // L1 GEMM tile space

// ---------------- device scratch ----------------
__device__ __nv_bfloat16  g_Hh[2][NSEQ*HD];
__device__ __nv_bfloat16  g_Hl[2][NSEQ*HD];
__device__ float          g_GI[(size_t)MTOT*G3];    // layer-0 pre-activations
__device__ float          g_GI2[(size_t)MTOT*G3];   // layer-1 pre-activations
__device__ __nv_bfloat16  g_FXh[(size_t)MTOT*HD];
__device__ __nv_bfloat16  g_FXl[(size_t)MTOT*HD];
__device__ __nv_bfloat16  g_X1h[(size_t)MTOT*HD];
__device__ __nv_bfloat16  g_X1l[(size_t)MTOT*HD];
__device__ __nv_bfloat16  g_Wh[4][G3*HD];
__device__ __nv_bfloat16  g_Wl[4][G3*HD];
__device__ float g_FL[NSEQ*HD];
__device__ float g_CAT[NSEQ*2*HD];
__device__ float g_SF[NSEQ*HD];
__device__ float g_V[NSEQ*HD];
__device__ float g_TF[NSEQ];
__device__ unsigned g_cnt[32];            // rowgroup step counters (16 per layer)
__device__ unsigned g_work;               // L1 GEMM tile queue head
__device__ int g_perm[NSEQ];
__device__ int g_gmax[16];

// ---------------- helpers ----------------
__device__ __forceinline__ float fast_sigmoid(float x){
    return __fdividef(1.f, 1.f + __expf(-x));
}
__device__ __forceinline__ float fast_tanh(float x){
    return 1.f - __fdividef(2.f, __expf(2.f*x) + 1.f);
}
__device__ __forceinline__ float softplus_f(float x){
    return (x > 20.f) ? x : log1pf(expf(x));
}
__device__ __forceinline__ float2 ffma2(float2 a, float2 b, float2 c){
    unsigned long long ua = reinterpret_cast<unsigned long long&>(a);
    unsigned long long ub = reinterpret_cast<unsigned long long&>(b);
    unsigned long long uc = reinterpret_cast<unsigned long long&>(c);
    unsigned long long ud;
    asm("fma.rn.f32x2 %0, %1, %2, %3;" : "=l"(ud) : "l"(ua), "l"(ub), "l"(uc));
    return reinterpret_cast<float2&>(ud);
}
__device__ __forceinline__ uint32_t smem_u32(const void* p){
    return (uint32_t)__cvta_generic_to_shared(p);
}
__device__ __forceinline__ void ldsm_x4(unsigned* r, uint32_t addr){
    asm volatile("ldmatrix.sync.aligned.m8n8.x4.shared.b16 {%0,%1,%2,%3}, [%4];\n"
        : "=r"(r[0]), "=r"(r[1]), "=r"(r[2]), "=r"(r[3]) : "r"(addr));
}
__device__ __forceinline__ void mma16816(float* c, const unsigned* a, const unsigned* b){
    asm volatile("mma.sync.aligned.m16n8k16.row.col.f32.bf16.bf16.f32 "
        "{%0,%1,%2,%3}, {%4,%5,%6,%7}, {%8,%9}, {%0,%1,%2,%3};\n"
        : "+f"(c[0]), "+f"(c[1]), "+f"(c[2]), "+f"(c[3])
        : "r"(a[0]), "r"(a[1]), "r"(a[2]), "r"(a[3]), "r"(b[0]), "r"(b[1]));
}
__device__ __forceinline__ unsigned ld_acq(const unsigned* p){
    unsigned v;
    asm volatile("ld.acquire.gpu.u32 %0, [%1];" : "=r"(v) : "l"(p) : "memory");
    return v;
}
__device__ __forceinline__ void red_release(unsigned* p){
    asm volatile("red.release.gpu.global.add.u32 [%0], %1;" :: "l"(p), "r"(1u) : "memory");
}
__device__ __forceinline__ void cp16(uint32_t dst, const void* src){
    asm volatile("cp.async.cg.shared.global [%0], [%1], 16;" :: "r"(dst), "l"(src) : "memory");
}
#define CP_COMMIT() asm volatile("cp.async.commit_group;" ::: "memory")
#define CP_WAIT1()  asm volatile("cp.async.wait_group 1;" ::: "memory")
#define CP_WAIT0()  asm volatile("cp.async.wait_group 0;" ::: "memory")

// ---------------- sort rows by flen (descending, deterministic) ----------------
__global__ void rank_kernel(const int* __restrict__ flen){
    __shared__ int fl_s[NSEQ];
    for (int i = threadIdx.x; i < NSEQ; i += 256) fl_s[i] = flen[i];
    __syncthreads();
    const int i = blockIdx.x*256 + threadIdx.x;
    const int f = fl_s[i];
    int r = 0;
    for (int jj = 0; jj < NSEQ; ++jj) {
        int fj = fl_s[jj];
        r += (fj > f) || (fj == f && jj < i);
    }
    g_perm[r] = i;
    if ((r & 127) == 0) g_gmax[r >> 7] = f;
    if (blockIdx.x == 0 && threadIdx.x < 32) g_cnt[threadIdx.x] = 0u;
    if (blockIdx.x == 0 && threadIdx.x == 0) g_work = 0u;
}

// ---------------- staging (cp.async) ----------------
__device__ __forceinline__ void stageA_seq(uint32_t sA_h, uint32_t sA_l,
        const __nv_bfloat16* __restrict__ Ah, const __nv_bfloat16* __restrict__ Al,
        const int* __restrict__ perm_s, int t, int kk, int tid){
    #pragma unroll
    for (int q = 0; q < 2; ++q) {
        int idx = q*256 + tid;
        int r = idx >> 2, ks = (idx & 3) << 3;
        size_t s = ((size_t)perm_s[r]*LSEQ + t)*HD + kk + ks;
        uint32_t d = (uint32_t)(r*40 + ks)*2u;
        cp16(sA_h + d, Ah + s);
        cp16(sA_l + d, Al + s);
    }
}
__device__ __forceinline__ void stageA_row(uint32_t sA_h, uint32_t sA_l,
        const __nv_bfloat16* __restrict__ Ah, const __nv_bfloat16* __restrict__ Al,
        const int* __restrict__ perm_s, int kk, int tid){
    #pragma unroll
    for (int q = 0; q < 2; ++q) {
        int idx = q*256 + tid;
        int r = idx >> 2, ks = (idx & 3) << 3;
        size_t s = (size_t)perm_s[r]*HD + kk + ks;
        uint32_t d = (uint32_t)(r*40 + ks)*2u;
        cp16(sA_h + d, Ah + s);
        cp16(sA_l + d, Al + s);
    }
}
__device__ __forceinline__ void stageB_cp(uint32_t sB_h, uint32_t sB_l,
        const __nv_bfloat16* __restrict__ Bh, const __nv_bfloat16* __restrict__ Bl,
        int ubu, int kk, int tid){
    #pragma unroll
    for (int q = 0; q < 2; ++q) {
        int idx = q*256 + tid;
        if (idx < 384) {
            int p = idx >> 2, ks = (idx & 3) << 3;
            int w = (p >> 5)*HD + ubu + (p & 31);
            size_t s = (size_t)w*HD + kk + ks;
            uint32_t d = (uint32_t)(p*40 + ks)*2u;
            cp16(sB_h + d, Bh + s);
            cp16(sB_l + d, Bl + s);
        }
    }
}
__device__ __forceinline__ void stageGI_piece(uint32_t cs, const float* __restrict__ GI,
        const int* __restrict__ perm_s, int t, size_t colbase, int piece, int tid){
    #pragma unroll
    for (int q = 0; q < 2; ++q) {
        int i = q*256 + tid;
        if (i < 384) {
            int i2 = piece*384 + i;
            int rl = i2 / 24, c16 = i2 % 24;
            const float* src = GI + ((size_t)perm_s[rl]*LSEQ + t)*G3 + colbase + c16*4;
            cp16(cs + (uint32_t)(rl*128 + c16*4)*4u, src);
        }
    }
}

// ---------------- MMA on one staged 32-k chunk (3-term hi/lo) ----------------
__device__ __forceinline__ void mma_chunk(
    float (&c)[2][6][4],
    uint32_t aAsh, uint32_t aAsl, uint32_t aBsh, uint32_t aBsl,
    int a_m, int a_k, int b_n, int b_k, int wm, int wn, int bstride, int bkoff)
{
    #pragma unroll
    for (int kt = 0; kt < 2; ++kt) {
        unsigned ah[2][4], al[2][4], bh[3][4], bl[3][4];
        #pragma unroll
        for (int mt = 0; mt < 2; ++mt) {
            uint32_t off = 2u*((wm*32 + mt*16 + a_m)*40 + kt*16 + a_k);
            ldsm_x4(ah[mt], aAsh + off);
            ldsm_x4(al[mt], aAsl + off);
        }
        #pragma unroll
        for (int np = 0; np < 3; ++np) {
            uint32_t off = 2u*((wn*48 + np*16 + b_n)*bstride + bkoff + kt*16 + b_k);
            ldsm_x4(bh[np], aBsh + off);
            ldsm_x4(bl[np], aBsl + off);
        }
        #pragma unroll
        for (int mt = 0; mt < 2; ++mt)
            #pragma unroll
            for (int nt = 0; nt < 6; ++nt) {
                const unsigned* B1 = &bh[nt>>1][(nt&1)*2];
                const unsigned* B2 = &bl[nt>>1][(nt&1)*2];
                mma16816(c[mt][nt], ah[mt], B1);
                mma16816(c[mt][nt], al[mt], B1);
                mma16816(c[mt][nt], ah[mt], B2);
            }
    }
}

// ---------------- hi/lo split conversions ----------------
__global__ void split_kernel(const float* __restrict__ x,
                             __nv_bfloat16* __restrict__ hi,
                             __nv_bfloat16* __restrict__ lo, int n){
    int i = blockIdx.x*256 + threadIdx.x;
    if (i < n){
        float v = x[i];
        __nv_bfloat16 h = __float2bfloat16(v);
        hi[i] = h;
        lo[i] = __float2bfloat16(v - __bfloat162float(h));
    }
}
__global__ void split_fx(const float* __restrict__ x,
                         __nv_bfloat16* __restrict__ hi,
                         __nv_bfloat16* __restrict__ lo,
                         const int* __restrict__ flen){
    int i = blockIdx.x*256 + threadIdx.x;
    int t   = (i >> 8) % LSEQ;
    int row = i / (LSEQ*HD);
    if (t >= flen[row]) return;
    float v = x[i];
    __nv_bfloat16 h = __float2bfloat16(v);
    hi[i] = h;
    lo[i] = __float2bfloat16(v - __bfloat162float(h));
}

// =====================================================================
// Big x-GEMM (layer 0), cp.async double-buffered, 2 CTAs/SM.
// grid (8 units, 16 seqgroups, 50 t); early exit when t >= gmax[sg].
// =====================================================================
#define BIG_ASH 0u
#define BIG_ASL 20480u
#define BIG_BSH 40960u
#define BIG_BSL 56320u
#define BIG_DYN 71680u

__global__ __launch_bounds__(256, 2) void hmma_big(
    const __nv_bfloat16* __restrict__ Ah, const __nv_bfloat16* __restrict__ Al,
    const __nv_bfloat16* __restrict__ Bh, const __nv_bfloat16* __restrict__ Bl,
    float* __restrict__ GI)
{
    const int sg = blockIdx.y;
    const int t  = blockIdx.z;
    if (t >= g_gmax[sg]) return;

    extern __shared__ char smraw[];
    __shared__ int perm_s[128];
    const uint32_t sb = smem_u32(smraw);
    const int tid  = threadIdx.x;
    const int lane = tid & 31, warp = tid >> 5;
    const int wm = warp >> 1, wn = warp & 1;
    const int ubu = blockIdx.x * 32;

    if (tid < 128) perm_s[tid] = g_perm[sg*128 + tid];
    __syncthreads();

    const int grp = lane >> 3, rr = lane & 7;
    const int a_m = (grp & 1)*8 + rr, a_k = (grp >> 1)*8;
    const int b_n = (grp >> 1)*8 + rr, b_k = (grp & 1)*8;

    float c[2][6][4];
    #pragma unroll
    for (int mt = 0; mt < 2; ++mt)
        #pragma unroll
        for (int nt = 0; nt < 6; ++nt)
            #pragma unroll
            for (int q = 0; q < 4; ++q) c[mt][nt][q] = 0.f;

    stageA_seq(sb + BIG_ASH, sb + BIG_ASL, Ah, Al, perm_s, t, 0, tid);
    stageB_cp(sb + BIG_BSH, sb + BIG_BSL, Bh, Bl, ubu, 0, tid);
    CP_COMMIT();

    for (int kc = 0; kc < 8; ++kc) {
        const int buf = kc & 1;
        if (kc < 7) {
            const int nb = buf ^ 1;
            stageA_seq(sb + BIG_ASH + nb*10240u, sb + BIG_ASL + nb*10240u,
                       Ah, Al, perm_s, t, (kc+1)*32, tid);
            stageB_cp(sb + BIG_BSH + nb*7680u, sb + BIG_BSL + nb*7680u,
                      Bh, Bl, ubu, (kc+1)*32, tid);
            CP_COMMIT();
            CP_WAIT1();
        } else {
            CP_WAIT0();
        }
        __syncthreads();
        mma_chunk(c, sb + BIG_ASH + buf*10240u, sb + BIG_ASL + buf*10240u,
                     sb + BIG_BSH + buf*7680u,  sb + BIG_BSL + buf*7680u,
                  a_m, a_k, b_n, b_k, wm, wn, 40, 0);
        __syncthreads();
    }

    const size_t colbase = (size_t)blockIdx.x * 96;
    #pragma unroll
    for (int mt = 0; mt < 2; ++mt)
        #pragma unroll
        for (int nt = 0; nt < 6; ++nt) {
            int rl = wm*32 + mt*16 + (lane >> 2);
            int cl = wn*48 + nt*8 + ((lane & 3) << 1);
            size_t r0 = ((size_t)perm_s[rl]*LSEQ + t)*G3;
            size_t r1 = ((size_t)perm_s[rl+8]*LSEQ + t)*G3;
            *(float2*)&GI[r0 + colbase + cl] = make_float2(c[mt][nt][0], c[mt][nt][1]);
            *(float2*)&GI[r1 + colbase + cl] = make_float2(c[mt][nt][2], c[mt][nt][3]);
        }
}

// =====================================================================
// Persistent GRU recurrence (per-rowgroup step bound gmax[rg]).
// LAYER 0: after the recurrence, CTAs steal layer-1 x-GEMM tiles from a
// global queue, gated on the resident rowgroup counters (deadlock-free:
// all 128 CTAs are co-resident; counters only advance via resident CTAs).
// =====================================================================
#define GRU_BSH 0u
#define GRU_BSL 50688u
#define GRU_ASH 101376u
#define GRU_ASL 121856u
#define GRU_CS  142336u
#define GRU_DYN 207872u
#define SM_B_STRIDE 264

template<int LAYER>
__global__ __launch_bounds__(256) void gru_persist(
    const __nv_bfloat16* __restrict__ Whh_h, const __nv_bfloat16* __restrict__ Whh_l,
    const float* __restrict__ GI,
    __nv_bfloat16* __restrict__ Hhb, __nv_bfloat16* __restrict__ Hlb,
    __nv_bfloat16* __restrict__ X1h, __nv_bfloat16* __restrict__ X1l,
    float* __restrict__ FL, const int* __restrict__ flen,
    const float* __restrict__ bih, const float* __restrict__ bhh,
    const __nv_bfloat16* __restrict__ sBh, const __nv_bfloat16* __restrict__ sBl,
    float* __restrict__ GI2)
{
    extern __shared__ char smraw[];
    __shared__ int perm_s[128];
    __shared__ int flen_s[128];
    __shared__ unsigned widx_s;
    const uint32_t sb = smem_u32(smraw);
    float* Cs = (float*)(smraw + GRU_CS);
    const uint32_t csb = sb + GRU_CS;
    unsigned short* Bsh = (unsigned short*)(smraw + GRU_BSH);
    unsigned short* Bsl = (unsigned short*)(smraw + GRU_BSL);

    const int tid  = threadIdx.x;
    const int lane = tid & 31, warp = tid >> 5;
    const int wm = warp >> 1, wn = warp & 1;
    const int rg   = blockIdx.x;
    const int ubu  = blockIdx.y * 32;
    const int tmax = g_gmax[rg];

    if (tid < 128) {
        int p = g_perm[rg*128 + tid];
        perm_s[tid] = p;
        flen_s[tid] = flen[p];
    }

    const int grp = lane >> 3, rr = lane & 7;
    const int a_m = (grp & 1)*8 + rr, a_k = (grp >> 1)*8;
    const int b_n = (grp >> 1)*8 + rr, b_k = (grp & 1)*8;

    // ---- load Whh tile once ----
    for (int idx = tid; idx < 96*32; idx += 256) {
        int p = idx >> 5, ks = (idx & 31) << 3;
        int w = (p >> 5)*HD + ubu + (p & 31);
        *(uint4*)&Bsh[p*SM_B_STRIDE + ks] = *(const uint4*)&Whh_h[(size_t)w*HD + ks];
        *(uint4*)&Bsl[p*SM_B_STRIDE + ks] = *(const uint4*)&Whh_l[(size_t)w*HD + ks];
    }
    __syncthreads();

    const int jl = tid & 31;
    const int j  = ubu + jl;
    const float b_r  = bih[j]      + bhh[j];
    const float b_z  = bih[HD+j]   + bhh[HD+j];
    const float bi_n = bih[2*HD+j];
    const float bh_n = bhh[2*HD+j];
    const size_t colbase = (size_t)blockIdx.y * 96;
    unsigned* cnt = &g_cnt[rg + (LAYER ? 16 : 0)];

    for (int t = 0; t < tmax; ++t) {
        const int pa = t & 1, pb = (t+1) & 1;
        const __nv_bfloat16* Ahp = Hhb + (size_t)pa*NSEQ*HD;
        const __nv_bfloat16* Alp = Hlb + (size_t)pa*NSEQ*HD;
        __nv_bfloat16* Hnh = Hhb + (size_t)pb*NSEQ*HD;
        __nv_bfloat16* Hnl = Hlb + (size_t)pb*NSEQ*HD;

        float c[2][6][4];
        #pragma unroll
        for (int mt = 0; mt < 2; ++mt)
            #pragma unroll
            for (int nt = 0; nt < 6; ++nt)
                #pragma unroll
                for (int q = 0; q < 4; ++q) c[mt][nt][q] = 0.f;

        if (t > 0) {
            stageA_row(sb + GRU_ASH, sb + GRU_ASL, Ahp, Alp, perm_s, 0, tid);
            stageGI_piece(csb, GI, perm_s, t, colbase, 0, tid);
            CP_COMMIT();
            for (int kc = 0; kc < 8; ++kc) {
                const int buf = kc & 1;
                if (kc < 7) {
                    const int nb = buf ^ 1;
                    stageA_row(sb + GRU_ASH + nb*10240u, sb + GRU_ASL + nb*10240u,
                               Ahp, Alp, perm_s, (kc+1)*32, tid);
                    stageGI_piece(csb, GI, perm_s, t, colbase, kc+1, tid);
                    CP_COMMIT();
                    CP_WAIT1();
                } else {
                    CP_WAIT0();
                }
                __syncthreads();
                mma_chunk(c, sb + GRU_ASH + buf*10240u, sb + GRU_ASL + buf*10240u,
                             sb + GRU_BSH, sb + GRU_BSL,
                          a_m, a_k, b_n, b_k, wm, wn, SM_B_STRIDE, kc*32);
                __syncthreads();
            }
        } else {
            #pragma unroll
            for (int pc = 0; pc < 8; ++pc)
                stageGI_piece(csb, GI, perm_s, t, colbase, pc, tid);
            CP_COMMIT();
            CP_WAIT0();
            __syncthreads();
        }

        // ---- merge fragments: r/z add into Cs, n store to hh_n column ----
        #pragma unroll
        for (int mt = 0; mt < 2; ++mt)
            #pragma unroll
            for (int nt = 0; nt < 6; ++nt) {
                int rl = wm*32 + mt*16 + (lane >> 2);
                int cl = wn*48 + nt*8 + ((lane & 3) << 1);
                const bool is_n = (cl >= 64);
                const int ccl = is_n ? cl + 32 : cl;
                float2* p0 = (float2*)&Cs[rl*128 + ccl];
                float2* p1 = (float2*)&Cs[(rl+8)*128 + ccl];
                if (is_n) {
                    *p0 = make_float2(c[mt][nt][0], c[mt][nt][1]);
                    *p1 = make_float2(c[mt][nt][2], c[mt][nt][3]);
                } else {
                    float2 v0 = *p0, v1 = *p1;
                    *p0 = make_float2(v0.x + c[mt][nt][0], v0.y + c[mt][nt][1]);
                    *p1 = make_float2(v1.x + c[mt][nt][2], v1.y + c[mt][nt][3]);
                }
            }
        __syncthreads();

        // ---- gate epilogue ----
        #pragma unroll
        for (int i = 0; i < 16; ++i) {
            const int rl  = (tid >> 5) + i*8;
            const int row = perm_s[rl];
            const float r = fast_sigmoid(Cs[rl*128 + jl]      + b_r);
            const float z = fast_sigmoid(Cs[rl*128 + 32 + jl] + b_z);
            const float n = fast_tanh(Cs[rl*128 + 64 + jl] + bi_n +
                                      r*(Cs[rl*128 + 96 + jl] + bh_n));
            float hp = 0.f;
            if (t > 0)
                hp = __bfloat162float(Ahp[(size_t)row*HD + j]) +
                     __bfloat162float(Alp[(size_t)row*HD + j]);
            const float h  = (1.f - z)*n + z*hp;
            __nv_bfloat16 hh = __float2bfloat16(h);
            __nv_bfloat16 hl = __float2bfloat16(h - __bfloat162float(hh));
            Hnh[(size_t)row*HD + j] = hh;
            Hnl[(size_t)row*HD + j] = hl;
            if (LAYER == 0) {
                size_t xi = ((size_t)row*LSEQ + t)*HD + j;
                X1h[xi] = hh; X1l[xi] = hl;
            } else {
                if (t == flen_s[rl] - 1) FL[(size_t)row*HD + j] = h;
            }
        }

        // ---- rowgroup barrier: always release (consumed by stealers), wait unless last ----
        __threadfence();
        __syncthreads();
        if (tid == 0) {
            red_release(cnt);
            if (t + 1 < tmax) {
                const unsigned target = 8u*(unsigned)(t+1);
                while (ld_acq(cnt) < target) __nanosleep(32);
            }
        }
        __syncthreads();
    }

    // =============== LAYER 0: steal layer-1 x-GEMM tiles ===============
    if (LAYER == 0) {
        for (;;) {
            __syncthreads();
            if (tid == 0) widx_s = atomicAdd(&g_work, 1u);
            __syncthreads();
            const unsigned widx = widx_s;
            if (widx >= (unsigned)NTILES) break;
            const int t   = (int)(widx / 128u);      // t ascending: matches availability
            const int sg  = (int)((widx / 8u) % 16u);
            const int ubx = (int)(widx % 8u);
            if (t >= g_gmax[sg]) continue;

            if (tid == 0) {
                const unsigned target = 8u*(unsigned)(t+1);
                while (ld_acq(&g_cnt[sg]) < target) __nanosleep(64);
            }
            if (tid < 128) perm_s[tid] = g_perm[sg*128 + tid];
            __syncthreads();

            float c[2][6][4];
            #pragma unroll
            for (int mt = 0; mt < 2; ++mt)
                #pragma unroll
                for (int nt = 0; nt < 6; ++nt)
                    #pragma unroll
                    for (int q = 0; q < 4; ++q) c[mt][nt][q] = 0.f;

            stageA_seq(sb + GRU_ASH, sb + GRU_ASL, X1h, X1l, perm_s, t, 0, tid);
            stageB_cp(sb + GRU_BSH, sb + GRU_BSL, sBh, sBl, ubx*32, 0, tid);
            CP_COMMIT();
            for (int kc = 0; kc < 8; ++kc) {
                const int buf = kc & 1;
                if (kc < 7) {
                    const int nb = buf ^ 1;
                    stageA_seq(sb + GRU_ASH + nb*10240u, sb + GRU_ASL + nb*10240u,
                               X1h, X1l, perm_s, t, (kc+1)*32, tid);
                    stageB_cp(sb + GRU_BSH + nb*7680u, sb + GRU_BSL + nb*7680u,
                              sBh, sBl, ubx*32, (kc+1)*32, tid);
                    CP_COMMIT();
                    CP_WAIT1();
                } else {
                    CP_WAIT0();
                }
                __syncthreads();
                mma_chunk(c, sb + GRU_ASH + buf*10240u, sb + GRU_ASL + buf*10240u,
                             sb + GRU_BSH + buf*7680u,  sb + GRU_BSL + buf*7680u,
                          a_m, a_k, b_n, b_k, wm, wn, 40, 0);
                __syncthreads();
            }

            const size_t cb2 = (size_t)ubx * 96;
            #pragma unroll
            for (int mt = 0; mt < 2; ++mt)
                #pragma unroll
                for (int nt = 0; nt < 6; ++nt) {
                    int rl = wm*32 + mt*16 + (lane >> 2);
                    int cl = wn*48 + nt*8 + ((lane & 3) << 1);
                    size_t r0 = ((size_t)perm_s[rl]*LSEQ + t)*G3;
                    size_t r1 = ((size_t)perm_s[rl+8]*LSEQ + t)*G3;
                    *(float2*)&GI2[r0 + cb2 + cl] = make_float2(c[mt][nt][0], c[mt][nt][1]);
                    *(float2*)&GI2[r1 + cb2 + cl] = make_float2(c[mt][nt][2], c[mt][nt][3]);
                }
        }
    }
}

// ---------------- fp32 tail GEMM (small) ----------------
template<int TRANSW>
__global__ __launch_bounds__(256) void sgemm_tn(
    const float* __restrict__ A, const float* __restrict__ W, float* __restrict__ C,
    int M, int N, int K)
{
    __shared__ float As[32][68];
    __shared__ float Bs[32][68];
    const int tid = threadIdx.x;
    const int tx = tid & 15, ty = tid >> 4;
    const int mb = blockIdx.x * 64, nb = blockIdx.y * 64;

    float2 acc[4][2];
    #pragma unroll
    for (int i = 0; i < 4; ++i) { acc[i][0] = make_float2(0.f,0.f); acc[i][1] = make_float2(0.f,0.f); }

    for (int kc = 0; kc < K; kc += 32) {
        #pragma unroll
        for (int q = 0; q < 2; ++q) {
            int idx = q*256 + tid;
            int row = idx >> 3;
            int k4  = (idx & 7) << 2;
            const float4 v = *reinterpret_cast<const float4*>(&A[(size_t)(mb+row)*K + kc + k4]);
            As[k4+0][row] = v.x; As[k4+1][row] = v.y; As[k4+2][row] = v.z; As[k4+3][row] = v.w;
        }
        if (!TRANSW) {
            #pragma unroll
            for (int q = 0; q < 2; ++q) {
                int idx = q*256 + tid;
                int n  = idx >> 3;
                int k4 = (idx & 7) << 2;
                const float4 v = *reinterpret_cast<const float4*>(&W[(size_t)(nb+n)*K + kc + k4]);
                Bs[k4+0][n] = v.x; Bs[k4+1][n] = v.y; Bs[k4+2][n] = v.z; Bs[k4+3][n] = v.w;
            }
        } else {
            #pragma unroll
            for (int q = 0; q < 2; ++q) {
                int idx = q*256 + tid;
                int k  = idx >> 4;
                int n4 = (idx & 15) << 2;
                const float4 v = *reinterpret_cast<const float4*>(&W[(size_t)(kc+k)*N + nb + n4]);
                *reinterpret_cast<float4*>(&Bs[k][n4]) = v;
            }
        }
        __syncthreads();
        #pragma unroll
        for (int k = 0; k < 32; ++k) {
            const float4 a4 = *reinterpret_cast<const float4*>(&As[k][ty<<2]);
            const float4 b4 = *reinterpret_cast<const float4*>(&Bs[k][tx<<2]);
            const float2 b0 = make_float2(b4.x, b4.y);
            const float2 b1 = make_float2(b4.z, b4.w);
            float av[4] = {a4.x, a4.y, a4.z, a4.w};
            #pragma unroll
            for (int i = 0; i < 4; ++i) {
                float2 aa = make_float2(av[i], av[i]);
                acc[i][0] = ffma2(aa, b0, acc[i][0]);
                acc[i][1] = ffma2(aa, b1, acc[i][1]);
            }
        }
        __syncthreads();
    }
    #pragma unroll
    for (int i = 0; i < 4; ++i) {
        const int row = mb + (ty<<2) + i;
        float4 o;
        o.x = acc[i][0].x; o.y = acc[i][0].y; o.z = acc[i][1].x; o.w = acc[i][1].y;
        *reinterpret_cast<float4*>(&C[(size_t)row*N + nb + (tx<<2)]) = o;
    }
}

__global__ void build_cat(const float* __restrict__ self_x,
                          const float* __restrict__ FL,
                          float* __restrict__ CAT){
    const int m = blockIdx.x, tid = threadIdx.x;
    CAT[(size_t)m*2*HD + tid]      = self_x[(size_t)(m>>5)*HD + tid];
    CAT[(size_t)m*2*HD + HD + tid] = FL[(size_t)m*HD + tid];
}

__global__ __launch_bounds__(256) void tf_kernel(
    const float* __restrict__ common_x, const float* __restrict__ common_time,
    const float* __restrict__ V, const int* __restrict__ clen, float* __restrict__ TF)
{
    const int m = blockIdx.x;
    __shared__ float vs[HD];
    __shared__ float wsum[8];
    const int tid = threadIdx.x;
    vs[tid] = V[(size_t)m*HD + tid];
    __syncthreads();
    const int warp = tid >> 5, lane = tid & 31;
    const int cl = clen[m];
    float acc = 0.f;
    for (int s = warp; s < cl; s += 8) {
        const float* cx = common_x + ((size_t)m*SSEQ + s)*HD;
        float p = 0.f;
        #pragma unroll
        for (int q = 0; q < 8; ++q) p += cx[lane + 32*q] * vs[lane + 32*q];
        #pragma unroll
        for (int off = 16; off; off >>= 1) p += __shfl_xor_sync(0xffffffffu, p, off);
        if (lane == 0)
            acc += softplus_f(p) * expf(-common_time[(size_t)m*SSEQ + s]);
    }
    if (lane == 0) wsum[warp] = acc;
    __syncthreads();
    if (tid == 0) {
        float s = 0.f;
        for (int w = 0; w < 8; ++w) s += wsum[w];
        TF[m] = s;
    }
}

__global__ __launch_bounds__(256) void out_kernel(
    const float* __restrict__ TF, const float* __restrict__ FL,
    const int* __restrict__ fnum, float* __restrict__ out)
{
    const int b = blockIdx.x;
    __shared__ float w[MAXF];
    const int tid = threadIdx.x;
    const int fn = fnum[b];
    if (tid < MAXF) w[tid] = (tid < fn) ? TF[b*MAXF + tid] : 0.f;
    __syncthreads();
    if (tid == 0) {
        float mx = w[0];
        for (int f = 1; f < MAXF; ++f) mx = fmaxf(mx, w[f]);
        float s = 0.f;
        for (int f = 0; f < MAXF; ++f) { float e = expf(w[f] - mx); w[f] = e; s += e; }
        float inv = 1.f / s;
        for (int f = 0; f < MAXF; ++f) w[f] *= inv;
    }
    __syncthreads();
    float acc = 0.f;
    for (int f = 0; f < fn; ++f)
        acc += w[f] * FL[(size_t)(b*MAXF + f)*HD + tid];
    out[(size_t)b*HD + tid] = acc;
}

// ---------------- host launcher ----------------
extern "C" void kernel_launch(void* const* d_in, const int* in_sizes, int n_in,
                              void* d_out, int out_size)
{
    const float* self_x      = (const float*)d_in[0];
    const float* common_x    = (const float*)d_in[1];
    const float* common_time = (const float*)d_in[2];
    const float* friend_x    = (const float*)d_in[3];
    const float* Wih0 = (const float*)d_in[4];
    const float* Whh0 = (const float*)d_in[5];
    const float* bih0 = (const float*)d_in[6];
    const float* bhh0 = (const float*)d_in[7];
    const float* Wih1 = (const float*)d_in[8];
    const float* Whh1 = (const float*)d_in[9];
    const float* bih1 = (const float*)d_in[10];
    const float* bhh1 = (const float*)d_in[11];
    const float* Wf   = (const float*)d_in[12];
    const float* Wb   = (const float*)d_in[13];
    const int*   flen = (const int*)d_in[14];
    const int*   fnum = (const int*)d_in[15];
    const int*   clen = (const int*)d_in[16];
    float* out = (float*)d_out;

    float *GI, *GI2, *FL, *CAT, *SF, *V, *TF;
    __nv_bfloat16 *Hh, *Hl, *FXh, *FXl, *X1h, *X1l, *Wh, *Wl;
    cudaGetSymbolAddress((void**)&Hh,  g_Hh);
    cudaGetSymbolAddress((void**)&Hl,  g_Hl);
    cudaGetSymbolAddress((void**)&GI,  g_GI);
    cudaGetSymbolAddress((void**)&GI2, g_GI2);
    cudaGetSymbolAddress((void**)&FXh, g_FXh);
    cudaGetSymbolAddress((void**)&FXl, g_FXl);
    cudaGetSymbolAddress((void**)&X1h, g_X1h);
    cudaGetSymbolAddress((void**)&X1l, g_X1l);
    cudaGetSymbolAddress((void**)&Wh,  g_Wh);
    cudaGetSymbolAddress((void**)&Wl,  g_Wl);
    cudaGetSymbolAddress((void**)&FL,  g_FL);
    cudaGetSymbolAddress((void**)&CAT, g_CAT);
    cudaGetSymbolAddress((void**)&SF,  g_SF);
    cudaGetSymbolAddress((void**)&V,   g_V);
    cudaGetSymbolAddress((void**)&TF,  g_TF);

    const float* Wsrc[4] = {Wih0, Whh0, Wih1, Whh1};

    static bool init_done = false;
    if (!init_done) {
        cudaFuncSetAttribute(hmma_big,       cudaFuncAttributeMaxDynamicSharedMemorySize, BIG_DYN);
        cudaFuncSetAttribute(gru_persist<0>, cudaFuncAttributeMaxDynamicSharedMemorySize, GRU_DYN);
        cudaFuncSetAttribute(gru_persist<1>, cudaFuncAttributeMaxDynamicSharedMemorySize, GRU_DYN);
        init_done = true;
    }

    // --- sort rows by flen + reset counters/queue ---
    rank_kernel<<<NSEQ/256, 256>>>(flen);

    // --- conversions ---
    split_fx<<<((size_t)MTOT*HD + 255)/256, 256>>>(friend_x, FXh, FXl, flen);
    for (int w = 0; w < 4; ++w)
        split_kernel<<<(G3*HD + 255)/256, 256>>>(Wsrc[w], Wh + (size_t)w*G3*HD,
                                                 Wl + (size_t)w*G3*HD, G3*HD);

    const dim3 big_grid(8, 16, LSEQ);
    const dim3 pgrid(16, 8);

    // ---- layer 0 big GEMM ----
    hmma_big<<<big_grid, 256, BIG_DYN>>>(FXh, FXl,
        Wh + 0*(size_t)G3*HD, Wl + 0*(size_t)G3*HD, GI);

    // ---- layer 0 recurrence + embedded layer-1 x-GEMM (work stealing) ----
    gru_persist<0><<<pgrid, 256, GRU_DYN>>>(
        Wh + 1*(size_t)G3*HD, Wl + 1*(size_t)G3*HD, GI,
        Hh, Hl, X1h, X1l, nullptr, flen, bih0, bhh0,
        Wh + 2*(size_t)G3*HD, Wl + 2*(size_t)G3*HD, GI2);

    // ---- layer 1 recurrence (GI2 fully materialized by kernel above) ----
    gru_persist<1><<<pgrid, 256, GRU_DYN>>>(
        Wh + 3*(size_t)G3*HD, Wl + 3*(size_t)G3*HD, GI2,
        Hh, Hl, nullptr, nullptr, FL, flen, bih1, bhh1,
        nullptr, nullptr, nullptr);

    // ---- tail ----
    build_cat<<<NSEQ, 256>>>(self_x, FL, CAT);
    sgemm_tn<0><<<dim3(NSEQ/64, HD/64), 256>>>(CAT, Wf, SF, NSEQ, HD, 2*HD);
    sgemm_tn<1><<<dim3(NSEQ/64, HD/64), 256>>>(SF,  Wb, V,  NSEQ, HD, HD);
    tf_kernel<<<NSEQ, 256>>>(common_x, common_time, V, clen, TF);
    out_kernel<<<NBATCH, 256>>>(TF, FL, fnum, out);
}